// round 7
// baseline (speedup 1.0000x reference)
#include <cuda_runtime.h>
#include <cuda_bf16.h>
#include <stdint.h>
#include <math.h>

typedef unsigned int u32;

// ---------------------------------------------------------------------------
// x_in [4,16,32,32,256], qkv_w [256,768], proj_w [256,256], proj_b [256]
// rpb_table [343,8], fc_w [27,24], fc_b [27], dep_w [256,27,3,3,3],
// dep_b [256], alpha, beta; out [4,16,32,32,256] float32
// ---------------------------------------------------------------------------
#define LSP 16384

__device__ float g_qkv  [(size_t)65536 * 768];
__device__ float g_fconv[(size_t)4 * 864 * LSP];

__device__ __nv_bfloat16 g_xh[(size_t)65536 * 256];
__device__ __nv_bfloat16 g_xl[(size_t)65536 * 256];
__device__ __nv_bfloat16 g_ah[(size_t)65536 * 256];
__device__ __nv_bfloat16 g_al[(size_t)65536 * 256];
__device__ __nv_bfloat16 g_wqh[256 * 768];
__device__ __nv_bfloat16 g_wql[256 * 768];
__device__ __nv_bfloat16 g_pwh[256 * 256];
__device__ __nv_bfloat16 g_pwl[256 * 256];

__device__ __forceinline__ u32 smem_u32(const void* p) {
    return (u32)__cvta_generic_to_shared(p);
}

__device__ __forceinline__ void ldsm_x4(u32& r0, u32& r1, u32& r2, u32& r3, u32 a) {
    asm volatile("ldmatrix.sync.aligned.m8n8.x4.shared.b16 {%0,%1,%2,%3}, [%4];\n"
                 : "=r"(r0), "=r"(r1), "=r"(r2), "=r"(r3) : "r"(a));
}

__device__ __forceinline__ void ldsm_x4t(u32& r0, u32& r1, u32& r2, u32& r3, u32 a) {
    asm volatile("ldmatrix.sync.aligned.m8n8.x4.trans.shared.b16 {%0,%1,%2,%3}, [%4];\n"
                 : "=r"(r0), "=r"(r1), "=r"(r2), "=r"(r3) : "r"(a));
}

__device__ __forceinline__ void mma_bf16(float* c, const u32* a, const u32* b) {
    asm volatile(
        "mma.sync.aligned.m16n8k16.row.col.f32.bf16.bf16.f32 "
        "{%0,%1,%2,%3}, {%4,%5,%6,%7}, {%8,%9}, {%0,%1,%2,%3};\n"
        : "+f"(c[0]), "+f"(c[1]), "+f"(c[2]), "+f"(c[3])
        : "r"(a[0]), "r"(a[1]), "r"(a[2]), "r"(a[3]), "r"(b[0]), "r"(b[1]));
}

__device__ __forceinline__ float warp16_max(float v) {
    v = fmaxf(v, __shfl_xor_sync(0xffffffffu, v, 1));
    v = fmaxf(v, __shfl_xor_sync(0xffffffffu, v, 2));
    v = fmaxf(v, __shfl_xor_sync(0xffffffffu, v, 4));
    v = fmaxf(v, __shfl_xor_sync(0xffffffffu, v, 8));
    return v;
}

__device__ __forceinline__ float warp16_sum(float v) {
    v += __shfl_xor_sync(0xffffffffu, v, 1);
    v += __shfl_xor_sync(0xffffffffu, v, 2);
    v += __shfl_xor_sync(0xffffffffu, v, 4);
    v += __shfl_xor_sync(0xffffffffu, v, 8);
    return v;
}

// ---------------------------------------------------------------------------
// Elementwise fp32 -> (bf16 hi, bf16 lo) split.
// ---------------------------------------------------------------------------
__global__ __launch_bounds__(256) void split_kernel(
    const float* __restrict__ s, __nv_bfloat16* __restrict__ h,
    __nv_bfloat16* __restrict__ l, int n4)
{
    int i = blockIdx.x * blockDim.x + threadIdx.x;
    if (i >= n4) {
        return;
    }
    float4 v = reinterpret_cast<const float4*>(s)[i];
    __nv_bfloat16 h0 = __float2bfloat16(v.x);
    __nv_bfloat16 h1 = __float2bfloat16(v.y);
    __nv_bfloat16 h2 = __float2bfloat16(v.z);
    __nv_bfloat16 h3 = __float2bfloat16(v.w);
    __nv_bfloat16 l0 = __float2bfloat16(v.x - __bfloat162float(h0));
    __nv_bfloat16 l1 = __float2bfloat16(v.y - __bfloat162float(h1));
    __nv_bfloat16 l2 = __float2bfloat16(v.z - __bfloat162float(h2));
    __nv_bfloat16 l3 = __float2bfloat16(v.w - __bfloat162float(h3));
    __nv_bfloat162* hp = reinterpret_cast<__nv_bfloat162*>(h) + i * 2;
    __nv_bfloat162* lp = reinterpret_cast<__nv_bfloat162*>(l) + i * 2;
    hp[0] = __halves2bfloat162(h0, h1);
    hp[1] = __halves2bfloat162(h2, h3);
    lp[0] = __halves2bfloat162(l0, l1);
    lp[1] = __halves2bfloat162(l2, l3);
}

// ---------------------------------------------------------------------------
// Tensor-core GEMM on pre-split bf16, double-buffered smem (dynamic, 76KB).
// C = Ah@Bh + Ah@Bl + Al@Bh. 128x128x32 tile, 256 threads.
// MODE 0: plain fp32 store. MODE 1: window-reverse + out += alpha*(acc+bias).
// ---------------------------------------------------------------------------
#define GEMM_SMEM_BYTES ((2 * 5120 + 2 * 5120 + 2 * 4352 + 2 * 4352) * 2)

template<int MODE>
__global__ __launch_bounds__(256) void gemm_bf16(
    const __nv_bfloat16* __restrict__ Ah, const __nv_bfloat16* __restrict__ Al,
    const __nv_bfloat16* __restrict__ Bh, const __nv_bfloat16* __restrict__ Bl,
    float* __restrict__ C, int M, int N, int K,
    const float* __restrict__ bias, const float* __restrict__ alpha_p)
{
    extern __shared__ __nv_bfloat16 gsm[];
    __nv_bfloat16* pAh = gsm;
    __nv_bfloat16* pAl = gsm + 10240;
    __nv_bfloat16* pBh = gsm + 20480;
    __nv_bfloat16* pBl = gsm + 29184;

    const int tid = threadIdx.x;
    const int lane = tid & 31;
    const int wid = tid >> 5;
    const int wm = (wid & 1) * 64;
    const int wn = (wid >> 1) * 32;
    const int bm = blockIdx.y * 128;
    const int bn = blockIdx.x * 128;

    float acc[4][4][4];
#pragma unroll
    for (int i = 0; i < 4; i++) {
#pragma unroll
        for (int j = 0; j < 4; j++) {
#pragma unroll
            for (int r = 0; r < 4; r++) {
                acc[i][j][r] = 0.0f;
            }
        }
    }

    const int nk = K >> 5;
    uint4 rAh[2];
    uint4 rAl[2];
    uint4 rBh[2];
    uint4 rBl[2];

#pragma unroll
    for (int i = 0; i < 2; i++) {
        int u = tid + i * 256;
        int ar = u >> 2;
        int ac = (u & 3) * 8;
        size_t aidx = (size_t)(bm + ar) * K + ac;
        rAh[i] = *reinterpret_cast<const uint4*>(Ah + aidx);
        rAl[i] = *reinterpret_cast<const uint4*>(Al + aidx);
        int br = u >> 4;
        int bc = (u & 15) * 8;
        size_t bidx = (size_t)br * N + bn + bc;
        rBh[i] = *reinterpret_cast<const uint4*>(Bh + bidx);
        rBl[i] = *reinterpret_cast<const uint4*>(Bl + bidx);
    }
#pragma unroll
    for (int i = 0; i < 2; i++) {
        int u = tid + i * 256;
        int ar = u >> 2;
        int ac = (u & 3) * 8;
        *reinterpret_cast<uint4*>(pAh + ar * 40 + ac) = rAh[i];
        *reinterpret_cast<uint4*>(pAl + ar * 40 + ac) = rAl[i];
        int br = u >> 4;
        int bc = (u & 15) * 8;
        *reinterpret_cast<uint4*>(pBh + br * 136 + bc) = rBh[i];
        *reinterpret_cast<uint4*>(pBl + br * 136 + bc) = rBl[i];
    }
    __syncthreads();

    const int a_r = lane & 15;
    const int a_k = (lane >> 4) * 8;

    for (int kt = 0; kt < nk; kt++) {
        const int curA = (kt & 1) * 5120;
        const int curB = (kt & 1) * 4352;

        if (kt + 1 < nk) {
#pragma unroll
            for (int i = 0; i < 2; i++) {
                int u = tid + i * 256;
                int ar = u >> 2;
                int ac = (u & 3) * 8;
                size_t aidx = (size_t)(bm + ar) * K + (kt + 1) * 32 + ac;
                rAh[i] = *reinterpret_cast<const uint4*>(Ah + aidx);
                rAl[i] = *reinterpret_cast<const uint4*>(Al + aidx);
                int br = u >> 4;
                int bc = (u & 15) * 8;
                size_t bidx = (size_t)((kt + 1) * 32 + br) * N + bn + bc;
                rBh[i] = *reinterpret_cast<const uint4*>(Bh + bidx);
                rBl[i] = *reinterpret_cast<const uint4*>(Bl + bidx);
            }
        }

#pragma unroll
        for (int ks = 0; ks < 2; ks++) {
            u32 aH[4][4];
            u32 aL[4][4];
            u32 bH[4][2];
            u32 bL[4][2];
#pragma unroll
            for (int mi = 0; mi < 4; mi++) {
                u32 adr = smem_u32(pAh + curA + (wm + mi * 16 + a_r) * 40 + ks * 16 + a_k);
                ldsm_x4(aH[mi][0], aH[mi][1], aH[mi][2], aH[mi][3], adr);
                adr = smem_u32(pAl + curA + (wm + mi * 16 + a_r) * 40 + ks * 16 + a_k);
                ldsm_x4(aL[mi][0], aL[mi][1], aL[mi][2], aL[mi][3], adr);
            }
#pragma unroll
            for (int nj = 0; nj < 2; nj++) {
                u32 r0;
                u32 r1;
                u32 r2;
                u32 r3;
                u32 adr = smem_u32(pBh + curB + (ks * 16 + a_r) * 136 + wn + nj * 16 + a_k);
                ldsm_x4t(r0, r1, r2, r3, adr);
                bH[nj * 2][0] = r0;
                bH[nj * 2][1] = r1;
                bH[nj * 2 + 1][0] = r2;
                bH[nj * 2 + 1][1] = r3;
                adr = smem_u32(pBl + curB + (ks * 16 + a_r) * 136 + wn + nj * 16 + a_k);
                ldsm_x4t(r0, r1, r2, r3, adr);
                bL[nj * 2][0] = r0;
                bL[nj * 2][1] = r1;
                bL[nj * 2 + 1][0] = r2;
                bL[nj * 2 + 1][1] = r3;
            }
#pragma unroll
            for (int mi = 0; mi < 4; mi++) {
#pragma unroll
                for (int ni = 0; ni < 4; ni++) {
                    mma_bf16(acc[mi][ni], aH[mi], bH[ni]);
                    mma_bf16(acc[mi][ni], aH[mi], bL[ni]);
                    mma_bf16(acc[mi][ni], aL[mi], bH[ni]);
                }
            }
        }

        if (kt + 1 < nk) {
            const int nxtA = ((kt + 1) & 1) * 5120;
            const int nxtB = ((kt + 1) & 1) * 4352;
#pragma unroll
            for (int i = 0; i < 2; i++) {
                int u = tid + i * 256;
                int ar = u >> 2;
                int ac = (u & 3) * 8;
                *reinterpret_cast<uint4*>(pAh + nxtA + ar * 40 + ac) = rAh[i];
                *reinterpret_cast<uint4*>(pAl + nxtA + ar * 40 + ac) = rAl[i];
                int br = u >> 4;
                int bc = (u & 15) * 8;
                *reinterpret_cast<uint4*>(pBh + nxtB + br * 136 + bc) = rBh[i];
                *reinterpret_cast<uint4*>(pBl + nxtB + br * 136 + bc) = rBl[i];
            }
        }
        __syncthreads();
    }

    const int g = lane >> 2;
    const int tg = lane & 3;

    if (MODE == 0) {
#pragma unroll
        for (int mi = 0; mi < 4; mi++) {
            int row0 = bm + wm + mi * 16 + g;
#pragma unroll
            for (int ni = 0; ni < 4; ni++) {
                int col = bn + wn + ni * 8 + tg * 2;
                float2 v0;
                float2 v1;
                v0.x = acc[mi][ni][0];
                v0.y = acc[mi][ni][1];
                v1.x = acc[mi][ni][2];
                v1.y = acc[mi][ni][3];
                *reinterpret_cast<float2*>(&C[(size_t)row0 * N + col]) = v0;
                *reinterpret_cast<float2*>(&C[(size_t)(row0 + 8) * N + col]) = v1;
            }
        }
    } else {
        const float alpha = alpha_p[0];
#pragma unroll
        for (int mi = 0; mi < 4; mi++) {
#pragma unroll
            for (int half = 0; half < 2; half++) {
                int row = bm + wm + mi * 16 + g + half * 8;
                int win = row >> 6;
                int tok = row & 63;
                int b = win >> 8;
                int r2 = win & 255;
                int dblk = r2 >> 6;
                int h2 = r2 & 63;
                int hblk = h2 >> 3;
                int wblk = h2 & 7;
                int z4 = tok >> 4;
                int y4 = (tok >> 2) & 3;
                int x4 = tok & 3;
                size_t spat = (((size_t)b * 16 + dblk * 4 + z4) * 32 + hblk * 4 + y4) * 32
                              + wblk * 4 + x4;
#pragma unroll
                for (int ni = 0; ni < 4; ni++) {
                    int col = bn + wn + ni * 8 + tg * 2;
                    float2 pb = *reinterpret_cast<const float2*>(&bias[col]);
                    float* dst = &C[spat * 256 + col];
                    float2 e = *reinterpret_cast<float2*>(dst);
                    e.x += alpha * (acc[mi][ni][half * 2 + 0] + pb.x);
                    e.y += alpha * (acc[mi][ni][half * 2 + 1] + pb.y);
                    *reinterpret_cast<float2*>(dst) = e;
                }
            }
        }
    }
}

// ---------------------------------------------------------------------------
// fconv
// ---------------------------------------------------------------------------
__global__ __launch_bounds__(1024) void fconv_kernel(
    const float* __restrict__ fcw, const float* __restrict__ fcb)
{
    __shared__ float s_fcw[27 * 24];
    __shared__ float s_fcb[27];
    __shared__ float s_out[32 * 9 * 33];

    const int tid = threadIdx.x;
    const int b = blockIdx.y;
    const int l0 = blockIdx.x * 32;

    if (tid < 648) {
        s_fcw[tid] = fcw[tid];
    }
    if (tid < 27) {
        s_fcb[tid] = fcb[tid];
    }
    __syncthreads();

    const float* qb = g_qkv + (size_t)b * 12582912;
    float acc[27];
#pragma unroll
    for (int o = 0; o < 27; o++) {
        acc[o] = s_fcb[o];
    }

#pragma unroll 4
    for (int g = 0; g < 24; g++) {
        float v = qb[(size_t)g * 524288 + (size_t)l0 * 32 + tid];
#pragma unroll
        for (int o = 0; o < 27; o++) {
            acc[o] = fmaf(s_fcw[o * 24 + g], v, acc[o]);
        }
    }

    const int xx = tid & 31;
    const int ll = tid >> 5;
    float* fco = g_fconv + (size_t)b * 864 * LSP;
#pragma unroll
    for (int r = 0; r < 3; r++) {
#pragma unroll
        for (int oo = 0; oo < 9; oo++) {
            s_out[(xx * 9 + oo) * 33 + ll] = acc[r * 9 + oo];
        }
        __syncthreads();
#pragma unroll
        for (int it = 0; it < 9; it++) {
            int e = it * 1024 + tid;
            int l = e & 31;
            int rest = e >> 5;
            int o = rest % 9;
            int x2 = rest / 9;
            fco[(size_t)(x2 * 27 + r * 9 + o) * LSP + l0 + l] =
                s_out[(x2 * 9 + o) * 33 + l];
        }
        __syncthreads();
    }
}

// ---------------------------------------------------------------------------
// Grouped conv, z-streaming: block tile 32x x 16y x 8z x 8oc per (b,g).
// Window in smem: [27k][3 rolling z][18y][34x] fp32 = 198KB; weights 23KB.
// Per thread: 2oc x 2y x 4x per z-step, patch in registers (0.67 B/FMA).
// ---------------------------------------------------------------------------
#define CONV_WIN_FLOATS (27 * 3 * 18 * 34)
#define CONV_DEP_FLOATS (8 * 729)
#define CONV_SMEM_BYTES ((CONV_WIN_FLOATS + CONV_DEP_FLOATS) * 4)

__device__ __forceinline__ void conv_load_plane(
    float* swin, const float* fin, int tid, int y0, int z0, int zl)
{
    int gz = z0 + zl;
    int rot = (zl + 1) % 3;
    bool okz = (gz >= 0 && gz < 16);
    for (int kk = 0; kk < 27; kk++) {
        float* dst = swin + (kk * 3 + rot) * (18 * 34);
        const float* src = fin + (size_t)kk * LSP + gz * 1024;
        for (int e = tid; e < 612; e += 256) {
            int y = e / 34;
            int x = e - y * 34;
            int gy = y0 + y - 1;
            int gx = x - 1;
            float v = 0.0f;
            if (okz && gy >= 0 && gy < 32 && gx >= 0 && gx < 32) {
                v = src[gy * 32 + gx];
            }
            dst[y * 34 + x] = v;
        }
    }
}

__global__ __launch_bounds__(256) void conv_kernel(
    const float* __restrict__ dep_w, const float* __restrict__ dep_b,
    const float* __restrict__ beta_p, float* __restrict__ out)
{
    extern __shared__ float sm[];
    float* swin = sm;
    float* sdep = sm + CONV_WIN_FLOATS;

    const int tid = threadIdx.x;
    const int y0 = blockIdx.x * 16;
    const int z0 = blockIdx.y * 8;
    const int bg = blockIdx.z;
    const int b = bg >> 5;
    const int g = bg & 31;

    for (int e = tid; e < CONV_DEP_FLOATS; e += 256) {
        sdep[e] = dep_w[(size_t)(g * 8) * 729 + e];
    }

    const float* fin = g_fconv + ((size_t)(b * 864 + g * 27)) * LSP;

    conv_load_plane(swin, fin, tid, y0, z0, -1);
    conv_load_plane(swin, fin, tid, y0, z0, 0);

    const int xq = tid & 7;
    const int yq = (tid >> 3) & 7;
    const int ocp = tid >> 6;
    const float beta = beta_p[0];
    const int oc0 = g * 8 + ocp * 2;
    const float bb0 = dep_b[oc0];
    const float bb1 = dep_b[oc0 + 1];
    const float* wbase0 = sdep + (ocp * 2) * 729;
    const float* wbase1 = wbase0 + 729;

    for (int z = 0; z < 8; z++) {
        __syncthreads();
        conv_load_plane(swin, fin, tid, y0, z0, z + 1);
        __syncthreads();

        const int rot0 = z % 3;
        const int rot1 = (z + 1) % 3;
        const int rot2 = (z + 2) % 3;

        float acc0[2][4];
        float acc1[2][4];
#pragma unroll
        for (int oy = 0; oy < 2; oy++) {
#pragma unroll
            for (int ox = 0; ox < 4; ox++) {
                acc0[oy][ox] = 0.0f;
                acc1[oy][ox] = 0.0f;
            }
        }

#pragma unroll 1
        for (int k = 0; k < 27; k++) {
            float P[3][4][6];
            const float* base0 = swin + ((k * 3 + rot0) * 18 + yq * 2) * 34 + xq * 4;
            const float* base1 = swin + ((k * 3 + rot1) * 18 + yq * 2) * 34 + xq * 4;
            const float* base2 = swin + ((k * 3 + rot2) * 18 + yq * 2) * 34 + xq * 4;
#pragma unroll
            for (int ry = 0; ry < 4; ry++) {
                float2 a0 = *reinterpret_cast<const float2*>(base0 + ry * 34);
                float2 a1 = *reinterpret_cast<const float2*>(base0 + ry * 34 + 2);
                float2 a2 = *reinterpret_cast<const float2*>(base0 + ry * 34 + 4);
                P[0][ry][0] = a0.x; P[0][ry][1] = a0.y;
                P[0][ry][2] = a1.x; P[0][ry][3] = a1.y;
                P[0][ry][4] = a2.x; P[0][ry][5] = a2.y;
                float2 c0 = *reinterpret_cast<const float2*>(base1 + ry * 34);
                float2 c1 = *reinterpret_cast<const float2*>(base1 + ry * 34 + 2);
                float2 c2 = *reinterpret_cast<const float2*>(base1 + ry * 34 + 4);
                P[1][ry][0] = c0.x; P[1][ry][1] = c0.y;
                P[1][ry][2] = c1.x; P[1][ry][3] = c1.y;
                P[1][ry][4] = c2.x; P[1][ry][5] = c2.y;
                float2 d0 = *reinterpret_cast<const float2*>(base2 + ry * 34);
                float2 d1 = *reinterpret_cast<const float2*>(base2 + ry * 34 + 2);
                float2 d2 = *reinterpret_cast<const float2*>(base2 + ry * 34 + 4);
                P[2][ry][0] = d0.x; P[2][ry][1] = d0.y;
                P[2][ry][2] = d1.x; P[2][ry][3] = d1.y;
                P[2][ry][4] = d2.x; P[2][ry][5] = d2.y;
            }
            const float* w0 = wbase0 + k * 27;
            const float* w1 = wbase1 + k * 27;
#pragma unroll
            for (int dz = 0; dz < 3; dz++) {
#pragma unroll
                for (int dy = 0; dy < 3; dy++) {
                    float w00 = w0[dz * 9 + dy * 3 + 0];
                    float w01 = w0[dz * 9 + dy * 3 + 1];
                    float w02 = w0[dz * 9 + dy * 3 + 2];
                    float w10 = w1[dz * 9 + dy * 3 + 0];
                    float w11 = w1[dz * 9 + dy * 3 + 1];
                    float w12 = w1[dz * 9 + dy * 3 + 2];
#pragma unroll
                    for (int oy = 0; oy < 2; oy++) {
#pragma unroll
                        for (int ox = 0; ox < 4; ox++) {
                            float v0 = P[dz][oy + dy][ox + 0];
                            float v1 = P[dz][oy + dy][ox + 1];
                            float v2 = P[dz][oy + dy][ox + 2];
                            acc0[oy][ox] = fmaf(v0, w00, acc0[oy][ox]);
                            acc0[oy][ox] = fmaf(v1, w01, acc0[oy][ox]);
                            acc0[oy][ox] = fmaf(v2, w02, acc0[oy][ox]);
                            acc1[oy][ox] = fmaf(v0, w10, acc1[oy][ox]);
                            acc1[oy][ox] = fmaf(v1, w11, acc1[oy][ox]);
                            acc1[oy][ox] = fmaf(v2, w12, acc1[oy][ox]);
                        }
                    }
                }
            }
        }

        const int gz = z0 + z;
#pragma unroll
        for (int oy = 0; oy < 2; oy++) {
#pragma unroll
            for (int ox = 0; ox < 4; ox++) {
                size_t spat = (size_t)b * LSP + gz * 1024
                              + (y0 + yq * 2 + oy) * 32 + xq * 4 + ox;
                float2 v;
                v.x = beta * (acc0[oy][ox] + bb0);
                v.y = beta * (acc1[oy][ox] + bb1);
                *reinterpret_cast<float2*>(out + spat * 256 + oc0) = v;
            }
        }
    }
}

// ---------------------------------------------------------------------------
// Windowed attention -> bf16 split output (g_ah/g_al).
// ---------------------------------------------------------------------------
__global__ __launch_bounds__(256) void attn_kernel(const float* __restrict__ rpb)
{
    __shared__ __align__(16) float sq[64][36];
    __shared__ __align__(16) float skT[32][68];
    __shared__ __align__(16) float sv[64][36];
    __shared__ __align__(16) float sS[64][68];
    __shared__ float sbias[343];

    const int tid = threadIdx.x;
    const int win = blockIdx.x;
    const int head = blockIdx.y;
    const int b = win >> 8;
    const int rr = win & 255;
    const int dblk = rr >> 6;
    const int h2 = rr & 63;
    const int hblk = h2 >> 3;
    const int wblk = h2 & 7;

    for (int i = tid; i < 343; i += 256) {
        sbias[i] = rpb[i * 8 + head];
    }

    for (int e = tid; e < 64 * 32; e += 256) {
        int tok = e >> 5;
        int dd = e & 31;
        int z = tok >> 4;
        int y = (tok >> 2) & 3;
        int x = tok & 3;
        size_t spat = (((size_t)b * 16 + dblk * 4 + z) * 32 + hblk * 4 + y) * 32
                      + wblk * 4 + x;
        const float* src = g_qkv + spat * 768 + head * 32 + dd;
        sq[tok][dd] = src[0];
        skT[dd][tok] = src[256];
        sv[tok][dd] = src[512];
    }
    __syncthreads();

    const int i4 = tid >> 4;
    const int jq = tid & 15;
    const int i0 = i4 * 4;
    const int j0 = jq * 4;

    float dots[4][4];
#pragma unroll
    for (int r = 0; r < 4; r++) {
#pragma unroll
        for (int c = 0; c < 4; c++) {
            dots[r][c] = 0.0f;
        }
    }

#pragma unroll
    for (int d8 = 0; d8 < 4; d8++) {
        float qreg[4][8];
#pragma unroll
        for (int r = 0; r < 4; r++) {
            float4 q0 = *reinterpret_cast<const float4*>(&sq[i0 + r][d8 * 8]);
            float4 q1 = *reinterpret_cast<const float4*>(&sq[i0 + r][d8 * 8 + 4]);
            qreg[r][0] = q0.x; qreg[r][1] = q0.y; qreg[r][2] = q0.z; qreg[r][3] = q0.w;
            qreg[r][4] = q1.x; qreg[r][5] = q1.y; qreg[r][6] = q1.z; qreg[r][7] = q1.w;
        }
#pragma unroll
        for (int dd = 0; dd < 8; dd++) {
            float4 kv = *reinterpret_cast<const float4*>(&skT[d8 * 8 + dd][j0]);
#pragma unroll
            for (int r = 0; r < 4; r++) {
                dots[r][0] = fmaf(qreg[r][dd], kv.x, dots[r][0]);
                dots[r][1] = fmaf(qreg[r][dd], kv.y, dots[r][1]);
                dots[r][2] = fmaf(qreg[r][dd], kv.z, dots[r][2]);
                dots[r][3] = fmaf(qreg[r][dd], kv.w, dots[r][3]);
            }
        }
    }

    const float scale = 0.17677669529663687f;
#pragma unroll
    for (int r = 0; r < 4; r++) {
        int ti = i0 + r;
        int zi = ti >> 4;
        int yi = (ti >> 2) & 3;
        int xi = ti & 3;
        float sv4[4];
#pragma unroll
        for (int c = 0; c < 4; c++) {
            int tj = j0 + c;
            int zj = tj >> 4;
            int yj = (tj >> 2) & 3;
            int xj = tj & 3;
            int rel = (zi - zj + 3) * 49 + (yi - yj + 3) * 7 + (xi - xj + 3);
            sv4[c] = dots[r][c] * scale + sbias[rel];
        }
        float rmax = fmaxf(fmaxf(sv4[0], sv4[1]), fmaxf(sv4[2], sv4[3]));
        rmax = warp16_max(rmax);
        float rsum = 0.0f;
#pragma unroll
        for (int c = 0; c < 4; c++) {
            sv4[c] = __expf(sv4[c] - rmax);
            rsum += sv4[c];
        }
        rsum = warp16_sum(rsum);
        float inv = 1.0f / rsum;
        float4 pv;
        pv.x = sv4[0] * inv;
        pv.y = sv4[1] * inv;
        pv.z = sv4[2] * inv;
        pv.w = sv4[3] * inv;
        *reinterpret_cast<float4*>(&sS[i0 + r][j0]) = pv;
    }
    __syncthreads();

    const int p2 = tid >> 3;
    const int dg = tid & 7;
    const int r0 = p2 * 2;
    const int r1 = r0 + 1;
    float o0[4] = {0.0f, 0.0f, 0.0f, 0.0f};
    float o1[4] = {0.0f, 0.0f, 0.0f, 0.0f};
#pragma unroll 4
    for (int j = 0; j < 64; j++) {
        float4 v = *reinterpret_cast<const float4*>(&sv[j][dg * 4]);
        float pa = sS[r0][j];
        float pbv = sS[r1][j];
        o0[0] = fmaf(pa, v.x, o0[0]);
        o0[1] = fmaf(pa, v.y, o0[1]);
        o0[2] = fmaf(pa, v.z, o0[2]);
        o0[3] = fmaf(pa, v.w, o0[3]);
        o1[0] = fmaf(pbv, v.x, o1[0]);
        o1[1] = fmaf(pbv, v.y, o1[1]);
        o1[2] = fmaf(pbv, v.z, o1[2]);
        o1[3] = fmaf(pbv, v.w, o1[3]);
    }
    size_t off0 = ((size_t)win * 64 + r0) * 256 + head * 32 + dg * 4;
    size_t off1 = ((size_t)win * 64 + r1) * 256 + head * 32 + dg * 4;
#pragma unroll
    for (int pass = 0; pass < 2; pass++) {
        const float* ov = (pass == 0) ? o0 : o1;
        size_t off = (pass == 0) ? off0 : off1;
        __nv_bfloat16 hh[4];
        __nv_bfloat16 ll[4];
#pragma unroll
        for (int c = 0; c < 4; c++) {
            hh[c] = __float2bfloat16(ov[c]);
            ll[c] = __float2bfloat16(ov[c] - __bfloat162float(hh[c]));
        }
        __nv_bfloat162* hp = reinterpret_cast<__nv_bfloat162*>(g_ah + off);
        __nv_bfloat162* lp = reinterpret_cast<__nv_bfloat162*>(g_al + off);
        hp[0] = __halves2bfloat162(hh[0], hh[1]);
        hp[1] = __halves2bfloat162(hh[2], hh[3]);
        lp[0] = __halves2bfloat162(ll[0], ll[1]);
        lp[1] = __halves2bfloat162(ll[2], ll[3]);
    }
}

// ---------------------------------------------------------------------------
// Launch
// ---------------------------------------------------------------------------
extern "C" void kernel_launch(void* const* d_in, const int* in_sizes, int n_in,
                              void* d_out, int out_size)
{
    (void)in_sizes;
    (void)n_in;
    (void)out_size;
    const float* x_in   = (const float*)d_in[0];
    const float* qkv_w  = (const float*)d_in[1];
    const float* proj_w = (const float*)d_in[2];
    const float* proj_b = (const float*)d_in[3];
    const float* rpb    = (const float*)d_in[4];
    const float* fc_w   = (const float*)d_in[5];
    const float* fc_b   = (const float*)d_in[6];
    const float* dep_w  = (const float*)d_in[7];
    const float* dep_b  = (const float*)d_in[8];
    const float* alpha  = (const float*)d_in[9];
    const float* beta   = (const float*)d_in[10];
    float* out = (float*)d_out;

    float* p_qkv;
    __nv_bfloat16* p_xh;
    __nv_bfloat16* p_xl;
    __nv_bfloat16* p_ah;
    __nv_bfloat16* p_al;
    __nv_bfloat16* p_wqh;
    __nv_bfloat16* p_wql;
    __nv_bfloat16* p_pwh;
    __nv_bfloat16* p_pwl;
    cudaGetSymbolAddress((void**)&p_qkv, g_qkv);
    cudaGetSymbolAddress((void**)&p_xh, g_xh);
    cudaGetSymbolAddress((void**)&p_xl, g_xl);
    cudaGetSymbolAddress((void**)&p_ah, g_ah);
    cudaGetSymbolAddress((void**)&p_al, g_al);
    cudaGetSymbolAddress((void**)&p_wqh, g_wqh);
    cudaGetSymbolAddress((void**)&p_wql, g_wql);
    cudaGetSymbolAddress((void**)&p_pwh, g_pwh);
    cudaGetSymbolAddress((void**)&p_pwl, g_pwl);

    cudaFuncSetAttribute(gemm_bf16<0>, cudaFuncAttributeMaxDynamicSharedMemorySize,
                         GEMM_SMEM_BYTES);
    cudaFuncSetAttribute(gemm_bf16<1>, cudaFuncAttributeMaxDynamicSharedMemorySize,
                         GEMM_SMEM_BYTES);
    cudaFuncSetAttribute(conv_kernel, cudaFuncAttributeMaxDynamicSharedMemorySize,
                         CONV_SMEM_BYTES);

    // bf16 splits
    split_kernel<<<16384, 256>>>(x_in, p_xh, p_xl, 4194304);
    split_kernel<<<192, 256>>>(qkv_w, p_wqh, p_wql, 49152);
    split_kernel<<<64, 256>>>(proj_w, p_pwh, p_pwl, 16384);

    // 1) qkv = x_in @ qkv_w
    gemm_bf16<0><<<dim3(6, 512), 256, GEMM_SMEM_BYTES>>>(
        p_xh, p_xl, p_wqh, p_wql, p_qkv, 65536, 768, 256,
        (const float*)0, (const float*)0);
    // 2) f_conv
    fconv_kernel<<<dim3(512, 4), 1024>>>(fc_w, fc_b);
    // 3) grouped conv (z-streaming) -> out = beta*(conv + dep_b)
    conv_kernel<<<dim3(2, 2, 128), 256, CONV_SMEM_BYTES>>>(dep_w, dep_b, beta, out);
    // 4) attention -> g_ah/g_al (bf16 split)
    attn_kernel<<<dim3(1024, 8), 256>>>(rpb);
    // 5) proj + window-reverse + out += alpha*(...)
    gemm_bf16<1><<<dim3(2, 512), 256, GEMM_SMEM_BYTES>>>(
        p_ah, p_al, p_pwh, p_pwl, out, 65536, 256, 256, proj_b, alpha);
}

// round 8
// speedup vs baseline: 1.4175x; 1.4175x over previous
#include <cuda_runtime.h>
#include <cuda_bf16.h>
#include <stdint.h>
#include <math.h>

typedef unsigned int u32;

// ---------------------------------------------------------------------------
// x_in [4,16,32,32,256], qkv_w [256,768], proj_w [256,256], proj_b [256]
// rpb_table [343,8], fc_w [27,24], fc_b [27], dep_w [256,27,3,3,3],
// dep_b [256], alpha, beta; out [4,16,32,32,256] float32
// ---------------------------------------------------------------------------
#define LSP 16384

__device__ float g_qkv  [(size_t)65536 * 768];
__device__ float g_fconv[(size_t)4 * 864 * LSP];

__device__ __nv_bfloat16 g_xh[(size_t)65536 * 256];
__device__ __nv_bfloat16 g_xl[(size_t)65536 * 256];
__device__ __nv_bfloat16 g_ah[(size_t)65536 * 256];
__device__ __nv_bfloat16 g_al[(size_t)65536 * 256];
__device__ __nv_bfloat16 g_wqh[256 * 768];
__device__ __nv_bfloat16 g_wql[256 * 768];
__device__ __nv_bfloat16 g_pwh[256 * 256];
__device__ __nv_bfloat16 g_pwl[256 * 256];

__device__ __forceinline__ u32 smem_u32(const void* p) {
    return (u32)__cvta_generic_to_shared(p);
}

__device__ __forceinline__ void ldsm_x4(u32& r0, u32& r1, u32& r2, u32& r3, u32 a) {
    asm volatile("ldmatrix.sync.aligned.m8n8.x4.shared.b16 {%0,%1,%2,%3}, [%4];\n"
                 : "=r"(r0), "=r"(r1), "=r"(r2), "=r"(r3) : "r"(a));
}

__device__ __forceinline__ void ldsm_x4t(u32& r0, u32& r1, u32& r2, u32& r3, u32 a) {
    asm volatile("ldmatrix.sync.aligned.m8n8.x4.trans.shared.b16 {%0,%1,%2,%3}, [%4];\n"
                 : "=r"(r0), "=r"(r1), "=r"(r2), "=r"(r3) : "r"(a));
}

__device__ __forceinline__ void mma_bf16(float* c, const u32* a, const u32* b) {
    asm volatile(
        "mma.sync.aligned.m16n8k16.row.col.f32.bf16.bf16.f32 "
        "{%0,%1,%2,%3}, {%4,%5,%6,%7}, {%8,%9}, {%0,%1,%2,%3};\n"
        : "+f"(c[0]), "+f"(c[1]), "+f"(c[2]), "+f"(c[3])
        : "r"(a[0]), "r"(a[1]), "r"(a[2]), "r"(a[3]), "r"(b[0]), "r"(b[1]));
}

__device__ __forceinline__ float warp16_max(float v) {
    v = fmaxf(v, __shfl_xor_sync(0xffffffffu, v, 1));
    v = fmaxf(v, __shfl_xor_sync(0xffffffffu, v, 2));
    v = fmaxf(v, __shfl_xor_sync(0xffffffffu, v, 4));
    v = fmaxf(v, __shfl_xor_sync(0xffffffffu, v, 8));
    return v;
}

__device__ __forceinline__ float warp16_sum(float v) {
    v += __shfl_xor_sync(0xffffffffu, v, 1);
    v += __shfl_xor_sync(0xffffffffu, v, 2);
    v += __shfl_xor_sync(0xffffffffu, v, 4);
    v += __shfl_xor_sync(0xffffffffu, v, 8);
    return v;
}

// ---------------------------------------------------------------------------
// Merged elementwise fp32 -> (bf16 hi, bf16 lo) split for all 3 tensors.
// ---------------------------------------------------------------------------
#define SPLIT_N1 4194304
#define SPLIT_N2 49152
#define SPLIT_N3 16384

__global__ __launch_bounds__(256) void split3_kernel(
    const float* __restrict__ x, const float* __restrict__ wq,
    const float* __restrict__ pw)
{
    int i = blockIdx.x * blockDim.x + threadIdx.x;
    const float* s;
    __nv_bfloat16* h;
    __nv_bfloat16* l;
    int idx;
    if (i < SPLIT_N1) {
        s = x;
        h = g_xh;
        l = g_xl;
        idx = i;
    } else if (i < SPLIT_N1 + SPLIT_N2) {
        s = wq;
        h = g_wqh;
        l = g_wql;
        idx = i - SPLIT_N1;
    } else if (i < SPLIT_N1 + SPLIT_N2 + SPLIT_N3) {
        s = pw;
        h = g_pwh;
        l = g_pwl;
        idx = i - SPLIT_N1 - SPLIT_N2;
    } else {
        return;
    }
    float4 v = reinterpret_cast<const float4*>(s)[idx];
    __nv_bfloat16 h0 = __float2bfloat16(v.x);
    __nv_bfloat16 h1 = __float2bfloat16(v.y);
    __nv_bfloat16 h2 = __float2bfloat16(v.z);
    __nv_bfloat16 h3 = __float2bfloat16(v.w);
    __nv_bfloat16 l0 = __float2bfloat16(v.x - __bfloat162float(h0));
    __nv_bfloat16 l1 = __float2bfloat16(v.y - __bfloat162float(h1));
    __nv_bfloat16 l2 = __float2bfloat16(v.z - __bfloat162float(h2));
    __nv_bfloat16 l3 = __float2bfloat16(v.w - __bfloat162float(h3));
    __nv_bfloat162* hp = reinterpret_cast<__nv_bfloat162*>(h) + idx * 2;
    __nv_bfloat162* lp = reinterpret_cast<__nv_bfloat162*>(l) + idx * 2;
    hp[0] = __halves2bfloat162(h0, h1);
    hp[1] = __halves2bfloat162(h2, h3);
    lp[0] = __halves2bfloat162(l0, l1);
    lp[1] = __halves2bfloat162(l2, l3);
}

// ---------------------------------------------------------------------------
// Tensor-core GEMM on pre-split bf16, double-buffered smem (dynamic, 76KB).
// C = Ah@Bh + Ah@Bl + Al@Bh. 128x128x32 tile, 256 threads.
// MODE 0: plain fp32 store. MODE 1: window-reverse + out += alpha*(acc+bias).
// ---------------------------------------------------------------------------
#define GEMM_SMEM_BYTES ((2 * 5120 + 2 * 5120 + 2 * 4352 + 2 * 4352) * 2)

template<int MODE>
__global__ __launch_bounds__(256) void gemm_bf16(
    const __nv_bfloat16* __restrict__ Ah, const __nv_bfloat16* __restrict__ Al,
    const __nv_bfloat16* __restrict__ Bh, const __nv_bfloat16* __restrict__ Bl,
    float* __restrict__ C, int M, int N, int K,
    const float* __restrict__ bias, const float* __restrict__ alpha_p)
{
    extern __shared__ __nv_bfloat16 gsm[];
    __nv_bfloat16* pAh = gsm;
    __nv_bfloat16* pAl = gsm + 10240;
    __nv_bfloat16* pBh = gsm + 20480;
    __nv_bfloat16* pBl = gsm + 29184;

    const int tid = threadIdx.x;
    const int lane = tid & 31;
    const int wid = tid >> 5;
    const int wm = (wid & 1) * 64;
    const int wn = (wid >> 1) * 32;
    const int bm = blockIdx.y * 128;
    const int bn = blockIdx.x * 128;

    float acc[4][4][4];
#pragma unroll
    for (int i = 0; i < 4; i++) {
#pragma unroll
        for (int j = 0; j < 4; j++) {
#pragma unroll
            for (int r = 0; r < 4; r++) {
                acc[i][j][r] = 0.0f;
            }
        }
    }

    const int nk = K >> 5;
    uint4 rAh[2];
    uint4 rAl[2];
    uint4 rBh[2];
    uint4 rBl[2];

#pragma unroll
    for (int i = 0; i < 2; i++) {
        int u = tid + i * 256;
        int ar = u >> 2;
        int ac = (u & 3) * 8;
        size_t aidx = (size_t)(bm + ar) * K + ac;
        rAh[i] = *reinterpret_cast<const uint4*>(Ah + aidx);
        rAl[i] = *reinterpret_cast<const uint4*>(Al + aidx);
        int br = u >> 4;
        int bc = (u & 15) * 8;
        size_t bidx = (size_t)br * N + bn + bc;
        rBh[i] = *reinterpret_cast<const uint4*>(Bh + bidx);
        rBl[i] = *reinterpret_cast<const uint4*>(Bl + bidx);
    }
#pragma unroll
    for (int i = 0; i < 2; i++) {
        int u = tid + i * 256;
        int ar = u >> 2;
        int ac = (u & 3) * 8;
        *reinterpret_cast<uint4*>(pAh + ar * 40 + ac) = rAh[i];
        *reinterpret_cast<uint4*>(pAl + ar * 40 + ac) = rAl[i];
        int br = u >> 4;
        int bc = (u & 15) * 8;
        *reinterpret_cast<uint4*>(pBh + br * 136 + bc) = rBh[i];
        *reinterpret_cast<uint4*>(pBl + br * 136 + bc) = rBl[i];
    }
    __syncthreads();

    const int a_r = lane & 15;
    const int a_k = (lane >> 4) * 8;

    for (int kt = 0; kt < nk; kt++) {
        const int curA = (kt & 1) * 5120;
        const int curB = (kt & 1) * 4352;

        if (kt + 1 < nk) {
#pragma unroll
            for (int i = 0; i < 2; i++) {
                int u = tid + i * 256;
                int ar = u >> 2;
                int ac = (u & 3) * 8;
                size_t aidx = (size_t)(bm + ar) * K + (kt + 1) * 32 + ac;
                rAh[i] = *reinterpret_cast<const uint4*>(Ah + aidx);
                rAl[i] = *reinterpret_cast<const uint4*>(Al + aidx);
                int br = u >> 4;
                int bc = (u & 15) * 8;
                size_t bidx = (size_t)((kt + 1) * 32 + br) * N + bn + bc;
                rBh[i] = *reinterpret_cast<const uint4*>(Bh + bidx);
                rBl[i] = *reinterpret_cast<const uint4*>(Bl + bidx);
            }
        }

#pragma unroll
        for (int ks = 0; ks < 2; ks++) {
            u32 aH[4][4];
            u32 aL[4][4];
            u32 bH[4][2];
            u32 bL[4][2];
#pragma unroll
            for (int mi = 0; mi < 4; mi++) {
                u32 adr = smem_u32(pAh + curA + (wm + mi * 16 + a_r) * 40 + ks * 16 + a_k);
                ldsm_x4(aH[mi][0], aH[mi][1], aH[mi][2], aH[mi][3], adr);
                adr = smem_u32(pAl + curA + (wm + mi * 16 + a_r) * 40 + ks * 16 + a_k);
                ldsm_x4(aL[mi][0], aL[mi][1], aL[mi][2], aL[mi][3], adr);
            }
#pragma unroll
            for (int nj = 0; nj < 2; nj++) {
                u32 r0;
                u32 r1;
                u32 r2;
                u32 r3;
                u32 adr = smem_u32(pBh + curB + (ks * 16 + a_r) * 136 + wn + nj * 16 + a_k);
                ldsm_x4t(r0, r1, r2, r3, adr);
                bH[nj * 2][0] = r0;
                bH[nj * 2][1] = r1;
                bH[nj * 2 + 1][0] = r2;
                bH[nj * 2 + 1][1] = r3;
                adr = smem_u32(pBl + curB + (ks * 16 + a_r) * 136 + wn + nj * 16 + a_k);
                ldsm_x4t(r0, r1, r2, r3, adr);
                bL[nj * 2][0] = r0;
                bL[nj * 2][1] = r1;
                bL[nj * 2 + 1][0] = r2;
                bL[nj * 2 + 1][1] = r3;
            }
#pragma unroll
            for (int mi = 0; mi < 4; mi++) {
#pragma unroll
                for (int ni = 0; ni < 4; ni++) {
                    mma_bf16(acc[mi][ni], aH[mi], bH[ni]);
                    mma_bf16(acc[mi][ni], aH[mi], bL[ni]);
                    mma_bf16(acc[mi][ni], aL[mi], bH[ni]);
                }
            }
        }

        if (kt + 1 < nk) {
            const int nxtA = ((kt + 1) & 1) * 5120;
            const int nxtB = ((kt + 1) & 1) * 4352;
#pragma unroll
            for (int i = 0; i < 2; i++) {
                int u = tid + i * 256;
                int ar = u >> 2;
                int ac = (u & 3) * 8;
                *reinterpret_cast<uint4*>(pAh + nxtA + ar * 40 + ac) = rAh[i];
                *reinterpret_cast<uint4*>(pAl + nxtA + ar * 40 + ac) = rAl[i];
                int br = u >> 4;
                int bc = (u & 15) * 8;
                *reinterpret_cast<uint4*>(pBh + nxtB + br * 136 + bc) = rBh[i];
                *reinterpret_cast<uint4*>(pBl + nxtB + br * 136 + bc) = rBl[i];
            }
        }
        __syncthreads();
    }

    const int g = lane >> 2;
    const int tg = lane & 3;

    if (MODE == 0) {
#pragma unroll
        for (int mi = 0; mi < 4; mi++) {
            int row0 = bm + wm + mi * 16 + g;
#pragma unroll
            for (int ni = 0; ni < 4; ni++) {
                int col = bn + wn + ni * 8 + tg * 2;
                float2 v0;
                float2 v1;
                v0.x = acc[mi][ni][0];
                v0.y = acc[mi][ni][1];
                v1.x = acc[mi][ni][2];
                v1.y = acc[mi][ni][3];
                *reinterpret_cast<float2*>(&C[(size_t)row0 * N + col]) = v0;
                *reinterpret_cast<float2*>(&C[(size_t)(row0 + 8) * N + col]) = v1;
            }
        }
    } else {
        const float alpha = alpha_p[0];
#pragma unroll
        for (int mi = 0; mi < 4; mi++) {
#pragma unroll
            for (int half = 0; half < 2; half++) {
                int row = bm + wm + mi * 16 + g + half * 8;
                int win = row >> 6;
                int tok = row & 63;
                int b = win >> 8;
                int r2 = win & 255;
                int dblk = r2 >> 6;
                int h2 = r2 & 63;
                int hblk = h2 >> 3;
                int wblk = h2 & 7;
                int z4 = tok >> 4;
                int y4 = (tok >> 2) & 3;
                int x4 = tok & 3;
                size_t spat = (((size_t)b * 16 + dblk * 4 + z4) * 32 + hblk * 4 + y4) * 32
                              + wblk * 4 + x4;
#pragma unroll
                for (int ni = 0; ni < 4; ni++) {
                    int col = bn + wn + ni * 8 + tg * 2;
                    float2 pb = *reinterpret_cast<const float2*>(&bias[col]);
                    float* dst = &C[spat * 256 + col];
                    float2 e = *reinterpret_cast<float2*>(dst);
                    e.x += alpha * (acc[mi][ni][half * 2 + 0] + pb.x);
                    e.y += alpha * (acc[mi][ni][half * 2 + 1] + pb.y);
                    *reinterpret_cast<float2*>(dst) = e;
                }
            }
        }
    }
}

// ---------------------------------------------------------------------------
// fconv
// ---------------------------------------------------------------------------
__global__ __launch_bounds__(1024) void fconv_kernel(
    const float* __restrict__ fcw, const float* __restrict__ fcb)
{
    __shared__ float s_fcw[27 * 24];
    __shared__ float s_fcb[27];
    __shared__ float s_out[32 * 9 * 33];

    const int tid = threadIdx.x;
    const int b = blockIdx.y;
    const int l0 = blockIdx.x * 32;

    if (tid < 648) {
        s_fcw[tid] = fcw[tid];
    }
    if (tid < 27) {
        s_fcb[tid] = fcb[tid];
    }
    __syncthreads();

    const float* qb = g_qkv + (size_t)b * 12582912;
    float acc[27];
#pragma unroll
    for (int o = 0; o < 27; o++) {
        acc[o] = s_fcb[o];
    }

#pragma unroll 4
    for (int g = 0; g < 24; g++) {
        float v = qb[(size_t)g * 524288 + (size_t)l0 * 32 + tid];
#pragma unroll
        for (int o = 0; o < 27; o++) {
            acc[o] = fmaf(s_fcw[o * 24 + g], v, acc[o]);
        }
    }

    const int xx = tid & 31;
    const int ll = tid >> 5;
    float* fco = g_fconv + (size_t)b * 864 * LSP;
#pragma unroll
    for (int r = 0; r < 3; r++) {
#pragma unroll
        for (int oo = 0; oo < 9; oo++) {
            s_out[(xx * 9 + oo) * 33 + ll] = acc[r * 9 + oo];
        }
        __syncthreads();
#pragma unroll
        for (int it = 0; it < 9; it++) {
            int e = it * 1024 + tid;
            int l = e & 31;
            int rest = e >> 5;
            int o = rest % 9;
            int x2 = rest / 9;
            fco[(size_t)(x2 * 27 + r * 9 + o) * LSP + l0 + l] =
                s_out[(x2 * 9 + o) * 33 + l];
        }
        __syncthreads();
    }
}

// ---------------------------------------------------------------------------
// Grouped conv (R6 structure): 2z x 8y x 32x tile, 512 threads,
// per-thread 2oc x 4x. Weights re-laid [oc][k][dz*3+dy][4] for LDS.128.
// ---------------------------------------------------------------------------
#define CONV_SW_FLOATS  (27 * 4 * 10 * 36)
#define CONV_DEP_FLOATS (8 * 27 * 9 * 4)
#define CONV_SMEM_BYTES ((CONV_SW_FLOATS + CONV_DEP_FLOATS) * 4)

__global__ __launch_bounds__(512) void conv_kernel(
    const float* __restrict__ dep_w, const float* __restrict__ dep_b,
    const float* __restrict__ beta_p, float* __restrict__ out)
{
    extern __shared__ float sm[];
    float* sw = sm;
    float* sdep = sm + CONV_SW_FLOATS;

    const int tid = threadIdx.x;
    const int y0 = blockIdx.x * 8;
    const int z0 = blockIdx.y * 2;
    const int bg = blockIdx.z;
    const int b = bg >> 5;
    const int g = bg & 31;

    // weights: dep_w[(g*8+ocl)*729 + k*27 + dydz*3 + dx]
    //   -> sdep[((ocl*27 + k)*9 + dydz)*4 + dx], dx==3 slot zero-padded
    for (int e = tid; e < CONV_DEP_FLOATS; e += 512) {
        int dx = e & 3;
        int rest = e >> 2;
        int dydz = rest % 9;
        int rest2 = rest / 9;
        int k = rest2 % 27;
        int ocl = rest2 / 27;
        float v = 0.0f;
        if (dx < 3) {
            v = dep_w[(size_t)(g * 8 + ocl) * 729 + k * 27 + dydz * 3 + dx];
        }
        sdep[e] = v;
    }

    const float* fin = g_fconv + ((size_t)(b * 864 + g * 27)) * LSP;
    for (int e = tid; e < 27 * 4 * 10 * 34; e += 512) {
        int x = e % 34;
        int t1 = e / 34;
        int yy = t1 % 10;
        int t2 = t1 / 10;
        int wz = t2 & 3;
        int k = t2 >> 2;
        int gx = x - 1;
        int gy = y0 + yy - 1;
        int gz = z0 + wz - 1;
        float v = 0.0f;
        if (gx >= 0 && gx < 32 && gy >= 0 && gy < 32 && gz >= 0 && gz < 16) {
            v = fin[(size_t)k * LSP + gz * 1024 + gy * 32 + gx];
        }
        sw[((k * 4 + wz) * 10 + yy) * 36 + x] = v;
    }
    __syncthreads();

    const int xq = tid & 7;
    const int ocp = (tid >> 3) & 3;
    const int yy = (tid >> 5) & 7;
    const int zz = tid >> 8;
    const int oc0 = ocp * 2;

    float acc0[4] = {0.0f, 0.0f, 0.0f, 0.0f};
    float acc1[4] = {0.0f, 0.0f, 0.0f, 0.0f};

    const float* wd0 = sdep + (oc0 * 27) * 36;       // (ocl*27 + k)*9*4 = ocl*972
    const float* wd1 = wd0 + 972;

#pragma unroll 1
    for (int k = 0; k < 27; k++) {
#pragma unroll
        for (int dz = 0; dz < 3; dz++) {
#pragma unroll
            for (int dy = 0; dy < 3; dy++) {
                const float* wrow = &sw[((k * 4 + zz + dz) * 10 + yy + dy) * 36 + xq * 4];
                float4 wa = *reinterpret_cast<const float4*>(wrow);
                float2 wb = *reinterpret_cast<const float2*>(wrow + 4);
                float win[6];
                win[0] = wa.x; win[1] = wa.y; win[2] = wa.z; win[3] = wa.w;
                win[4] = wb.x; win[5] = wb.y;
                float4 w0v = *reinterpret_cast<const float4*>(wd0 + (k * 9 + dz * 3 + dy) * 4);
                float4 w1v = *reinterpret_cast<const float4*>(wd1 + (k * 9 + dz * 3 + dy) * 4);
                float w0[3];
                float w1[3];
                w0[0] = w0v.x; w0[1] = w0v.y; w0[2] = w0v.z;
                w1[0] = w1v.x; w1[1] = w1v.y; w1[2] = w1v.z;
#pragma unroll
                for (int dx = 0; dx < 3; dx++) {
#pragma unroll
                    for (int c = 0; c < 4; c++) {
                        acc0[c] = fmaf(win[c + dx], w0[dx], acc0[c]);
                        acc1[c] = fmaf(win[c + dx], w1[dx], acc1[c]);
                    }
                }
            }
        }
    }

    const float beta = beta_p[0];
    const int ocg0 = g * 8 + oc0;
    const float b0 = dep_b[ocg0];
    const float b1 = dep_b[ocg0 + 1];
    const size_t spatbase = (size_t)b * LSP + (z0 + zz) * 1024 + (y0 + yy) * 32 + xq * 4;
#pragma unroll
    for (int c = 0; c < 4; c++) {
        float2 v;
        v.x = beta * (acc0[c] + b0);
        v.y = beta * (acc1[c] + b1);
        *reinterpret_cast<float2*>(out + (spatbase + c) * 256 + ocg0) = v;
    }
}

// ---------------------------------------------------------------------------
// Windowed attention -> bf16 split output (g_ah/g_al).
// ---------------------------------------------------------------------------
__global__ __launch_bounds__(256) void attn_kernel(const float* __restrict__ rpb)
{
    __shared__ __align__(16) float sq[64][36];
    __shared__ __align__(16) float skT[32][68];
    __shared__ __align__(16) float sv[64][36];
    __shared__ __align__(16) float sS[64][68];
    __shared__ float sbias[343];

    const int tid = threadIdx.x;
    const int win = blockIdx.x;
    const int head = blockIdx.y;
    const int b = win >> 8;
    const int rr = win & 255;
    const int dblk = rr >> 6;
    const int h2 = rr & 63;
    const int hblk = h2 >> 3;
    const int wblk = h2 & 7;

    for (int i = tid; i < 343; i += 256) {
        sbias[i] = rpb[i * 8 + head];
    }

    for (int e = tid; e < 64 * 32; e += 256) {
        int tok = e >> 5;
        int dd = e & 31;
        int z = tok >> 4;
        int y = (tok >> 2) & 3;
        int x = tok & 3;
        size_t spat = (((size_t)b * 16 + dblk * 4 + z) * 32 + hblk * 4 + y) * 32
                      + wblk * 4 + x;
        const float* src = g_qkv + spat * 768 + head * 32 + dd;
        sq[tok][dd] = src[0];
        skT[dd][tok] = src[256];
        sv[tok][dd] = src[512];
    }
    __syncthreads();

    const int i4 = tid >> 4;
    const int jq = tid & 15;
    const int i0 = i4 * 4;
    const int j0 = jq * 4;

    float dots[4][4];
#pragma unroll
    for (int r = 0; r < 4; r++) {
#pragma unroll
        for (int c = 0; c < 4; c++) {
            dots[r][c] = 0.0f;
        }
    }

#pragma unroll
    for (int d8 = 0; d8 < 4; d8++) {
        float qreg[4][8];
#pragma unroll
        for (int r = 0; r < 4; r++) {
            float4 q0 = *reinterpret_cast<const float4*>(&sq[i0 + r][d8 * 8]);
            float4 q1 = *reinterpret_cast<const float4*>(&sq[i0 + r][d8 * 8 + 4]);
            qreg[r][0] = q0.x; qreg[r][1] = q0.y; qreg[r][2] = q0.z; qreg[r][3] = q0.w;
            qreg[r][4] = q1.x; qreg[r][5] = q1.y; qreg[r][6] = q1.z; qreg[r][7] = q1.w;
        }
#pragma unroll
        for (int dd = 0; dd < 8; dd++) {
            float4 kv = *reinterpret_cast<const float4*>(&skT[d8 * 8 + dd][j0]);
#pragma unroll
            for (int r = 0; r < 4; r++) {
                dots[r][0] = fmaf(qreg[r][dd], kv.x, dots[r][0]);
                dots[r][1] = fmaf(qreg[r][dd], kv.y, dots[r][1]);
                dots[r][2] = fmaf(qreg[r][dd], kv.z, dots[r][2]);
                dots[r][3] = fmaf(qreg[r][dd], kv.w, dots[r][3]);
            }
        }
    }

    const float scale = 0.17677669529663687f;
#pragma unroll
    for (int r = 0; r < 4; r++) {
        int ti = i0 + r;
        int zi = ti >> 4;
        int yi = (ti >> 2) & 3;
        int xi = ti & 3;
        float sv4[4];
#pragma unroll
        for (int c = 0; c < 4; c++) {
            int tj = j0 + c;
            int zj = tj >> 4;
            int yj = (tj >> 2) & 3;
            int xj = tj & 3;
            int rel = (zi - zj + 3) * 49 + (yi - yj + 3) * 7 + (xi - xj + 3);
            sv4[c] = dots[r][c] * scale + sbias[rel];
        }
        float rmax = fmaxf(fmaxf(sv4[0], sv4[1]), fmaxf(sv4[2], sv4[3]));
        rmax = warp16_max(rmax);
        float rsum = 0.0f;
#pragma unroll
        for (int c = 0; c < 4; c++) {
            sv4[c] = __expf(sv4[c] - rmax);
            rsum += sv4[c];
        }
        rsum = warp16_sum(rsum);
        float inv = 1.0f / rsum;
        float4 pv;
        pv.x = sv4[0] * inv;
        pv.y = sv4[1] * inv;
        pv.z = sv4[2] * inv;
        pv.w = sv4[3] * inv;
        *reinterpret_cast<float4*>(&sS[i0 + r][j0]) = pv;
    }
    __syncthreads();

    const int p2 = tid >> 3;
    const int dg = tid & 7;
    const int r0 = p2 * 2;
    const int r1 = r0 + 1;
    float o0[4] = {0.0f, 0.0f, 0.0f, 0.0f};
    float o1[4] = {0.0f, 0.0f, 0.0f, 0.0f};
#pragma unroll 4
    for (int j = 0; j < 64; j++) {
        float4 v = *reinterpret_cast<const float4*>(&sv[j][dg * 4]);
        float pa = sS[r0][j];
        float pbv = sS[r1][j];
        o0[0] = fmaf(pa, v.x, o0[0]);
        o0[1] = fmaf(pa, v.y, o0[1]);
        o0[2] = fmaf(pa, v.z, o0[2]);
        o0[3] = fmaf(pa, v.w, o0[3]);
        o1[0] = fmaf(pbv, v.x, o1[0]);
        o1[1] = fmaf(pbv, v.y, o1[1]);
        o1[2] = fmaf(pbv, v.z, o1[2]);
        o1[3] = fmaf(pbv, v.w, o1[3]);
    }
    size_t off0 = ((size_t)win * 64 + r0) * 256 + head * 32 + dg * 4;
    size_t off1 = ((size_t)win * 64 + r1) * 256 + head * 32 + dg * 4;
#pragma unroll
    for (int pass = 0; pass < 2; pass++) {
        const float* ov = (pass == 0) ? o0 : o1;
        size_t off = (pass == 0) ? off0 : off1;
        __nv_bfloat16 hh[4];
        __nv_bfloat16 ll[4];
#pragma unroll
        for (int c = 0; c < 4; c++) {
            hh[c] = __float2bfloat16(ov[c]);
            ll[c] = __float2bfloat16(ov[c] - __bfloat162float(hh[c]));
        }
        __nv_bfloat162* hp = reinterpret_cast<__nv_bfloat162*>(g_ah + off);
        __nv_bfloat162* lp = reinterpret_cast<__nv_bfloat162*>(g_al + off);
        hp[0] = __halves2bfloat162(hh[0], hh[1]);
        hp[1] = __halves2bfloat162(hh[2], hh[3]);
        lp[0] = __halves2bfloat162(ll[0], ll[1]);
        lp[1] = __halves2bfloat162(ll[2], ll[3]);
    }
}

// ---------------------------------------------------------------------------
// Launch. Order puts conv at app-launch index 3 (the ncu-captured slot).
// ---------------------------------------------------------------------------
extern "C" void kernel_launch(void* const* d_in, const int* in_sizes, int n_in,
                              void* d_out, int out_size)
{
    (void)in_sizes;
    (void)n_in;
    (void)out_size;
    const float* x_in   = (const float*)d_in[0];
    const float* qkv_w  = (const float*)d_in[1];
    const float* proj_w = (const float*)d_in[2];
    const float* proj_b = (const float*)d_in[3];
    const float* rpb    = (const float*)d_in[4];
    const float* fc_w   = (const float*)d_in[5];
    const float* fc_b   = (const float*)d_in[6];
    const float* dep_w  = (const float*)d_in[7];
    const float* dep_b  = (const float*)d_in[8];
    const float* alpha  = (const float*)d_in[9];
    const float* beta   = (const float*)d_in[10];
    float* out = (float*)d_out;

    float* p_qkv;
    __nv_bfloat16* p_xh;
    __nv_bfloat16* p_xl;
    __nv_bfloat16* p_ah;
    __nv_bfloat16* p_al;
    __nv_bfloat16* p_wqh;
    __nv_bfloat16* p_wql;
    __nv_bfloat16* p_pwh;
    __nv_bfloat16* p_pwl;
    cudaGetSymbolAddress((void**)&p_qkv, g_qkv);
    cudaGetSymbolAddress((void**)&p_xh, g_xh);
    cudaGetSymbolAddress((void**)&p_xl, g_xl);
    cudaGetSymbolAddress((void**)&p_ah, g_ah);
    cudaGetSymbolAddress((void**)&p_al, g_al);
    cudaGetSymbolAddress((void**)&p_wqh, g_wqh);
    cudaGetSymbolAddress((void**)&p_wql, g_wql);
    cudaGetSymbolAddress((void**)&p_pwh, g_pwh);
    cudaGetSymbolAddress((void**)&p_pwl, g_pwl);

    cudaFuncSetAttribute(gemm_bf16<0>, cudaFuncAttributeMaxDynamicSharedMemorySize,
                         GEMM_SMEM_BYTES);
    cudaFuncSetAttribute(gemm_bf16<1>, cudaFuncAttributeMaxDynamicSharedMemorySize,
                         GEMM_SMEM_BYTES);
    cudaFuncSetAttribute(conv_kernel, cudaFuncAttributeMaxDynamicSharedMemorySize,
                         CONV_SMEM_BYTES);

    // 0) merged bf16 splits
    split3_kernel<<<16640, 256>>>(x_in, qkv_w, proj_w);
    // 1) qkv = x_in @ qkv_w
    gemm_bf16<0><<<dim3(6, 512), 256, GEMM_SMEM_BYTES>>>(
        p_xh, p_xl, p_wqh, p_wql, p_qkv, 65536, 768, 256,
        (const float*)0, (const float*)0);
    // 2) f_conv
    fconv_kernel<<<dim3(512, 4), 1024>>>(fc_w, fc_b);
    // 3) grouped conv -> out = beta*(conv + dep_b)    [profiled slot]
    conv_kernel<<<dim3(4, 8, 128), 512, CONV_SMEM_BYTES>>>(dep_w, dep_b, beta, out);
    // 4) attention -> g_ah/g_al (bf16 split)
    attn_kernel<<<dim3(1024, 8), 256>>>(rpb);
    // 5) proj + window-reverse + out += alpha*(...)
    gemm_bf16<1><<<dim3(2, 512), 256, GEMM_SMEM_BYTES>>>(
        p_ah, p_al, p_pwh, p_pwl, out, 65536, 256, 256, proj_b, alpha);
}

// round 9
// speedup vs baseline: 1.7271x; 1.2183x over previous
#include <cuda_runtime.h>
#include <cuda_bf16.h>
#include <stdint.h>
#include <math.h>

typedef unsigned int u32;

// ---------------------------------------------------------------------------
// x_in [4,16,32,32,256], qkv_w [256,768], proj_w [256,256], proj_b [256]
// rpb_table [343,8], fc_w [27,24], fc_b [27], dep_w [256,27,3,3,3],
// dep_b [256], alpha, beta; out [4,16,32,32,256] float32
// ---------------------------------------------------------------------------
#define LSP 16384

__device__ float g_qkv  [(size_t)65536 * 768];
__device__ float g_fconv[(size_t)4 * 864 * LSP];

__device__ __nv_bfloat16 g_xh[(size_t)65536 * 256];
__device__ __nv_bfloat16 g_xl[(size_t)65536 * 256];
__device__ __nv_bfloat16 g_ah[(size_t)65536 * 256];
__device__ __nv_bfloat16 g_al[(size_t)65536 * 256];
__device__ __nv_bfloat16 g_wqh[256 * 768];
__device__ __nv_bfloat16 g_wql[256 * 768];
__device__ __nv_bfloat16 g_pwh[256 * 256];
__device__ __nv_bfloat16 g_pwl[256 * 256];

__device__ __forceinline__ u32 smem_u32(const void* p) {
    return (u32)__cvta_generic_to_shared(p);
}

__device__ __forceinline__ void ldsm_x4(u32& r0, u32& r1, u32& r2, u32& r3, u32 a) {
    asm volatile("ldmatrix.sync.aligned.m8n8.x4.shared.b16 {%0,%1,%2,%3}, [%4];\n"
                 : "=r"(r0), "=r"(r1), "=r"(r2), "=r"(r3) : "r"(a));
}

__device__ __forceinline__ void ldsm_x4t(u32& r0, u32& r1, u32& r2, u32& r3, u32 a) {
    asm volatile("ldmatrix.sync.aligned.m8n8.x4.trans.shared.b16 {%0,%1,%2,%3}, [%4];\n"
                 : "=r"(r0), "=r"(r1), "=r"(r2), "=r"(r3) : "r"(a));
}

__device__ __forceinline__ void mma_bf16(float* c, const u32* a, const u32* b) {
    asm volatile(
        "mma.sync.aligned.m16n8k16.row.col.f32.bf16.bf16.f32 "
        "{%0,%1,%2,%3}, {%4,%5,%6,%7}, {%8,%9}, {%0,%1,%2,%3};\n"
        : "+f"(c[0]), "+f"(c[1]), "+f"(c[2]), "+f"(c[3])
        : "r"(a[0]), "r"(a[1]), "r"(a[2]), "r"(a[3]), "r"(b[0]), "r"(b[1]));
}

__device__ __forceinline__ float warp16_max(float v) {
    v = fmaxf(v, __shfl_xor_sync(0xffffffffu, v, 1));
    v = fmaxf(v, __shfl_xor_sync(0xffffffffu, v, 2));
    v = fmaxf(v, __shfl_xor_sync(0xffffffffu, v, 4));
    v = fmaxf(v, __shfl_xor_sync(0xffffffffu, v, 8));
    return v;
}

__device__ __forceinline__ float warp16_sum(float v) {
    v += __shfl_xor_sync(0xffffffffu, v, 1);
    v += __shfl_xor_sync(0xffffffffu, v, 2);
    v += __shfl_xor_sync(0xffffffffu, v, 4);
    v += __shfl_xor_sync(0xffffffffu, v, 8);
    return v;
}

// ---------------------------------------------------------------------------
// Merged elementwise fp32 -> (bf16 hi, bf16 lo) split for all 3 tensors.
// ---------------------------------------------------------------------------
#define SPLIT_N1 4194304
#define SPLIT_N2 49152
#define SPLIT_N3 16384

__global__ __launch_bounds__(256) void split3_kernel(
    const float* __restrict__ x, const float* __restrict__ wq,
    const float* __restrict__ pw)
{
    int i = blockIdx.x * blockDim.x + threadIdx.x;
    const float* s;
    __nv_bfloat16* h;
    __nv_bfloat16* l;
    int idx;
    if (i < SPLIT_N1) {
        s = x;
        h = g_xh;
        l = g_xl;
        idx = i;
    } else if (i < SPLIT_N1 + SPLIT_N2) {
        s = wq;
        h = g_wqh;
        l = g_wql;
        idx = i - SPLIT_N1;
    } else if (i < SPLIT_N1 + SPLIT_N2 + SPLIT_N3) {
        s = pw;
        h = g_pwh;
        l = g_pwl;
        idx = i - SPLIT_N1 - SPLIT_N2;
    } else {
        return;
    }
    float4 v = reinterpret_cast<const float4*>(s)[idx];
    __nv_bfloat16 h0 = __float2bfloat16(v.x);
    __nv_bfloat16 h1 = __float2bfloat16(v.y);
    __nv_bfloat16 h2 = __float2bfloat16(v.z);
    __nv_bfloat16 h3 = __float2bfloat16(v.w);
    __nv_bfloat16 l0 = __float2bfloat16(v.x - __bfloat162float(h0));
    __nv_bfloat16 l1 = __float2bfloat16(v.y - __bfloat162float(h1));
    __nv_bfloat16 l2 = __float2bfloat16(v.z - __bfloat162float(h2));
    __nv_bfloat16 l3 = __float2bfloat16(v.w - __bfloat162float(h3));
    __nv_bfloat162* hp = reinterpret_cast<__nv_bfloat162*>(h) + idx * 2;
    __nv_bfloat162* lp = reinterpret_cast<__nv_bfloat162*>(l) + idx * 2;
    hp[0] = __halves2bfloat162(h0, h1);
    hp[1] = __halves2bfloat162(h2, h3);
    lp[0] = __halves2bfloat162(l0, l1);
    lp[1] = __halves2bfloat162(l2, l3);
}

// ---------------------------------------------------------------------------
// Tensor-core GEMM on pre-split bf16, double-buffered smem (dynamic, 76KB).
// C = Ah@Bh + Ah@Bl + Al@Bh. 128x128x32 tile, 256 threads.
// MODE 0: plain fp32 store. MODE 1: window-reverse + out += alpha*(acc+bias).
// ---------------------------------------------------------------------------
#define GEMM_SMEM_BYTES ((2 * 5120 + 2 * 5120 + 2 * 4352 + 2 * 4352) * 2)

template<int MODE>
__global__ __launch_bounds__(256) void gemm_bf16(
    const __nv_bfloat16* __restrict__ Ah, const __nv_bfloat16* __restrict__ Al,
    const __nv_bfloat16* __restrict__ Bh, const __nv_bfloat16* __restrict__ Bl,
    float* __restrict__ C, int M, int N, int K,
    const float* __restrict__ bias, const float* __restrict__ alpha_p)
{
    extern __shared__ __nv_bfloat16 gsm[];
    __nv_bfloat16* pAh = gsm;
    __nv_bfloat16* pAl = gsm + 10240;
    __nv_bfloat16* pBh = gsm + 20480;
    __nv_bfloat16* pBl = gsm + 29184;

    const int tid = threadIdx.x;
    const int lane = tid & 31;
    const int wid = tid >> 5;
    const int wm = (wid & 1) * 64;
    const int wn = (wid >> 1) * 32;
    const int bm = blockIdx.y * 128;
    const int bn = blockIdx.x * 128;

    float acc[4][4][4];
#pragma unroll
    for (int i = 0; i < 4; i++) {
#pragma unroll
        for (int j = 0; j < 4; j++) {
#pragma unroll
            for (int r = 0; r < 4; r++) {
                acc[i][j][r] = 0.0f;
            }
        }
    }

    const int nk = K >> 5;
    uint4 rAh[2];
    uint4 rAl[2];
    uint4 rBh[2];
    uint4 rBl[2];

#pragma unroll
    for (int i = 0; i < 2; i++) {
        int u = tid + i * 256;
        int ar = u >> 2;
        int ac = (u & 3) * 8;
        size_t aidx = (size_t)(bm + ar) * K + ac;
        rAh[i] = *reinterpret_cast<const uint4*>(Ah + aidx);
        rAl[i] = *reinterpret_cast<const uint4*>(Al + aidx);
        int br = u >> 4;
        int bc = (u & 15) * 8;
        size_t bidx = (size_t)br * N + bn + bc;
        rBh[i] = *reinterpret_cast<const uint4*>(Bh + bidx);
        rBl[i] = *reinterpret_cast<const uint4*>(Bl + bidx);
    }
#pragma unroll
    for (int i = 0; i < 2; i++) {
        int u = tid + i * 256;
        int ar = u >> 2;
        int ac = (u & 3) * 8;
        *reinterpret_cast<uint4*>(pAh + ar * 40 + ac) = rAh[i];
        *reinterpret_cast<uint4*>(pAl + ar * 40 + ac) = rAl[i];
        int br = u >> 4;
        int bc = (u & 15) * 8;
        *reinterpret_cast<uint4*>(pBh + br * 136 + bc) = rBh[i];
        *reinterpret_cast<uint4*>(pBl + br * 136 + bc) = rBl[i];
    }
    __syncthreads();

    const int a_r = lane & 15;
    const int a_k = (lane >> 4) * 8;

    for (int kt = 0; kt < nk; kt++) {
        const int curA = (kt & 1) * 5120;
        const int curB = (kt & 1) * 4352;

        if (kt + 1 < nk) {
#pragma unroll
            for (int i = 0; i < 2; i++) {
                int u = tid + i * 256;
                int ar = u >> 2;
                int ac = (u & 3) * 8;
                size_t aidx = (size_t)(bm + ar) * K + (kt + 1) * 32 + ac;
                rAh[i] = *reinterpret_cast<const uint4*>(Ah + aidx);
                rAl[i] = *reinterpret_cast<const uint4*>(Al + aidx);
                int br = u >> 4;
                int bc = (u & 15) * 8;
                size_t bidx = (size_t)((kt + 1) * 32 + br) * N + bn + bc;
                rBh[i] = *reinterpret_cast<const uint4*>(Bh + bidx);
                rBl[i] = *reinterpret_cast<const uint4*>(Bl + bidx);
            }
        }

#pragma unroll
        for (int ks = 0; ks < 2; ks++) {
            u32 aH[4][4];
            u32 aL[4][4];
            u32 bH[4][2];
            u32 bL[4][2];
#pragma unroll
            for (int mi = 0; mi < 4; mi++) {
                u32 adr = smem_u32(pAh + curA + (wm + mi * 16 + a_r) * 40 + ks * 16 + a_k);
                ldsm_x4(aH[mi][0], aH[mi][1], aH[mi][2], aH[mi][3], adr);
                adr = smem_u32(pAl + curA + (wm + mi * 16 + a_r) * 40 + ks * 16 + a_k);
                ldsm_x4(aL[mi][0], aL[mi][1], aL[mi][2], aL[mi][3], adr);
            }
#pragma unroll
            for (int nj = 0; nj < 2; nj++) {
                u32 r0;
                u32 r1;
                u32 r2;
                u32 r3;
                u32 adr = smem_u32(pBh + curB + (ks * 16 + a_r) * 136 + wn + nj * 16 + a_k);
                ldsm_x4t(r0, r1, r2, r3, adr);
                bH[nj * 2][0] = r0;
                bH[nj * 2][1] = r1;
                bH[nj * 2 + 1][0] = r2;
                bH[nj * 2 + 1][1] = r3;
                adr = smem_u32(pBl + curB + (ks * 16 + a_r) * 136 + wn + nj * 16 + a_k);
                ldsm_x4t(r0, r1, r2, r3, adr);
                bL[nj * 2][0] = r0;
                bL[nj * 2][1] = r1;
                bL[nj * 2 + 1][0] = r2;
                bL[nj * 2 + 1][1] = r3;
            }
#pragma unroll
            for (int mi = 0; mi < 4; mi++) {
#pragma unroll
                for (int ni = 0; ni < 4; ni++) {
                    mma_bf16(acc[mi][ni], aH[mi], bH[ni]);
                    mma_bf16(acc[mi][ni], aH[mi], bL[ni]);
                    mma_bf16(acc[mi][ni], aL[mi], bH[ni]);
                }
            }
        }

        if (kt + 1 < nk) {
            const int nxtA = ((kt + 1) & 1) * 5120;
            const int nxtB = ((kt + 1) & 1) * 4352;
#pragma unroll
            for (int i = 0; i < 2; i++) {
                int u = tid + i * 256;
                int ar = u >> 2;
                int ac = (u & 3) * 8;
                *reinterpret_cast<uint4*>(pAh + nxtA + ar * 40 + ac) = rAh[i];
                *reinterpret_cast<uint4*>(pAl + nxtA + ar * 40 + ac) = rAl[i];
                int br = u >> 4;
                int bc = (u & 15) * 8;
                *reinterpret_cast<uint4*>(pBh + nxtB + br * 136 + bc) = rBh[i];
                *reinterpret_cast<uint4*>(pBl + nxtB + br * 136 + bc) = rBl[i];
            }
        }
        __syncthreads();
    }

    const int g = lane >> 2;
    const int tg = lane & 3;

    if (MODE == 0) {
#pragma unroll
        for (int mi = 0; mi < 4; mi++) {
            int row0 = bm + wm + mi * 16 + g;
#pragma unroll
            for (int ni = 0; ni < 4; ni++) {
                int col = bn + wn + ni * 8 + tg * 2;
                float2 v0;
                float2 v1;
                v0.x = acc[mi][ni][0];
                v0.y = acc[mi][ni][1];
                v1.x = acc[mi][ni][2];
                v1.y = acc[mi][ni][3];
                *reinterpret_cast<float2*>(&C[(size_t)row0 * N + col]) = v0;
                *reinterpret_cast<float2*>(&C[(size_t)(row0 + 8) * N + col]) = v1;
            }
        }
    } else {
        const float alpha = alpha_p[0];
#pragma unroll
        for (int mi = 0; mi < 4; mi++) {
#pragma unroll
            for (int half = 0; half < 2; half++) {
                int row = bm + wm + mi * 16 + g + half * 8;
                int win = row >> 6;
                int tok = row & 63;
                int b = win >> 8;
                int r2 = win & 255;
                int dblk = r2 >> 6;
                int h2 = r2 & 63;
                int hblk = h2 >> 3;
                int wblk = h2 & 7;
                int z4 = tok >> 4;
                int y4 = (tok >> 2) & 3;
                int x4 = tok & 3;
                size_t spat = (((size_t)b * 16 + dblk * 4 + z4) * 32 + hblk * 4 + y4) * 32
                              + wblk * 4 + x4;
#pragma unroll
                for (int ni = 0; ni < 4; ni++) {
                    int col = bn + wn + ni * 8 + tg * 2;
                    float2 pb = *reinterpret_cast<const float2*>(&bias[col]);
                    float* dst = &C[spat * 256 + col];
                    float2 e = *reinterpret_cast<float2*>(dst);
                    e.x += alpha * (acc[mi][ni][half * 2 + 0] + pb.x);
                    e.y += alpha * (acc[mi][ni][half * 2 + 1] + pb.y);
                    *reinterpret_cast<float2*>(dst) = e;
                }
            }
        }
    }
}

// ---------------------------------------------------------------------------
// fconv
// ---------------------------------------------------------------------------
__global__ __launch_bounds__(1024) void fconv_kernel(
    const float* __restrict__ fcw, const float* __restrict__ fcb)
{
    __shared__ float s_fcw[27 * 24];
    __shared__ float s_fcb[27];
    __shared__ float s_out[32 * 9 * 33];

    const int tid = threadIdx.x;
    const int b = blockIdx.y;
    const int l0 = blockIdx.x * 32;

    if (tid < 648) {
        s_fcw[tid] = fcw[tid];
    }
    if (tid < 27) {
        s_fcb[tid] = fcb[tid];
    }
    __syncthreads();

    const float* qb = g_qkv + (size_t)b * 12582912;
    float acc[27];
#pragma unroll
    for (int o = 0; o < 27; o++) {
        acc[o] = s_fcb[o];
    }

#pragma unroll 4
    for (int g = 0; g < 24; g++) {
        float v = qb[(size_t)g * 524288 + (size_t)l0 * 32 + tid];
#pragma unroll
        for (int o = 0; o < 27; o++) {
            acc[o] = fmaf(s_fcw[o * 24 + g], v, acc[o]);
        }
    }

    const int xx = tid & 31;
    const int ll = tid >> 5;
    float* fco = g_fconv + (size_t)b * 864 * LSP;
#pragma unroll
    for (int r = 0; r < 3; r++) {
#pragma unroll
        for (int oo = 0; oo < 9; oo++) {
            s_out[(xx * 9 + oo) * 33 + ll] = acc[r * 9 + oo];
        }
        __syncthreads();
#pragma unroll
        for (int it = 0; it < 9; it++) {
            int e = it * 1024 + tid;
            int l = e & 31;
            int rest = e >> 5;
            int o = rest % 9;
            int x2 = rest / 9;
            fco[(size_t)(x2 * 27 + r * 9 + o) * LSP + l0 + l] =
                s_out[(x2 * 9 + o) * 33 + l];
        }
        __syncthreads();
    }
}

// ---------------------------------------------------------------------------
// Grouped conv: 2z x 8y x 32x tile, 512 threads, per-thread 2oc x 4x.
// k-reduction streamed in 2 chunks (14 + 13) so window smem fits 2 blocks/SM:
//   window chunk 14*4*10*36 = 80.6KB, weights 31.1KB -> 111.7KB total.
// ---------------------------------------------------------------------------
#define CONV_KCHUNK 14
#define CONV_SW_FLOATS  (CONV_KCHUNK * 4 * 10 * 36)
#define CONV_DEP_FLOATS (8 * 27 * 9 * 4)
#define CONV_SMEM_BYTES ((CONV_SW_FLOATS + CONV_DEP_FLOATS) * 4)

__device__ __forceinline__ void conv_load_chunk(
    float* sw, const float* fin, int tid, int y0, int z0, int kbase, int nk)
{
    for (int e = tid; e < nk * 1360; e += 512) {
        int x = e % 34;
        int t1 = e / 34;
        int yy = t1 % 10;
        int t2 = t1 / 10;
        int wz = t2 & 3;
        int kl = t2 >> 2;
        int gx = x - 1;
        int gy = y0 + yy - 1;
        int gz = z0 + wz - 1;
        float v = 0.0f;
        if (gx >= 0 && gx < 32 && gy >= 0 && gy < 32 && gz >= 0 && gz < 16) {
            v = fin[(size_t)(kbase + kl) * LSP + gz * 1024 + gy * 32 + gx];
        }
        sw[((kl * 4 + wz) * 10 + yy) * 36 + x] = v;
    }
}

__global__ __launch_bounds__(512) void conv_kernel(
    const float* __restrict__ dep_w, const float* __restrict__ dep_b,
    const float* __restrict__ beta_p, float* __restrict__ out)
{
    extern __shared__ float sm[];
    float* sw = sm;
    float* sdep = sm + CONV_SW_FLOATS;

    const int tid = threadIdx.x;
    const int y0 = blockIdx.x * 8;
    const int z0 = blockIdx.y * 2;
    const int bg = blockIdx.z;
    const int b = bg >> 5;
    const int g = bg & 31;

    // weights: dep_w[(g*8+ocl)*729 + k*27 + dydz*3 + dx]
    //   -> sdep[((ocl*27 + k)*9 + dydz)*4 + dx], dx==3 slot zero-padded
    for (int e = tid; e < CONV_DEP_FLOATS; e += 512) {
        int dx = e & 3;
        int rest = e >> 2;
        int dydz = rest % 9;
        int rest2 = rest / 9;
        int k = rest2 % 27;
        int ocl = rest2 / 27;
        float v = 0.0f;
        if (dx < 3) {
            v = dep_w[(size_t)(g * 8 + ocl) * 729 + k * 27 + dydz * 3 + dx];
        }
        sdep[e] = v;
    }

    const float* fin = g_fconv + ((size_t)(b * 864 + g * 27)) * LSP;
    conv_load_chunk(sw, fin, tid, y0, z0, 0, CONV_KCHUNK);
    __syncthreads();

    const int xq = tid & 7;
    const int ocp = (tid >> 3) & 3;
    const int yy = (tid >> 5) & 7;
    const int zz = tid >> 8;
    const int oc0 = ocp * 2;

    float acc0[4] = {0.0f, 0.0f, 0.0f, 0.0f};
    float acc1[4] = {0.0f, 0.0f, 0.0f, 0.0f};

    const float* wd0 = sdep + oc0 * 972;
    const float* wd1 = wd0 + 972;

#pragma unroll
    for (int chunk = 0; chunk < 2; chunk++) {
        const int kbase = chunk * CONV_KCHUNK;
        const int nk = (chunk == 0) ? CONV_KCHUNK : (27 - CONV_KCHUNK);
#pragma unroll 1
        for (int kl = 0; kl < nk; kl++) {
            const int k = kbase + kl;
#pragma unroll
            for (int dz = 0; dz < 3; dz++) {
#pragma unroll
                for (int dy = 0; dy < 3; dy++) {
                    const float* wrow = &sw[((kl * 4 + zz + dz) * 10 + yy + dy) * 36 + xq * 4];
                    float4 wa = *reinterpret_cast<const float4*>(wrow);
                    float2 wb = *reinterpret_cast<const float2*>(wrow + 4);
                    float win[6];
                    win[0] = wa.x; win[1] = wa.y; win[2] = wa.z; win[3] = wa.w;
                    win[4] = wb.x; win[5] = wb.y;
                    float4 w0v = *reinterpret_cast<const float4*>(wd0 + (k * 9 + dz * 3 + dy) * 4);
                    float4 w1v = *reinterpret_cast<const float4*>(wd1 + (k * 9 + dz * 3 + dy) * 4);
                    float w0[3];
                    float w1[3];
                    w0[0] = w0v.x; w0[1] = w0v.y; w0[2] = w0v.z;
                    w1[0] = w1v.x; w1[1] = w1v.y; w1[2] = w1v.z;
#pragma unroll
                    for (int dx = 0; dx < 3; dx++) {
#pragma unroll
                        for (int c = 0; c < 4; c++) {
                            acc0[c] = fmaf(win[c + dx], w0[dx], acc0[c]);
                            acc1[c] = fmaf(win[c + dx], w1[dx], acc1[c]);
                        }
                    }
                }
            }
        }
        if (chunk == 0) {
            __syncthreads();
            conv_load_chunk(sw, fin, tid, y0, z0, CONV_KCHUNK, 27 - CONV_KCHUNK);
            __syncthreads();
        }
    }

    const float beta = beta_p[0];
    const int ocg0 = g * 8 + oc0;
    const float b0 = dep_b[ocg0];
    const float b1 = dep_b[ocg0 + 1];
    const size_t spatbase = (size_t)b * LSP + (z0 + zz) * 1024 + (y0 + yy) * 32 + xq * 4;
#pragma unroll
    for (int c = 0; c < 4; c++) {
        float2 v;
        v.x = beta * (acc0[c] + b0);
        v.y = beta * (acc1[c] + b1);
        *reinterpret_cast<float2*>(out + (spatbase + c) * 256 + ocg0) = v;
    }
}

// ---------------------------------------------------------------------------
// Windowed attention -> bf16 split output (g_ah/g_al).
// ---------------------------------------------------------------------------
__global__ __launch_bounds__(256) void attn_kernel(const float* __restrict__ rpb)
{
    __shared__ __align__(16) float sq[64][36];
    __shared__ __align__(16) float skT[32][68];
    __shared__ __align__(16) float sv[64][36];
    __shared__ __align__(16) float sS[64][68];
    __shared__ float sbias[343];

    const int tid = threadIdx.x;
    const int win = blockIdx.x;
    const int head = blockIdx.y;
    const int b = win >> 8;
    const int rr = win & 255;
    const int dblk = rr >> 6;
    const int h2 = rr & 63;
    const int hblk = h2 >> 3;
    const int wblk = h2 & 7;

    for (int i = tid; i < 343; i += 256) {
        sbias[i] = rpb[i * 8 + head];
    }

    for (int e = tid; e < 64 * 32; e += 256) {
        int tok = e >> 5;
        int dd = e & 31;
        int z = tok >> 4;
        int y = (tok >> 2) & 3;
        int x = tok & 3;
        size_t spat = (((size_t)b * 16 + dblk * 4 + z) * 32 + hblk * 4 + y) * 32
                      + wblk * 4 + x;
        const float* src = g_qkv + spat * 768 + head * 32 + dd;
        sq[tok][dd] = src[0];
        skT[dd][tok] = src[256];
        sv[tok][dd] = src[512];
    }
    __syncthreads();

    const int i4 = tid >> 4;
    const int jq = tid & 15;
    const int i0 = i4 * 4;
    const int j0 = jq * 4;

    float dots[4][4];
#pragma unroll
    for (int r = 0; r < 4; r++) {
#pragma unroll
        for (int c = 0; c < 4; c++) {
            dots[r][c] = 0.0f;
        }
    }

#pragma unroll
    for (int d8 = 0; d8 < 4; d8++) {
        float qreg[4][8];
#pragma unroll
        for (int r = 0; r < 4; r++) {
            float4 q0 = *reinterpret_cast<const float4*>(&sq[i0 + r][d8 * 8]);
            float4 q1 = *reinterpret_cast<const float4*>(&sq[i0 + r][d8 * 8 + 4]);
            qreg[r][0] = q0.x; qreg[r][1] = q0.y; qreg[r][2] = q0.z; qreg[r][3] = q0.w;
            qreg[r][4] = q1.x; qreg[r][5] = q1.y; qreg[r][6] = q1.z; qreg[r][7] = q1.w;
        }
#pragma unroll
        for (int dd = 0; dd < 8; dd++) {
            float4 kv = *reinterpret_cast<const float4*>(&skT[d8 * 8 + dd][j0]);
#pragma unroll
            for (int r = 0; r < 4; r++) {
                dots[r][0] = fmaf(qreg[r][dd], kv.x, dots[r][0]);
                dots[r][1] = fmaf(qreg[r][dd], kv.y, dots[r][1]);
                dots[r][2] = fmaf(qreg[r][dd], kv.z, dots[r][2]);
                dots[r][3] = fmaf(qreg[r][dd], kv.w, dots[r][3]);
            }
        }
    }

    const float scale = 0.17677669529663687f;
#pragma unroll
    for (int r = 0; r < 4; r++) {
        int ti = i0 + r;
        int zi = ti >> 4;
        int yi = (ti >> 2) & 3;
        int xi = ti & 3;
        float sv4[4];
#pragma unroll
        for (int c = 0; c < 4; c++) {
            int tj = j0 + c;
            int zj = tj >> 4;
            int yj = (tj >> 2) & 3;
            int xj = tj & 3;
            int rel = (zi - zj + 3) * 49 + (yi - yj + 3) * 7 + (xi - xj + 3);
            sv4[c] = dots[r][c] * scale + sbias[rel];
        }
        float rmax = fmaxf(fmaxf(sv4[0], sv4[1]), fmaxf(sv4[2], sv4[3]));
        rmax = warp16_max(rmax);
        float rsum = 0.0f;
#pragma unroll
        for (int c = 0; c < 4; c++) {
            sv4[c] = __expf(sv4[c] - rmax);
            rsum += sv4[c];
        }
        rsum = warp16_sum(rsum);
        float inv = 1.0f / rsum;
        float4 pv;
        pv.x = sv4[0] * inv;
        pv.y = sv4[1] * inv;
        pv.z = sv4[2] * inv;
        pv.w = sv4[3] * inv;
        *reinterpret_cast<float4*>(&sS[i0 + r][j0]) = pv;
    }
    __syncthreads();

    const int p2 = tid >> 3;
    const int dg = tid & 7;
    const int r0 = p2 * 2;
    const int r1 = r0 + 1;
    float o0[4] = {0.0f, 0.0f, 0.0f, 0.0f};
    float o1[4] = {0.0f, 0.0f, 0.0f, 0.0f};
#pragma unroll 4
    for (int j = 0; j < 64; j++) {
        float4 v = *reinterpret_cast<const float4*>(&sv[j][dg * 4]);
        float pa = sS[r0][j];
        float pbv = sS[r1][j];
        o0[0] = fmaf(pa, v.x, o0[0]);
        o0[1] = fmaf(pa, v.y, o0[1]);
        o0[2] = fmaf(pa, v.z, o0[2]);
        o0[3] = fmaf(pa, v.w, o0[3]);
        o1[0] = fmaf(pbv, v.x, o1[0]);
        o1[1] = fmaf(pbv, v.y, o1[1]);
        o1[2] = fmaf(pbv, v.z, o1[2]);
        o1[3] = fmaf(pbv, v.w, o1[3]);
    }
    size_t off0 = ((size_t)win * 64 + r0) * 256 + head * 32 + dg * 4;
    size_t off1 = ((size_t)win * 64 + r1) * 256 + head * 32 + dg * 4;
#pragma unroll
    for (int pass = 0; pass < 2; pass++) {
        const float* ov = (pass == 0) ? o0 : o1;
        size_t off = (pass == 0) ? off0 : off1;
        __nv_bfloat16 hh[4];
        __nv_bfloat16 ll[4];
#pragma unroll
        for (int c = 0; c < 4; c++) {
            hh[c] = __float2bfloat16(ov[c]);
            ll[c] = __float2bfloat16(ov[c] - __bfloat162float(hh[c]));
        }
        __nv_bfloat162* hp = reinterpret_cast<__nv_bfloat162*>(g_ah + off);
        __nv_bfloat162* lp = reinterpret_cast<__nv_bfloat162*>(g_al + off);
        hp[0] = __halves2bfloat162(hh[0], hh[1]);
        hp[1] = __halves2bfloat162(hh[2], hh[3]);
        lp[0] = __halves2bfloat162(ll[0], ll[1]);
        lp[1] = __halves2bfloat162(ll[2], ll[3]);
    }
}

// ---------------------------------------------------------------------------
// Launch. Order keeps conv at app-launch index 3 (the ncu-captured slot).
// ---------------------------------------------------------------------------
extern "C" void kernel_launch(void* const* d_in, const int* in_sizes, int n_in,
                              void* d_out, int out_size)
{
    (void)in_sizes;
    (void)n_in;
    (void)out_size;
    const float* x_in   = (const float*)d_in[0];
    const float* qkv_w  = (const float*)d_in[1];
    const float* proj_w = (const float*)d_in[2];
    const float* proj_b = (const float*)d_in[3];
    const float* rpb    = (const float*)d_in[4];
    const float* fc_w   = (const float*)d_in[5];
    const float* fc_b   = (const float*)d_in[6];
    const float* dep_w  = (const float*)d_in[7];
    const float* dep_b  = (const float*)d_in[8];
    const float* alpha  = (const float*)d_in[9];
    const float* beta   = (const float*)d_in[10];
    float* out = (float*)d_out;

    float* p_qkv;
    __nv_bfloat16* p_xh;
    __nv_bfloat16* p_xl;
    __nv_bfloat16* p_ah;
    __nv_bfloat16* p_al;
    __nv_bfloat16* p_wqh;
    __nv_bfloat16* p_wql;
    __nv_bfloat16* p_pwh;
    __nv_bfloat16* p_pwl;
    cudaGetSymbolAddress((void**)&p_qkv, g_qkv);
    cudaGetSymbolAddress((void**)&p_xh, g_xh);
    cudaGetSymbolAddress((void**)&p_xl, g_xl);
    cudaGetSymbolAddress((void**)&p_ah, g_ah);
    cudaGetSymbolAddress((void**)&p_al, g_al);
    cudaGetSymbolAddress((void**)&p_wqh, g_wqh);
    cudaGetSymbolAddress((void**)&p_wql, g_wql);
    cudaGetSymbolAddress((void**)&p_pwh, g_pwh);
    cudaGetSymbolAddress((void**)&p_pwl, g_pwl);

    cudaFuncSetAttribute(gemm_bf16<0>, cudaFuncAttributeMaxDynamicSharedMemorySize,
                         GEMM_SMEM_BYTES);
    cudaFuncSetAttribute(gemm_bf16<1>, cudaFuncAttributeMaxDynamicSharedMemorySize,
                         GEMM_SMEM_BYTES);
    cudaFuncSetAttribute(conv_kernel, cudaFuncAttributeMaxDynamicSharedMemorySize,
                         CONV_SMEM_BYTES);

    // 0) merged bf16 splits
    split3_kernel<<<16640, 256>>>(x_in, qkv_w, proj_w);
    // 1) qkv = x_in @ qkv_w
    gemm_bf16<0><<<dim3(6, 512), 256, GEMM_SMEM_BYTES>>>(
        p_xh, p_xl, p_wqh, p_wql, p_qkv, 65536, 768, 256,
        (const float*)0, (const float*)0);
    // 2) f_conv
    fconv_kernel<<<dim3(512, 4), 1024>>>(fc_w, fc_b);
    // 3) grouped conv (k-chunked, 2 blocks/SM) -> out = beta*(conv + dep_b)
    conv_kernel<<<dim3(4, 8, 128), 512, CONV_SMEM_BYTES>>>(dep_w, dep_b, beta, out);
    // 4) attention -> g_ah/g_al (bf16 split)
    attn_kernel<<<dim3(1024, 8), 256>>>(rpb);
    // 5) proj + window-reverse + out += alpha*(...)
    gemm_bf16<1><<<dim3(2, 512), 256, GEMM_SMEM_BYTES>>>(
        p_ah, p_al, p_pwh, p_pwl, out, 65536, 256, 256, proj_b, alpha);
}

// round 10
// speedup vs baseline: 1.7326x; 1.0032x over previous
#include <cuda_runtime.h>
#include <cuda_bf16.h>
#include <stdint.h>
#include <math.h>

typedef unsigned int u32;

// ---------------------------------------------------------------------------
// x_in [4,16,32,32,256], qkv_w [256,768], proj_w [256,256], proj_b [256]
// rpb_table [343,8], fc_w [27,24], fc_b [27], dep_w [256,27,3,3,3],
// dep_b [256], alpha, beta; out [4,16,32,32,256] float32
// ---------------------------------------------------------------------------
#define LSP 16384

__device__ float g_qkv  [(size_t)65536 * 768];
__device__ float g_fconv[(size_t)4 * 864 * LSP];

__device__ __nv_bfloat16 g_xh[(size_t)65536 * 256];
__device__ __nv_bfloat16 g_xl[(size_t)65536 * 256];
__device__ __nv_bfloat16 g_ah[(size_t)65536 * 256];
__device__ __nv_bfloat16 g_al[(size_t)65536 * 256];
__device__ __nv_bfloat16 g_wqh[256 * 768];
__device__ __nv_bfloat16 g_wql[256 * 768];
__device__ __nv_bfloat16 g_pwh[256 * 256];
__device__ __nv_bfloat16 g_pwl[256 * 256];

__device__ __forceinline__ u32 smem_u32(const void* p) {
    return (u32)__cvta_generic_to_shared(p);
}

__device__ __forceinline__ void ldsm_x4(u32& r0, u32& r1, u32& r2, u32& r3, u32 a) {
    asm volatile("ldmatrix.sync.aligned.m8n8.x4.shared.b16 {%0,%1,%2,%3}, [%4];\n"
                 : "=r"(r0), "=r"(r1), "=r"(r2), "=r"(r3) : "r"(a));
}

__device__ __forceinline__ void ldsm_x4t(u32& r0, u32& r1, u32& r2, u32& r3, u32 a) {
    asm volatile("ldmatrix.sync.aligned.m8n8.x4.trans.shared.b16 {%0,%1,%2,%3}, [%4];\n"
                 : "=r"(r0), "=r"(r1), "=r"(r2), "=r"(r3) : "r"(a));
}

__device__ __forceinline__ void mma_bf16(float* c, const u32* a, const u32* b) {
    asm volatile(
        "mma.sync.aligned.m16n8k16.row.col.f32.bf16.bf16.f32 "
        "{%0,%1,%2,%3}, {%4,%5,%6,%7}, {%8,%9}, {%0,%1,%2,%3};\n"
        : "+f"(c[0]), "+f"(c[1]), "+f"(c[2]), "+f"(c[3])
        : "r"(a[0]), "r"(a[1]), "r"(a[2]), "r"(a[3]), "r"(b[0]), "r"(b[1]));
}

__device__ __forceinline__ float warp16_max(float v) {
    v = fmaxf(v, __shfl_xor_sync(0xffffffffu, v, 1));
    v = fmaxf(v, __shfl_xor_sync(0xffffffffu, v, 2));
    v = fmaxf(v, __shfl_xor_sync(0xffffffffu, v, 4));
    v = fmaxf(v, __shfl_xor_sync(0xffffffffu, v, 8));
    return v;
}

__device__ __forceinline__ float warp16_sum(float v) {
    v += __shfl_xor_sync(0xffffffffu, v, 1);
    v += __shfl_xor_sync(0xffffffffu, v, 2);
    v += __shfl_xor_sync(0xffffffffu, v, 4);
    v += __shfl_xor_sync(0xffffffffu, v, 8);
    return v;
}

// ---------------------------------------------------------------------------
// Merged elementwise fp32 -> (bf16 hi, bf16 lo) split for all 3 tensors.
// ---------------------------------------------------------------------------
#define SPLIT_N1 4194304
#define SPLIT_N2 49152
#define SPLIT_N3 16384

__global__ __launch_bounds__(256) void split3_kernel(
    const float* __restrict__ x, const float* __restrict__ wq,
    const float* __restrict__ pw)
{
    int i = blockIdx.x * blockDim.x + threadIdx.x;
    const float* s;
    __nv_bfloat16* h;
    __nv_bfloat16* l;
    int idx;
    if (i < SPLIT_N1) {
        s = x;
        h = g_xh;
        l = g_xl;
        idx = i;
    } else if (i < SPLIT_N1 + SPLIT_N2) {
        s = wq;
        h = g_wqh;
        l = g_wql;
        idx = i - SPLIT_N1;
    } else if (i < SPLIT_N1 + SPLIT_N2 + SPLIT_N3) {
        s = pw;
        h = g_pwh;
        l = g_pwl;
        idx = i - SPLIT_N1 - SPLIT_N2;
    } else {
        return;
    }
    float4 v = reinterpret_cast<const float4*>(s)[idx];
    __nv_bfloat16 h0 = __float2bfloat16(v.x);
    __nv_bfloat16 h1 = __float2bfloat16(v.y);
    __nv_bfloat16 h2 = __float2bfloat16(v.z);
    __nv_bfloat16 h3 = __float2bfloat16(v.w);
    __nv_bfloat16 l0 = __float2bfloat16(v.x - __bfloat162float(h0));
    __nv_bfloat16 l1 = __float2bfloat16(v.y - __bfloat162float(h1));
    __nv_bfloat16 l2 = __float2bfloat16(v.z - __bfloat162float(h2));
    __nv_bfloat16 l3 = __float2bfloat16(v.w - __bfloat162float(h3));
    __nv_bfloat162* hp = reinterpret_cast<__nv_bfloat162*>(h) + idx * 2;
    __nv_bfloat162* lp = reinterpret_cast<__nv_bfloat162*>(l) + idx * 2;
    hp[0] = __halves2bfloat162(h0, h1);
    hp[1] = __halves2bfloat162(h2, h3);
    lp[0] = __halves2bfloat162(l0, l1);
    lp[1] = __halves2bfloat162(l2, l3);
}

// ---------------------------------------------------------------------------
// Tensor-core GEMM on pre-split bf16, double-buffered smem (dynamic, 76KB).
// ---------------------------------------------------------------------------
#define GEMM_SMEM_BYTES ((2 * 5120 + 2 * 5120 + 2 * 4352 + 2 * 4352) * 2)

template<int MODE>
__global__ __launch_bounds__(256) void gemm_bf16(
    const __nv_bfloat16* __restrict__ Ah, const __nv_bfloat16* __restrict__ Al,
    const __nv_bfloat16* __restrict__ Bh, const __nv_bfloat16* __restrict__ Bl,
    float* __restrict__ C, int M, int N, int K,
    const float* __restrict__ bias, const float* __restrict__ alpha_p)
{
    extern __shared__ __nv_bfloat16 gsm[];
    __nv_bfloat16* pAh = gsm;
    __nv_bfloat16* pAl = gsm + 10240;
    __nv_bfloat16* pBh = gsm + 20480;
    __nv_bfloat16* pBl = gsm + 29184;

    const int tid = threadIdx.x;
    const int lane = tid & 31;
    const int wid = tid >> 5;
    const int wm = (wid & 1) * 64;
    const int wn = (wid >> 1) * 32;
    const int bm = blockIdx.y * 128;
    const int bn = blockIdx.x * 128;

    float acc[4][4][4];
#pragma unroll
    for (int i = 0; i < 4; i++) {
#pragma unroll
        for (int j = 0; j < 4; j++) {
#pragma unroll
            for (int r = 0; r < 4; r++) {
                acc[i][j][r] = 0.0f;
            }
        }
    }

    const int nk = K >> 5;
    uint4 rAh[2];
    uint4 rAl[2];
    uint4 rBh[2];
    uint4 rBl[2];

#pragma unroll
    for (int i = 0; i < 2; i++) {
        int u = tid + i * 256;
        int ar = u >> 2;
        int ac = (u & 3) * 8;
        size_t aidx = (size_t)(bm + ar) * K + ac;
        rAh[i] = *reinterpret_cast<const uint4*>(Ah + aidx);
        rAl[i] = *reinterpret_cast<const uint4*>(Al + aidx);
        int br = u >> 4;
        int bc = (u & 15) * 8;
        size_t bidx = (size_t)br * N + bn + bc;
        rBh[i] = *reinterpret_cast<const uint4*>(Bh + bidx);
        rBl[i] = *reinterpret_cast<const uint4*>(Bl + bidx);
    }
#pragma unroll
    for (int i = 0; i < 2; i++) {
        int u = tid + i * 256;
        int ar = u >> 2;
        int ac = (u & 3) * 8;
        *reinterpret_cast<uint4*>(pAh + ar * 40 + ac) = rAh[i];
        *reinterpret_cast<uint4*>(pAl + ar * 40 + ac) = rAl[i];
        int br = u >> 4;
        int bc = (u & 15) * 8;
        *reinterpret_cast<uint4*>(pBh + br * 136 + bc) = rBh[i];
        *reinterpret_cast<uint4*>(pBl + br * 136 + bc) = rBl[i];
    }
    __syncthreads();

    const int a_r = lane & 15;
    const int a_k = (lane >> 4) * 8;

    for (int kt = 0; kt < nk; kt++) {
        const int curA = (kt & 1) * 5120;
        const int curB = (kt & 1) * 4352;

        if (kt + 1 < nk) {
#pragma unroll
            for (int i = 0; i < 2; i++) {
                int u = tid + i * 256;
                int ar = u >> 2;
                int ac = (u & 3) * 8;
                size_t aidx = (size_t)(bm + ar) * K + (kt + 1) * 32 + ac;
                rAh[i] = *reinterpret_cast<const uint4*>(Ah + aidx);
                rAl[i] = *reinterpret_cast<const uint4*>(Al + aidx);
                int br = u >> 4;
                int bc = (u & 15) * 8;
                size_t bidx = (size_t)((kt + 1) * 32 + br) * N + bn + bc;
                rBh[i] = *reinterpret_cast<const uint4*>(Bh + bidx);
                rBl[i] = *reinterpret_cast<const uint4*>(Bl + bidx);
            }
        }

#pragma unroll
        for (int ks = 0; ks < 2; ks++) {
            u32 aH[4][4];
            u32 aL[4][4];
            u32 bH[4][2];
            u32 bL[4][2];
#pragma unroll
            for (int mi = 0; mi < 4; mi++) {
                u32 adr = smem_u32(pAh + curA + (wm + mi * 16 + a_r) * 40 + ks * 16 + a_k);
                ldsm_x4(aH[mi][0], aH[mi][1], aH[mi][2], aH[mi][3], adr);
                adr = smem_u32(pAl + curA + (wm + mi * 16 + a_r) * 40 + ks * 16 + a_k);
                ldsm_x4(aL[mi][0], aL[mi][1], aL[mi][2], aL[mi][3], adr);
            }
#pragma unroll
            for (int nj = 0; nj < 2; nj++) {
                u32 r0;
                u32 r1;
                u32 r2;
                u32 r3;
                u32 adr = smem_u32(pBh + curB + (ks * 16 + a_r) * 136 + wn + nj * 16 + a_k);
                ldsm_x4t(r0, r1, r2, r3, adr);
                bH[nj * 2][0] = r0;
                bH[nj * 2][1] = r1;
                bH[nj * 2 + 1][0] = r2;
                bH[nj * 2 + 1][1] = r3;
                adr = smem_u32(pBl + curB + (ks * 16 + a_r) * 136 + wn + nj * 16 + a_k);
                ldsm_x4t(r0, r1, r2, r3, adr);
                bL[nj * 2][0] = r0;
                bL[nj * 2][1] = r1;
                bL[nj * 2 + 1][0] = r2;
                bL[nj * 2 + 1][1] = r3;
            }
#pragma unroll
            for (int mi = 0; mi < 4; mi++) {
#pragma unroll
                for (int ni = 0; ni < 4; ni++) {
                    mma_bf16(acc[mi][ni], aH[mi], bH[ni]);
                    mma_bf16(acc[mi][ni], aH[mi], bL[ni]);
                    mma_bf16(acc[mi][ni], aL[mi], bH[ni]);
                }
            }
        }

        if (kt + 1 < nk) {
            const int nxtA = ((kt + 1) & 1) * 5120;
            const int nxtB = ((kt + 1) & 1) * 4352;
#pragma unroll
            for (int i = 0; i < 2; i++) {
                int u = tid + i * 256;
                int ar = u >> 2;
                int ac = (u & 3) * 8;
                *reinterpret_cast<uint4*>(pAh + nxtA + ar * 40 + ac) = rAh[i];
                *reinterpret_cast<uint4*>(pAl + nxtA + ar * 40 + ac) = rAl[i];
                int br = u >> 4;
                int bc = (u & 15) * 8;
                *reinterpret_cast<uint4*>(pBh + nxtB + br * 136 + bc) = rBh[i];
                *reinterpret_cast<uint4*>(pBl + nxtB + br * 136 + bc) = rBl[i];
            }
        }
        __syncthreads();
    }

    const int g = lane >> 2;
    const int tg = lane & 3;

    if (MODE == 0) {
#pragma unroll
        for (int mi = 0; mi < 4; mi++) {
            int row0 = bm + wm + mi * 16 + g;
#pragma unroll
            for (int ni = 0; ni < 4; ni++) {
                int col = bn + wn + ni * 8 + tg * 2;
                float2 v0;
                float2 v1;
                v0.x = acc[mi][ni][0];
                v0.y = acc[mi][ni][1];
                v1.x = acc[mi][ni][2];
                v1.y = acc[mi][ni][3];
                *reinterpret_cast<float2*>(&C[(size_t)row0 * N + col]) = v0;
                *reinterpret_cast<float2*>(&C[(size_t)(row0 + 8) * N + col]) = v1;
            }
        }
    } else {
        const float alpha = alpha_p[0];
#pragma unroll
        for (int mi = 0; mi < 4; mi++) {
#pragma unroll
            for (int half = 0; half < 2; half++) {
                int row = bm + wm + mi * 16 + g + half * 8;
                int win = row >> 6;
                int tok = row & 63;
                int b = win >> 8;
                int r2 = win & 255;
                int dblk = r2 >> 6;
                int h2 = r2 & 63;
                int hblk = h2 >> 3;
                int wblk = h2 & 7;
                int z4 = tok >> 4;
                int y4 = (tok >> 2) & 3;
                int x4 = tok & 3;
                size_t spat = (((size_t)b * 16 + dblk * 4 + z4) * 32 + hblk * 4 + y4) * 32
                              + wblk * 4 + x4;
#pragma unroll
                for (int ni = 0; ni < 4; ni++) {
                    int col = bn + wn + ni * 8 + tg * 2;
                    float2 pb = *reinterpret_cast<const float2*>(&bias[col]);
                    float* dst = &C[spat * 256 + col];
                    float2 e = *reinterpret_cast<float2*>(dst);
                    e.x += alpha * (acc[mi][ni][half * 2 + 0] + pb.x);
                    e.y += alpha * (acc[mi][ni][half * 2 + 1] + pb.y);
                    *reinterpret_cast<float2*>(dst) = e;
                }
            }
        }
    }
}

// ---------------------------------------------------------------------------
// fconv
// ---------------------------------------------------------------------------
__global__ __launch_bounds__(1024) void fconv_kernel(
    const float* __restrict__ fcw, const float* __restrict__ fcb)
{
    __shared__ float s_fcw[27 * 24];
    __shared__ float s_fcb[27];
    __shared__ float s_out[32 * 9 * 33];

    const int tid = threadIdx.x;
    const int b = blockIdx.y;
    const int l0 = blockIdx.x * 32;

    if (tid < 648) {
        s_fcw[tid] = fcw[tid];
    }
    if (tid < 27) {
        s_fcb[tid] = fcb[tid];
    }
    __syncthreads();

    const float* qb = g_qkv + (size_t)b * 12582912;
    float acc[27];
#pragma unroll
    for (int o = 0; o < 27; o++) {
        acc[o] = s_fcb[o];
    }

#pragma unroll 4
    for (int g = 0; g < 24; g++) {
        float v = qb[(size_t)g * 524288 + (size_t)l0 * 32 + tid];
#pragma unroll
        for (int o = 0; o < 27; o++) {
            acc[o] = fmaf(s_fcw[o * 24 + g], v, acc[o]);
        }
    }

    const int xx = tid & 31;
    const int ll = tid >> 5;
    float* fco = g_fconv + (size_t)b * 864 * LSP;
#pragma unroll
    for (int r = 0; r < 3; r++) {
#pragma unroll
        for (int oo = 0; oo < 9; oo++) {
            s_out[(xx * 9 + oo) * 33 + ll] = acc[r * 9 + oo];
        }
        __syncthreads();
#pragma unroll
        for (int it = 0; it < 9; it++) {
            int e = it * 1024 + tid;
            int l = e & 31;
            int rest = e >> 5;
            int o = rest % 9;
            int x2 = rest / 9;
            fco[(size_t)(x2 * 27 + r * 9 + o) * LSP + l0 + l] =
                s_out[(x2 * 9 + o) * 33 + l];
        }
        __syncthreads();
    }
}

// ---------------------------------------------------------------------------
// Grouped conv: 2z x 16y x 32x tile, 512 threads, per-thread 2oc x 2y x 4x.
// k streamed in 4 chunks (7,7,7,6): window 7*4*18*36 = 72.6KB + weights
// 31.1KB = 103.7KB -> 2 blocks/SM.
// ---------------------------------------------------------------------------
#define CONV_KCHUNK 7
#define CONV_SW_FLOATS  (CONV_KCHUNK * 4 * 18 * 36)
#define CONV_DEP_FLOATS (8 * 27 * 9 * 4)
#define CONV_SMEM_BYTES ((CONV_SW_FLOATS + CONV_DEP_FLOATS) * 4)

__device__ __forceinline__ void conv_load_chunk(
    float* sw, const float* fin, int tid, int y0, int z0, int kbase, int nk)
{
    const int elems = nk * 4 * 18 * 34;
    for (int e = tid; e < elems; e += 512) {
        int x = e % 34;
        int t1 = e / 34;
        int yy = t1 % 18;
        int t2 = t1 / 18;
        int wz = t2 & 3;
        int kl = t2 >> 2;
        int gx = x - 1;
        int gy = y0 + yy - 1;
        int gz = z0 + wz - 1;
        float v = 0.0f;
        if (gx >= 0 && gx < 32 && gy >= 0 && gy < 32 && gz >= 0 && gz < 16) {
            v = fin[(size_t)(kbase + kl) * LSP + gz * 1024 + gy * 32 + gx];
        }
        sw[((kl * 4 + wz) * 18 + yy) * 36 + x] = v;
    }
}

__global__ __launch_bounds__(512, 2) void conv_kernel(
    const float* __restrict__ dep_w, const float* __restrict__ dep_b,
    const float* __restrict__ beta_p, float* __restrict__ out)
{
    extern __shared__ float sm[];
    float* sw = sm;
    float* sdep = sm + CONV_SW_FLOATS;

    const int tid = threadIdx.x;
    const int y0 = blockIdx.x * 16;
    const int z0 = blockIdx.y * 2;
    const int bg = blockIdx.z;
    const int b = bg >> 5;
    const int g = bg & 31;

    // weights: dep_w[(g*8+ocl)*729 + k*27 + dydz*3 + dx]
    //   -> sdep[((ocl*27 + k)*9 + dydz)*4 + dx], dx==3 slot zero-padded
    for (int e = tid; e < CONV_DEP_FLOATS; e += 512) {
        int dx = e & 3;
        int rest = e >> 2;
        int dydz = rest % 9;
        int rest2 = rest / 9;
        int k = rest2 % 27;
        int ocl = rest2 / 27;
        float v = 0.0f;
        if (dx < 3) {
            v = dep_w[(size_t)(g * 8 + ocl) * 729 + k * 27 + dydz * 3 + dx];
        }
        sdep[e] = v;
    }

    const float* fin = g_fconv + ((size_t)(b * 864 + g * 27)) * LSP;
    conv_load_chunk(sw, fin, tid, y0, z0, 0, CONV_KCHUNK);
    __syncthreads();

    const int xq = tid & 7;
    const int yq = (tid >> 3) & 7;
    const int zz = (tid >> 6) & 1;
    const int ocp = tid >> 7;
    const int oc0 = ocp * 2;

    float acc0[2][4];
    float acc1[2][4];
#pragma unroll
    for (int oy = 0; oy < 2; oy++) {
#pragma unroll
        for (int c = 0; c < 4; c++) {
            acc0[oy][c] = 0.0f;
            acc1[oy][c] = 0.0f;
        }
    }

    const float* wd0 = sdep + oc0 * 972;
    const float* wd1 = wd0 + 972;

#pragma unroll
    for (int chunk = 0; chunk < 4; chunk++) {
        const int kbase = chunk * CONV_KCHUNK;
        const int nk = (chunk < 3) ? CONV_KCHUNK : (27 - 3 * CONV_KCHUNK);
#pragma unroll 1
        for (int kl = 0; kl < nk; kl++) {
            const int k = kbase + kl;
#pragma unroll
            for (int dz = 0; dz < 3; dz++) {
                const float* rowb = &sw[(((kl * 4) + zz + dz) * 18 + yq * 2) * 36 + xq * 4];
                float P[4][6];
#pragma unroll
                for (int ry = 0; ry < 4; ry++) {
                    float4 pa = *reinterpret_cast<const float4*>(rowb + ry * 36);
                    float2 pb = *reinterpret_cast<const float2*>(rowb + ry * 36 + 4);
                    P[ry][0] = pa.x;
                    P[ry][1] = pa.y;
                    P[ry][2] = pa.z;
                    P[ry][3] = pa.w;
                    P[ry][4] = pb.x;
                    P[ry][5] = pb.y;
                }
#pragma unroll
                for (int dy = 0; dy < 3; dy++) {
                    float4 w0v = *reinterpret_cast<const float4*>(wd0 + (k * 9 + dz * 3 + dy) * 4);
                    float4 w1v = *reinterpret_cast<const float4*>(wd1 + (k * 9 + dz * 3 + dy) * 4);
                    float w0[3];
                    float w1[3];
                    w0[0] = w0v.x;
                    w0[1] = w0v.y;
                    w0[2] = w0v.z;
                    w1[0] = w1v.x;
                    w1[1] = w1v.y;
                    w1[2] = w1v.z;
#pragma unroll
                    for (int oy = 0; oy < 2; oy++) {
#pragma unroll
                        for (int dx = 0; dx < 3; dx++) {
#pragma unroll
                            for (int c = 0; c < 4; c++) {
                                float pv = P[oy + dy][c + dx];
                                acc0[oy][c] = fmaf(pv, w0[dx], acc0[oy][c]);
                                acc1[oy][c] = fmaf(pv, w1[dx], acc1[oy][c]);
                            }
                        }
                    }
                }
            }
        }
        if (chunk < 3) {
            __syncthreads();
            const int nkn = (chunk < 2) ? CONV_KCHUNK : (27 - 3 * CONV_KCHUNK);
            conv_load_chunk(sw, fin, tid, y0, z0, kbase + CONV_KCHUNK, nkn);
            __syncthreads();
        }
    }

    const float beta = beta_p[0];
    const int ocg0 = g * 8 + oc0;
    const float b0 = dep_b[ocg0];
    const float b1 = dep_b[ocg0 + 1];
#pragma unroll
    for (int oy = 0; oy < 2; oy++) {
        const size_t spatbase = (size_t)b * LSP + (z0 + zz) * 1024
                                + (y0 + yq * 2 + oy) * 32 + xq * 4;
#pragma unroll
        for (int c = 0; c < 4; c++) {
            float2 v;
            v.x = beta * (acc0[oy][c] + b0);
            v.y = beta * (acc1[oy][c] + b1);
            *reinterpret_cast<float2*>(out + (spatbase + c) * 256 + ocg0) = v;
        }
    }
}

// ---------------------------------------------------------------------------
// Windowed attention -> bf16 split output (g_ah/g_al).
// ---------------------------------------------------------------------------
__global__ __launch_bounds__(256) void attn_kernel(const float* __restrict__ rpb)
{
    __shared__ __align__(16) float sq[64][36];
    __shared__ __align__(16) float skT[32][68];
    __shared__ __align__(16) float sv[64][36];
    __shared__ __align__(16) float sS[64][68];
    __shared__ float sbias[343];

    const int tid = threadIdx.x;
    const int win = blockIdx.x;
    const int head = blockIdx.y;
    const int b = win >> 8;
    const int rr = win & 255;
    const int dblk = rr >> 6;
    const int h2 = rr & 63;
    const int hblk = h2 >> 3;
    const int wblk = h2 & 7;

    for (int i = tid; i < 343; i += 256) {
        sbias[i] = rpb[i * 8 + head];
    }

    for (int e = tid; e < 64 * 32; e += 256) {
        int tok = e >> 5;
        int dd = e & 31;
        int z = tok >> 4;
        int y = (tok >> 2) & 3;
        int x = tok & 3;
        size_t spat = (((size_t)b * 16 + dblk * 4 + z) * 32 + hblk * 4 + y) * 32
                      + wblk * 4 + x;
        const float* src = g_qkv + spat * 768 + head * 32 + dd;
        sq[tok][dd] = src[0];
        skT[dd][tok] = src[256];
        sv[tok][dd] = src[512];
    }
    __syncthreads();

    const int i4 = tid >> 4;
    const int jq = tid & 15;
    const int i0 = i4 * 4;
    const int j0 = jq * 4;

    float dots[4][4];
#pragma unroll
    for (int r = 0; r < 4; r++) {
#pragma unroll
        for (int c = 0; c < 4; c++) {
            dots[r][c] = 0.0f;
        }
    }

#pragma unroll
    for (int d8 = 0; d8 < 4; d8++) {
        float qreg[4][8];
#pragma unroll
        for (int r = 0; r < 4; r++) {
            float4 q0 = *reinterpret_cast<const float4*>(&sq[i0 + r][d8 * 8]);
            float4 q1 = *reinterpret_cast<const float4*>(&sq[i0 + r][d8 * 8 + 4]);
            qreg[r][0] = q0.x; qreg[r][1] = q0.y; qreg[r][2] = q0.z; qreg[r][3] = q0.w;
            qreg[r][4] = q1.x; qreg[r][5] = q1.y; qreg[r][6] = q1.z; qreg[r][7] = q1.w;
        }
#pragma unroll
        for (int dd = 0; dd < 8; dd++) {
            float4 kv = *reinterpret_cast<const float4*>(&skT[d8 * 8 + dd][j0]);
#pragma unroll
            for (int r = 0; r < 4; r++) {
                dots[r][0] = fmaf(qreg[r][dd], kv.x, dots[r][0]);
                dots[r][1] = fmaf(qreg[r][dd], kv.y, dots[r][1]);
                dots[r][2] = fmaf(qreg[r][dd], kv.z, dots[r][2]);
                dots[r][3] = fmaf(qreg[r][dd], kv.w, dots[r][3]);
            }
        }
    }

    const float scale = 0.17677669529663687f;
#pragma unroll
    for (int r = 0; r < 4; r++) {
        int ti = i0 + r;
        int zi = ti >> 4;
        int yi = (ti >> 2) & 3;
        int xi = ti & 3;
        float sv4[4];
#pragma unroll
        for (int c = 0; c < 4; c++) {
            int tj = j0 + c;
            int zj = tj >> 4;
            int yj = (tj >> 2) & 3;
            int xj = tj & 3;
            int rel = (zi - zj + 3) * 49 + (yi - yj + 3) * 7 + (xi - xj + 3);
            sv4[c] = dots[r][c] * scale + sbias[rel];
        }
        float rmax = fmaxf(fmaxf(sv4[0], sv4[1]), fmaxf(sv4[2], sv4[3]));
        rmax = warp16_max(rmax);
        float rsum = 0.0f;
#pragma unroll
        for (int c = 0; c < 4; c++) {
            sv4[c] = __expf(sv4[c] - rmax);
            rsum += sv4[c];
        }
        rsum = warp16_sum(rsum);
        float inv = 1.0f / rsum;
        float4 pv;
        pv.x = sv4[0] * inv;
        pv.y = sv4[1] * inv;
        pv.z = sv4[2] * inv;
        pv.w = sv4[3] * inv;
        *reinterpret_cast<float4*>(&sS[i0 + r][j0]) = pv;
    }
    __syncthreads();

    const int p2 = tid >> 3;
    const int dg = tid & 7;
    const int r0 = p2 * 2;
    const int r1 = r0 + 1;
    float o0[4] = {0.0f, 0.0f, 0.0f, 0.0f};
    float o1[4] = {0.0f, 0.0f, 0.0f, 0.0f};
#pragma unroll 4
    for (int j = 0; j < 64; j++) {
        float4 v = *reinterpret_cast<const float4*>(&sv[j][dg * 4]);
        float pa = sS[r0][j];
        float pbv = sS[r1][j];
        o0[0] = fmaf(pa, v.x, o0[0]);
        o0[1] = fmaf(pa, v.y, o0[1]);
        o0[2] = fmaf(pa, v.z, o0[2]);
        o0[3] = fmaf(pa, v.w, o0[3]);
        o1[0] = fmaf(pbv, v.x, o1[0]);
        o1[1] = fmaf(pbv, v.y, o1[1]);
        o1[2] = fmaf(pbv, v.z, o1[2]);
        o1[3] = fmaf(pbv, v.w, o1[3]);
    }
    size_t off0 = ((size_t)win * 64 + r0) * 256 + head * 32 + dg * 4;
    size_t off1 = ((size_t)win * 64 + r1) * 256 + head * 32 + dg * 4;
#pragma unroll
    for (int pass = 0; pass < 2; pass++) {
        const float* ov = (pass == 0) ? o0 : o1;
        size_t off = (pass == 0) ? off0 : off1;
        __nv_bfloat16 hh[4];
        __nv_bfloat16 ll[4];
#pragma unroll
        for (int c = 0; c < 4; c++) {
            hh[c] = __float2bfloat16(ov[c]);
            ll[c] = __float2bfloat16(ov[c] - __bfloat162float(hh[c]));
        }
        __nv_bfloat162* hp = reinterpret_cast<__nv_bfloat162*>(g_ah + off);
        __nv_bfloat162* lp = reinterpret_cast<__nv_bfloat162*>(g_al + off);
        hp[0] = __halves2bfloat162(hh[0], hh[1]);
        hp[1] = __halves2bfloat162(hh[2], hh[3]);
        lp[0] = __halves2bfloat162(ll[0], ll[1]);
        lp[1] = __halves2bfloat162(ll[2], ll[3]);
    }
}

// ---------------------------------------------------------------------------
// Launch. Order keeps conv at app-launch index 3 (the ncu-captured slot).
// ---------------------------------------------------------------------------
extern "C" void kernel_launch(void* const* d_in, const int* in_sizes, int n_in,
                              void* d_out, int out_size)
{
    (void)in_sizes;
    (void)n_in;
    (void)out_size;
    const float* x_in   = (const float*)d_in[0];
    const float* qkv_w  = (const float*)d_in[1];
    const float* proj_w = (const float*)d_in[2];
    const float* proj_b = (const float*)d_in[3];
    const float* rpb    = (const float*)d_in[4];
    const float* fc_w   = (const float*)d_in[5];
    const float* fc_b   = (const float*)d_in[6];
    const float* dep_w  = (const float*)d_in[7];
    const float* dep_b  = (const float*)d_in[8];
    const float* alpha  = (const float*)d_in[9];
    const float* beta   = (const float*)d_in[10];
    float* out = (float*)d_out;

    float* p_qkv;
    __nv_bfloat16* p_xh;
    __nv_bfloat16* p_xl;
    __nv_bfloat16* p_ah;
    __nv_bfloat16* p_al;
    __nv_bfloat16* p_wqh;
    __nv_bfloat16* p_wql;
    __nv_bfloat16* p_pwh;
    __nv_bfloat16* p_pwl;
    cudaGetSymbolAddress((void**)&p_qkv, g_qkv);
    cudaGetSymbolAddress((void**)&p_xh, g_xh);
    cudaGetSymbolAddress((void**)&p_xl, g_xl);
    cudaGetSymbolAddress((void**)&p_ah, g_ah);
    cudaGetSymbolAddress((void**)&p_al, g_al);
    cudaGetSymbolAddress((void**)&p_wqh, g_wqh);
    cudaGetSymbolAddress((void**)&p_wql, g_wql);
    cudaGetSymbolAddress((void**)&p_pwh, g_pwh);
    cudaGetSymbolAddress((void**)&p_pwl, g_pwl);

    cudaFuncSetAttribute(gemm_bf16<0>, cudaFuncAttributeMaxDynamicSharedMemorySize,
                         GEMM_SMEM_BYTES);
    cudaFuncSetAttribute(gemm_bf16<1>, cudaFuncAttributeMaxDynamicSharedMemorySize,
                         GEMM_SMEM_BYTES);
    cudaFuncSetAttribute(conv_kernel, cudaFuncAttributeMaxDynamicSharedMemorySize,
                         CONV_SMEM_BYTES);

    // 0) merged bf16 splits
    split3_kernel<<<16640, 256>>>(x_in, qkv_w, proj_w);
    // 1) qkv = x_in @ qkv_w
    gemm_bf16<0><<<dim3(6, 512), 256, GEMM_SMEM_BYTES>>>(
        p_xh, p_xl, p_wqh, p_wql, p_qkv, 65536, 768, 256,
        (const float*)0, (const float*)0);
    // 2) f_conv
    fconv_kernel<<<dim3(512, 4), 1024>>>(fc_w, fc_b);
    // 3) grouped conv (2z x 16y x 32x, 4 k-chunks) -> out = beta*(conv+dep_b)
    conv_kernel<<<dim3(2, 8, 128), 512, CONV_SMEM_BYTES>>>(dep_w, dep_b, beta, out);
    // 4) attention -> g_ah/g_al (bf16 split)
    attn_kernel<<<dim3(1024, 8), 256>>>(rpb);
    // 5) proj + window-reverse + out += alpha*(...)
    gemm_bf16<1><<<dim3(2, 512), 256, GEMM_SMEM_BYTES>>>(
        p_ah, p_al, p_pwh, p_pwl, out, 65536, 256, 256, proj_b, alpha);
}

// round 11
// speedup vs baseline: 1.7376x; 1.0029x over previous
#include <cuda_runtime.h>
#include <cuda_bf16.h>
#include <stdint.h>
#include <math.h>

typedef unsigned int u32;

// ---------------------------------------------------------------------------
// x_in [4,16,32,32,256], qkv_w [256,768], proj_w [256,256], proj_b [256]
// rpb_table [343,8], fc_w [27,24], fc_b [27], dep_w [256,27,3,3,3],
// dep_b [256], alpha, beta; out [4,16,32,32,256] float32
// ---------------------------------------------------------------------------
#define LSP 16384

__device__ float g_qkv  [(size_t)65536 * 768];
__device__ float g_fconv[(size_t)4 * 864 * LSP];

__device__ __nv_bfloat16 g_xh[(size_t)65536 * 256];
__device__ __nv_bfloat16 g_xl[(size_t)65536 * 256];
__device__ __nv_bfloat16 g_ah[(size_t)65536 * 256];
__device__ __nv_bfloat16 g_al[(size_t)65536 * 256];
__device__ __nv_bfloat16 g_wqh[256 * 768];
__device__ __nv_bfloat16 g_wql[256 * 768];
__device__ __nv_bfloat16 g_pwh[256 * 256];
__device__ __nv_bfloat16 g_pwl[256 * 256];

__device__ __forceinline__ u32 smem_u32(const void* p) {
    return (u32)__cvta_generic_to_shared(p);
}

__device__ __forceinline__ void ldsm_x4(u32& r0, u32& r1, u32& r2, u32& r3, u32 a) {
    asm volatile("ldmatrix.sync.aligned.m8n8.x4.shared.b16 {%0,%1,%2,%3}, [%4];\n"
                 : "=r"(r0), "=r"(r1), "=r"(r2), "=r"(r3) : "r"(a));
}

__device__ __forceinline__ void ldsm_x4t(u32& r0, u32& r1, u32& r2, u32& r3, u32 a) {
    asm volatile("ldmatrix.sync.aligned.m8n8.x4.trans.shared.b16 {%0,%1,%2,%3}, [%4];\n"
                 : "=r"(r0), "=r"(r1), "=r"(r2), "=r"(r3) : "r"(a));
}

__device__ __forceinline__ void mma_bf16(float* c, const u32* a, const u32* b) {
    asm volatile(
        "mma.sync.aligned.m16n8k16.row.col.f32.bf16.bf16.f32 "
        "{%0,%1,%2,%3}, {%4,%5,%6,%7}, {%8,%9}, {%0,%1,%2,%3};\n"
        : "+f"(c[0]), "+f"(c[1]), "+f"(c[2]), "+f"(c[3])
        : "r"(a[0]), "r"(a[1]), "r"(a[2]), "r"(a[3]), "r"(b[0]), "r"(b[1]));
}

__device__ __forceinline__ float warp16_max(float v) {
    v = fmaxf(v, __shfl_xor_sync(0xffffffffu, v, 1));
    v = fmaxf(v, __shfl_xor_sync(0xffffffffu, v, 2));
    v = fmaxf(v, __shfl_xor_sync(0xffffffffu, v, 4));
    v = fmaxf(v, __shfl_xor_sync(0xffffffffu, v, 8));
    return v;
}

__device__ __forceinline__ float warp16_sum(float v) {
    v += __shfl_xor_sync(0xffffffffu, v, 1);
    v += __shfl_xor_sync(0xffffffffu, v, 2);
    v += __shfl_xor_sync(0xffffffffu, v, 4);
    v += __shfl_xor_sync(0xffffffffu, v, 8);
    return v;
}

// ---------------------------------------------------------------------------
// Merged elementwise fp32 -> (bf16 hi, bf16 lo) split for all 3 tensors.
// ---------------------------------------------------------------------------
#define SPLIT_N1 4194304
#define SPLIT_N2 49152
#define SPLIT_N3 16384

__global__ __launch_bounds__(256) void split3_kernel(
    const float* __restrict__ x, const float* __restrict__ wq,
    const float* __restrict__ pw)
{
    int i = blockIdx.x * blockDim.x + threadIdx.x;
    const float* s;
    __nv_bfloat16* h;
    __nv_bfloat16* l;
    int idx;
    if (i < SPLIT_N1) {
        s = x;
        h = g_xh;
        l = g_xl;
        idx = i;
    } else if (i < SPLIT_N1 + SPLIT_N2) {
        s = wq;
        h = g_wqh;
        l = g_wql;
        idx = i - SPLIT_N1;
    } else if (i < SPLIT_N1 + SPLIT_N2 + SPLIT_N3) {
        s = pw;
        h = g_pwh;
        l = g_pwl;
        idx = i - SPLIT_N1 - SPLIT_N2;
    } else {
        return;
    }
    float4 v = reinterpret_cast<const float4*>(s)[idx];
    __nv_bfloat16 h0 = __float2bfloat16(v.x);
    __nv_bfloat16 h1 = __float2bfloat16(v.y);
    __nv_bfloat16 h2 = __float2bfloat16(v.z);
    __nv_bfloat16 h3 = __float2bfloat16(v.w);
    __nv_bfloat16 l0 = __float2bfloat16(v.x - __bfloat162float(h0));
    __nv_bfloat16 l1 = __float2bfloat16(v.y - __bfloat162float(h1));
    __nv_bfloat16 l2 = __float2bfloat16(v.z - __bfloat162float(h2));
    __nv_bfloat16 l3 = __float2bfloat16(v.w - __bfloat162float(h3));
    __nv_bfloat162* hp = reinterpret_cast<__nv_bfloat162*>(h) + idx * 2;
    __nv_bfloat162* lp = reinterpret_cast<__nv_bfloat162*>(l) + idx * 2;
    hp[0] = __halves2bfloat162(h0, h1);
    hp[1] = __halves2bfloat162(h2, h3);
    lp[0] = __halves2bfloat162(l0, l1);
    lp[1] = __halves2bfloat162(l2, l3);
}

// ---------------------------------------------------------------------------
// Tensor-core GEMM on pre-split bf16, double-buffered smem (dynamic, 76KB).
// ---------------------------------------------------------------------------
#define GEMM_SMEM_BYTES ((2 * 5120 + 2 * 5120 + 2 * 4352 + 2 * 4352) * 2)

template<int MODE>
__global__ __launch_bounds__(256) void gemm_bf16(
    const __nv_bfloat16* __restrict__ Ah, const __nv_bfloat16* __restrict__ Al,
    const __nv_bfloat16* __restrict__ Bh, const __nv_bfloat16* __restrict__ Bl,
    float* __restrict__ C, int M, int N, int K,
    const float* __restrict__ bias, const float* __restrict__ alpha_p)
{
    extern __shared__ __nv_bfloat16 gsm[];
    __nv_bfloat16* pAh = gsm;
    __nv_bfloat16* pAl = gsm + 10240;
    __nv_bfloat16* pBh = gsm + 20480;
    __nv_bfloat16* pBl = gsm + 29184;

    const int tid = threadIdx.x;
    const int lane = tid & 31;
    const int wid = tid >> 5;
    const int wm = (wid & 1) * 64;
    const int wn = (wid >> 1) * 32;
    const int bm = blockIdx.y * 128;
    const int bn = blockIdx.x * 128;

    float acc[4][4][4];
#pragma unroll
    for (int i = 0; i < 4; i++) {
#pragma unroll
        for (int j = 0; j < 4; j++) {
#pragma unroll
            for (int r = 0; r < 4; r++) {
                acc[i][j][r] = 0.0f;
            }
        }
    }

    const int nk = K >> 5;
    uint4 rAh[2];
    uint4 rAl[2];
    uint4 rBh[2];
    uint4 rBl[2];

#pragma unroll
    for (int i = 0; i < 2; i++) {
        int u = tid + i * 256;
        int ar = u >> 2;
        int ac = (u & 3) * 8;
        size_t aidx = (size_t)(bm + ar) * K + ac;
        rAh[i] = *reinterpret_cast<const uint4*>(Ah + aidx);
        rAl[i] = *reinterpret_cast<const uint4*>(Al + aidx);
        int br = u >> 4;
        int bc = (u & 15) * 8;
        size_t bidx = (size_t)br * N + bn + bc;
        rBh[i] = *reinterpret_cast<const uint4*>(Bh + bidx);
        rBl[i] = *reinterpret_cast<const uint4*>(Bl + bidx);
    }
#pragma unroll
    for (int i = 0; i < 2; i++) {
        int u = tid + i * 256;
        int ar = u >> 2;
        int ac = (u & 3) * 8;
        *reinterpret_cast<uint4*>(pAh + ar * 40 + ac) = rAh[i];
        *reinterpret_cast<uint4*>(pAl + ar * 40 + ac) = rAl[i];
        int br = u >> 4;
        int bc = (u & 15) * 8;
        *reinterpret_cast<uint4*>(pBh + br * 136 + bc) = rBh[i];
        *reinterpret_cast<uint4*>(pBl + br * 136 + bc) = rBl[i];
    }
    __syncthreads();

    const int a_r = lane & 15;
    const int a_k = (lane >> 4) * 8;

    for (int kt = 0; kt < nk; kt++) {
        const int curA = (kt & 1) * 5120;
        const int curB = (kt & 1) * 4352;

        if (kt + 1 < nk) {
#pragma unroll
            for (int i = 0; i < 2; i++) {
                int u = tid + i * 256;
                int ar = u >> 2;
                int ac = (u & 3) * 8;
                size_t aidx = (size_t)(bm + ar) * K + (kt + 1) * 32 + ac;
                rAh[i] = *reinterpret_cast<const uint4*>(Ah + aidx);
                rAl[i] = *reinterpret_cast<const uint4*>(Al + aidx);
                int br = u >> 4;
                int bc = (u & 15) * 8;
                size_t bidx = (size_t)((kt + 1) * 32 + br) * N + bn + bc;
                rBh[i] = *reinterpret_cast<const uint4*>(Bh + bidx);
                rBl[i] = *reinterpret_cast<const uint4*>(Bl + bidx);
            }
        }

#pragma unroll
        for (int ks = 0; ks < 2; ks++) {
            u32 aH[4][4];
            u32 aL[4][4];
            u32 bH[4][2];
            u32 bL[4][2];
#pragma unroll
            for (int mi = 0; mi < 4; mi++) {
                u32 adr = smem_u32(pAh + curA + (wm + mi * 16 + a_r) * 40 + ks * 16 + a_k);
                ldsm_x4(aH[mi][0], aH[mi][1], aH[mi][2], aH[mi][3], adr);
                adr = smem_u32(pAl + curA + (wm + mi * 16 + a_r) * 40 + ks * 16 + a_k);
                ldsm_x4(aL[mi][0], aL[mi][1], aL[mi][2], aL[mi][3], adr);
            }
#pragma unroll
            for (int nj = 0; nj < 2; nj++) {
                u32 r0;
                u32 r1;
                u32 r2;
                u32 r3;
                u32 adr = smem_u32(pBh + curB + (ks * 16 + a_r) * 136 + wn + nj * 16 + a_k);
                ldsm_x4t(r0, r1, r2, r3, adr);
                bH[nj * 2][0] = r0;
                bH[nj * 2][1] = r1;
                bH[nj * 2 + 1][0] = r2;
                bH[nj * 2 + 1][1] = r3;
                adr = smem_u32(pBl + curB + (ks * 16 + a_r) * 136 + wn + nj * 16 + a_k);
                ldsm_x4t(r0, r1, r2, r3, adr);
                bL[nj * 2][0] = r0;
                bL[nj * 2][1] = r1;
                bL[nj * 2 + 1][0] = r2;
                bL[nj * 2 + 1][1] = r3;
            }
#pragma unroll
            for (int mi = 0; mi < 4; mi++) {
#pragma unroll
                for (int ni = 0; ni < 4; ni++) {
                    mma_bf16(acc[mi][ni], aH[mi], bH[ni]);
                    mma_bf16(acc[mi][ni], aH[mi], bL[ni]);
                    mma_bf16(acc[mi][ni], aL[mi], bH[ni]);
                }
            }
        }

        if (kt + 1 < nk) {
            const int nxtA = ((kt + 1) & 1) * 5120;
            const int nxtB = ((kt + 1) & 1) * 4352;
#pragma unroll
            for (int i = 0; i < 2; i++) {
                int u = tid + i * 256;
                int ar = u >> 2;
                int ac = (u & 3) * 8;
                *reinterpret_cast<uint4*>(pAh + nxtA + ar * 40 + ac) = rAh[i];
                *reinterpret_cast<uint4*>(pAl + nxtA + ar * 40 + ac) = rAl[i];
                int br = u >> 4;
                int bc = (u & 15) * 8;
                *reinterpret_cast<uint4*>(pBh + nxtB + br * 136 + bc) = rBh[i];
                *reinterpret_cast<uint4*>(pBl + nxtB + br * 136 + bc) = rBl[i];
            }
        }
        __syncthreads();
    }

    const int g = lane >> 2;
    const int tg = lane & 3;

    if (MODE == 0) {
#pragma unroll
        for (int mi = 0; mi < 4; mi++) {
            int row0 = bm + wm + mi * 16 + g;
#pragma unroll
            for (int ni = 0; ni < 4; ni++) {
                int col = bn + wn + ni * 8 + tg * 2;
                float2 v0;
                float2 v1;
                v0.x = acc[mi][ni][0];
                v0.y = acc[mi][ni][1];
                v1.x = acc[mi][ni][2];
                v1.y = acc[mi][ni][3];
                *reinterpret_cast<float2*>(&C[(size_t)row0 * N + col]) = v0;
                *reinterpret_cast<float2*>(&C[(size_t)(row0 + 8) * N + col]) = v1;
            }
        }
    } else {
        const float alpha = alpha_p[0];
#pragma unroll
        for (int mi = 0; mi < 4; mi++) {
#pragma unroll
            for (int half = 0; half < 2; half++) {
                int row = bm + wm + mi * 16 + g + half * 8;
                int win = row >> 6;
                int tok = row & 63;
                int b = win >> 8;
                int r2 = win & 255;
                int dblk = r2 >> 6;
                int h2 = r2 & 63;
                int hblk = h2 >> 3;
                int wblk = h2 & 7;
                int z4 = tok >> 4;
                int y4 = (tok >> 2) & 3;
                int x4 = tok & 3;
                size_t spat = (((size_t)b * 16 + dblk * 4 + z4) * 32 + hblk * 4 + y4) * 32
                              + wblk * 4 + x4;
#pragma unroll
                for (int ni = 0; ni < 4; ni++) {
                    int col = bn + wn + ni * 8 + tg * 2;
                    float2 pb = *reinterpret_cast<const float2*>(&bias[col]);
                    float* dst = &C[spat * 256 + col];
                    float2 e = *reinterpret_cast<float2*>(dst);
                    e.x += alpha * (acc[mi][ni][half * 2 + 0] + pb.x);
                    e.y += alpha * (acc[mi][ni][half * 2 + 1] + pb.y);
                    *reinterpret_cast<float2*>(dst) = e;
                }
            }
        }
    }
}

// ---------------------------------------------------------------------------
// fconv
// ---------------------------------------------------------------------------
__global__ __launch_bounds__(1024) void fconv_kernel(
    const float* __restrict__ fcw, const float* __restrict__ fcb)
{
    __shared__ float s_fcw[27 * 24];
    __shared__ float s_fcb[27];
    __shared__ float s_out[32 * 9 * 33];

    const int tid = threadIdx.x;
    const int b = blockIdx.y;
    const int l0 = blockIdx.x * 32;

    if (tid < 648) {
        s_fcw[tid] = fcw[tid];
    }
    if (tid < 27) {
        s_fcb[tid] = fcb[tid];
    }
    __syncthreads();

    const float* qb = g_qkv + (size_t)b * 12582912;
    float acc[27];
#pragma unroll
    for (int o = 0; o < 27; o++) {
        acc[o] = s_fcb[o];
    }

#pragma unroll 4
    for (int g = 0; g < 24; g++) {
        float v = qb[(size_t)g * 524288 + (size_t)l0 * 32 + tid];
#pragma unroll
        for (int o = 0; o < 27; o++) {
            acc[o] = fmaf(s_fcw[o * 24 + g], v, acc[o]);
        }
    }

    const int xx = tid & 31;
    const int ll = tid >> 5;
    float* fco = g_fconv + (size_t)b * 864 * LSP;
#pragma unroll
    for (int r = 0; r < 3; r++) {
#pragma unroll
        for (int oo = 0; oo < 9; oo++) {
            s_out[(xx * 9 + oo) * 33 + ll] = acc[r * 9 + oo];
        }
        __syncthreads();
#pragma unroll
        for (int it = 0; it < 9; it++) {
            int e = it * 1024 + tid;
            int l = e & 31;
            int rest = e >> 5;
            int o = rest % 9;
            int x2 = rest / 9;
            fco[(size_t)(x2 * 27 + r * 9 + o) * LSP + l0 + l] =
                s_out[(x2 * 9 + o) * 33 + l];
        }
        __syncthreads();
    }
}

// ---------------------------------------------------------------------------
// Grouped conv: 2z x 16y x 32x tile, 512 threads, per-thread 2oc x 2y x 4x.
// k streamed in 4 chunks (7,7,7,6); 103.7KB smem -> 2 blocks/SM.
// ---------------------------------------------------------------------------
#define CONV_KCHUNK 7
#define CONV_SW_FLOATS  (CONV_KCHUNK * 4 * 18 * 36)
#define CONV_DEP_FLOATS (8 * 27 * 9 * 4)
#define CONV_SMEM_BYTES ((CONV_SW_FLOATS + CONV_DEP_FLOATS) * 4)

__device__ __forceinline__ void conv_load_chunk(
    float* sw, const float* fin, int tid, int y0, int z0, int kbase, int nk)
{
    const int elems = nk * 4 * 18 * 34;
    for (int e = tid; e < elems; e += 512) {
        int x = e % 34;
        int t1 = e / 34;
        int yy = t1 % 18;
        int t2 = t1 / 18;
        int wz = t2 & 3;
        int kl = t2 >> 2;
        int gx = x - 1;
        int gy = y0 + yy - 1;
        int gz = z0 + wz - 1;
        float v = 0.0f;
        if (gx >= 0 && gx < 32 && gy >= 0 && gy < 32 && gz >= 0 && gz < 16) {
            v = fin[(size_t)(kbase + kl) * LSP + gz * 1024 + gy * 32 + gx];
        }
        sw[((kl * 4 + wz) * 18 + yy) * 36 + x] = v;
    }
}

__global__ __launch_bounds__(512, 2) void conv_kernel(
    const float* __restrict__ dep_w, const float* __restrict__ dep_b,
    const float* __restrict__ beta_p, float* __restrict__ out)
{
    extern __shared__ float sm[];
    float* sw = sm;
    float* sdep = sm + CONV_SW_FLOATS;

    const int tid = threadIdx.x;
    const int y0 = blockIdx.x * 16;
    const int z0 = blockIdx.y * 2;
    const int bg = blockIdx.z;
    const int b = bg >> 5;
    const int g = bg & 31;

    for (int e = tid; e < CONV_DEP_FLOATS; e += 512) {
        int dx = e & 3;
        int rest = e >> 2;
        int dydz = rest % 9;
        int rest2 = rest / 9;
        int k = rest2 % 27;
        int ocl = rest2 / 27;
        float v = 0.0f;
        if (dx < 3) {
            v = dep_w[(size_t)(g * 8 + ocl) * 729 + k * 27 + dydz * 3 + dx];
        }
        sdep[e] = v;
    }

    const float* fin = g_fconv + ((size_t)(b * 864 + g * 27)) * LSP;
    conv_load_chunk(sw, fin, tid, y0, z0, 0, CONV_KCHUNK);
    __syncthreads();

    const int xq = tid & 7;
    const int yq = (tid >> 3) & 7;
    const int zz = (tid >> 6) & 1;
    const int ocp = tid >> 7;
    const int oc0 = ocp * 2;

    float acc0[2][4];
    float acc1[2][4];
#pragma unroll
    for (int oy = 0; oy < 2; oy++) {
#pragma unroll
        for (int c = 0; c < 4; c++) {
            acc0[oy][c] = 0.0f;
            acc1[oy][c] = 0.0f;
        }
    }

    const float* wd0 = sdep + oc0 * 972;
    const float* wd1 = wd0 + 972;

#pragma unroll
    for (int chunk = 0; chunk < 4; chunk++) {
        const int kbase = chunk * CONV_KCHUNK;
        const int nk = (chunk < 3) ? CONV_KCHUNK : (27 - 3 * CONV_KCHUNK);
#pragma unroll 1
        for (int kl = 0; kl < nk; kl++) {
            const int k = kbase + kl;
#pragma unroll
            for (int dz = 0; dz < 3; dz++) {
                const float* rowb = &sw[(((kl * 4) + zz + dz) * 18 + yq * 2) * 36 + xq * 4];
                float P[4][6];
#pragma unroll
                for (int ry = 0; ry < 4; ry++) {
                    float4 pa = *reinterpret_cast<const float4*>(rowb + ry * 36);
                    float2 pb = *reinterpret_cast<const float2*>(rowb + ry * 36 + 4);
                    P[ry][0] = pa.x;
                    P[ry][1] = pa.y;
                    P[ry][2] = pa.z;
                    P[ry][3] = pa.w;
                    P[ry][4] = pb.x;
                    P[ry][5] = pb.y;
                }
#pragma unroll
                for (int dy = 0; dy < 3; dy++) {
                    float4 w0v = *reinterpret_cast<const float4*>(wd0 + (k * 9 + dz * 3 + dy) * 4);
                    float4 w1v = *reinterpret_cast<const float4*>(wd1 + (k * 9 + dz * 3 + dy) * 4);
                    float w0[3];
                    float w1[3];
                    w0[0] = w0v.x;
                    w0[1] = w0v.y;
                    w0[2] = w0v.z;
                    w1[0] = w1v.x;
                    w1[1] = w1v.y;
                    w1[2] = w1v.z;
#pragma unroll
                    for (int oy = 0; oy < 2; oy++) {
#pragma unroll
                        for (int dx = 0; dx < 3; dx++) {
#pragma unroll
                            for (int c = 0; c < 4; c++) {
                                float pv = P[oy + dy][c + dx];
                                acc0[oy][c] = fmaf(pv, w0[dx], acc0[oy][c]);
                                acc1[oy][c] = fmaf(pv, w1[dx], acc1[oy][c]);
                            }
                        }
                    }
                }
            }
        }
        if (chunk < 3) {
            __syncthreads();
            const int nkn = (chunk < 2) ? CONV_KCHUNK : (27 - 3 * CONV_KCHUNK);
            conv_load_chunk(sw, fin, tid, y0, z0, kbase + CONV_KCHUNK, nkn);
            __syncthreads();
        }
    }

    const float beta = beta_p[0];
    const int ocg0 = g * 8 + oc0;
    const float b0 = dep_b[ocg0];
    const float b1 = dep_b[ocg0 + 1];
#pragma unroll
    for (int oy = 0; oy < 2; oy++) {
        const size_t spatbase = (size_t)b * LSP + (z0 + zz) * 1024
                                + (y0 + yq * 2 + oy) * 32 + xq * 4;
#pragma unroll
        for (int c = 0; c < 4; c++) {
            float2 v;
            v.x = beta * (acc0[oy][c] + b0);
            v.y = beta * (acc1[oy][c] + b1);
            *reinterpret_cast<float2*>(out + (spatbase + c) * 256 + ocg0) = v;
        }
    }
}

// ---------------------------------------------------------------------------
// Windowed attention -> bf16 split output (g_ah/g_al).
// ---------------------------------------------------------------------------
__global__ __launch_bounds__(256) void attn_kernel(const float* __restrict__ rpb)
{
    __shared__ __align__(16) float sq[64][36];
    __shared__ __align__(16) float skT[32][68];
    __shared__ __align__(16) float sv[64][36];
    __shared__ __align__(16) float sS[64][68];
    __shared__ float sbias[343];

    const int tid = threadIdx.x;
    const int win = blockIdx.x;
    const int head = blockIdx.y;
    const int b = win >> 8;
    const int rr = win & 255;
    const int dblk = rr >> 6;
    const int h2 = rr & 63;
    const int hblk = h2 >> 3;
    const int wblk = h2 & 7;

    for (int i = tid; i < 343; i += 256) {
        sbias[i] = rpb[i * 8 + head];
    }

    for (int e = tid; e < 64 * 32; e += 256) {
        int tok = e >> 5;
        int dd = e & 31;
        int z = tok >> 4;
        int y = (tok >> 2) & 3;
        int x = tok & 3;
        size_t spat = (((size_t)b * 16 + dblk * 4 + z) * 32 + hblk * 4 + y) * 32
                      + wblk * 4 + x;
        const float* src = g_qkv + spat * 768 + head * 32 + dd;
        sq[tok][dd] = src[0];
        skT[dd][tok] = src[256];
        sv[tok][dd] = src[512];
    }
    __syncthreads();

    const int i4 = tid >> 4;
    const int jq = tid & 15;
    const int i0 = i4 * 4;
    const int j0 = jq * 4;

    float dots[4][4];
#pragma unroll
    for (int r = 0; r < 4; r++) {
#pragma unroll
        for (int c = 0; c < 4; c++) {
            dots[r][c] = 0.0f;
        }
    }

#pragma unroll
    for (int d8 = 0; d8 < 4; d8++) {
        float qreg[4][8];
#pragma unroll
        for (int r = 0; r < 4; r++) {
            float4 q0 = *reinterpret_cast<const float4*>(&sq[i0 + r][d8 * 8]);
            float4 q1 = *reinterpret_cast<const float4*>(&sq[i0 + r][d8 * 8 + 4]);
            qreg[r][0] = q0.x; qreg[r][1] = q0.y; qreg[r][2] = q0.z; qreg[r][3] = q0.w;
            qreg[r][4] = q1.x; qreg[r][5] = q1.y; qreg[r][6] = q1.z; qreg[r][7] = q1.w;
        }
#pragma unroll
        for (int dd = 0; dd < 8; dd++) {
            float4 kv = *reinterpret_cast<const float4*>(&skT[d8 * 8 + dd][j0]);
#pragma unroll
            for (int r = 0; r < 4; r++) {
                dots[r][0] = fmaf(qreg[r][dd], kv.x, dots[r][0]);
                dots[r][1] = fmaf(qreg[r][dd], kv.y, dots[r][1]);
                dots[r][2] = fmaf(qreg[r][dd], kv.z, dots[r][2]);
                dots[r][3] = fmaf(qreg[r][dd], kv.w, dots[r][3]);
            }
        }
    }

    const float scale = 0.17677669529663687f;
#pragma unroll
    for (int r = 0; r < 4; r++) {
        int ti = i0 + r;
        int zi = ti >> 4;
        int yi = (ti >> 2) & 3;
        int xi = ti & 3;
        float sv4[4];
#pragma unroll
        for (int c = 0; c < 4; c++) {
            int tj = j0 + c;
            int zj = tj >> 4;
            int yj = (tj >> 2) & 3;
            int xj = tj & 3;
            int rel = (zi - zj + 3) * 49 + (yi - yj + 3) * 7 + (xi - xj + 3);
            sv4[c] = dots[r][c] * scale + sbias[rel];
        }
        float rmax = fmaxf(fmaxf(sv4[0], sv4[1]), fmaxf(sv4[2], sv4[3]));
        rmax = warp16_max(rmax);
        float rsum = 0.0f;
#pragma unroll
        for (int c = 0; c < 4; c++) {
            sv4[c] = __expf(sv4[c] - rmax);
            rsum += sv4[c];
        }
        rsum = warp16_sum(rsum);
        float inv = 1.0f / rsum;
        float4 pv;
        pv.x = sv4[0] * inv;
        pv.y = sv4[1] * inv;
        pv.z = sv4[2] * inv;
        pv.w = sv4[3] * inv;
        *reinterpret_cast<float4*>(&sS[i0 + r][j0]) = pv;
    }
    __syncthreads();

    const int p2 = tid >> 3;
    const int dg = tid & 7;
    const int r0 = p2 * 2;
    const int r1 = r0 + 1;
    float o0[4] = {0.0f, 0.0f, 0.0f, 0.0f};
    float o1[4] = {0.0f, 0.0f, 0.0f, 0.0f};
#pragma unroll 4
    for (int j = 0; j < 64; j++) {
        float4 v = *reinterpret_cast<const float4*>(&sv[j][dg * 4]);
        float pa = sS[r0][j];
        float pbv = sS[r1][j];
        o0[0] = fmaf(pa, v.x, o0[0]);
        o0[1] = fmaf(pa, v.y, o0[1]);
        o0[2] = fmaf(pa, v.z, o0[2]);
        o0[3] = fmaf(pa, v.w, o0[3]);
        o1[0] = fmaf(pbv, v.x, o1[0]);
        o1[1] = fmaf(pbv, v.y, o1[1]);
        o1[2] = fmaf(pbv, v.z, o1[2]);
        o1[3] = fmaf(pbv, v.w, o1[3]);
    }
    size_t off0 = ((size_t)win * 64 + r0) * 256 + head * 32 + dg * 4;
    size_t off1 = ((size_t)win * 64 + r1) * 256 + head * 32 + dg * 4;
#pragma unroll
    for (int pass = 0; pass < 2; pass++) {
        const float* ov = (pass == 0) ? o0 : o1;
        size_t off = (pass == 0) ? off0 : off1;
        __nv_bfloat16 hh[4];
        __nv_bfloat16 ll[4];
#pragma unroll
        for (int c = 0; c < 4; c++) {
            hh[c] = __float2bfloat16(ov[c]);
            ll[c] = __float2bfloat16(ov[c] - __bfloat162float(hh[c]));
        }
        __nv_bfloat162* hp = reinterpret_cast<__nv_bfloat162*>(g_ah + off);
        __nv_bfloat162* lp = reinterpret_cast<__nv_bfloat162*>(g_al + off);
        hp[0] = __halves2bfloat162(hh[0], hh[1]);
        hp[1] = __halves2bfloat162(hh[2], hh[3]);
        lp[0] = __halves2bfloat162(ll[0], ll[1]);
        lp[1] = __halves2bfloat162(ll[2], ll[3]);
    }
}

// ---------------------------------------------------------------------------
// Launch. attn forked to a second stream, overlapping fconv+conv.
// DAG: split3 -> gemm0 -> { (fconv -> conv), attn } -> gemm1
// ---------------------------------------------------------------------------
extern "C" void kernel_launch(void* const* d_in, const int* in_sizes, int n_in,
                              void* d_out, int out_size)
{
    (void)in_sizes;
    (void)n_in;
    (void)out_size;
    const float* x_in   = (const float*)d_in[0];
    const float* qkv_w  = (const float*)d_in[1];
    const float* proj_w = (const float*)d_in[2];
    const float* proj_b = (const float*)d_in[3];
    const float* rpb    = (const float*)d_in[4];
    const float* fc_w   = (const float*)d_in[5];
    const float* fc_b   = (const float*)d_in[6];
    const float* dep_w  = (const float*)d_in[7];
    const float* dep_b  = (const float*)d_in[8];
    const float* alpha  = (const float*)d_in[9];
    const float* beta   = (const float*)d_in[10];
    float* out = (float*)d_out;

    float* p_qkv;
    __nv_bfloat16* p_xh;
    __nv_bfloat16* p_xl;
    __nv_bfloat16* p_ah;
    __nv_bfloat16* p_al;
    __nv_bfloat16* p_wqh;
    __nv_bfloat16* p_wql;
    __nv_bfloat16* p_pwh;
    __nv_bfloat16* p_pwl;
    cudaGetSymbolAddress((void**)&p_qkv, g_qkv);
    cudaGetSymbolAddress((void**)&p_xh, g_xh);
    cudaGetSymbolAddress((void**)&p_xl, g_xl);
    cudaGetSymbolAddress((void**)&p_ah, g_ah);
    cudaGetSymbolAddress((void**)&p_al, g_al);
    cudaGetSymbolAddress((void**)&p_wqh, g_wqh);
    cudaGetSymbolAddress((void**)&p_wql, g_wql);
    cudaGetSymbolAddress((void**)&p_pwh, g_pwh);
    cudaGetSymbolAddress((void**)&p_pwl, g_pwl);

    cudaFuncSetAttribute(gemm_bf16<0>, cudaFuncAttributeMaxDynamicSharedMemorySize,
                         GEMM_SMEM_BYTES);
    cudaFuncSetAttribute(gemm_bf16<1>, cudaFuncAttributeMaxDynamicSharedMemorySize,
                         GEMM_SMEM_BYTES);
    cudaFuncSetAttribute(conv_kernel, cudaFuncAttributeMaxDynamicSharedMemorySize,
                         CONV_SMEM_BYTES);

    // Side stream + fork/join events (created once; work per call is identical)
    static cudaStream_t s_attn = 0;
    static cudaEvent_t ev_fork = 0;
    static cudaEvent_t ev_join = 0;
    if (s_attn == 0) {
        cudaStreamCreateWithFlags(&s_attn, cudaStreamNonBlocking);
        cudaEventCreateWithFlags(&ev_fork, cudaEventDisableTiming);
        cudaEventCreateWithFlags(&ev_join, cudaEventDisableTiming);
    }

    // 0) merged bf16 splits
    split3_kernel<<<16640, 256>>>(x_in, qkv_w, proj_w);
    // 1) qkv = x_in @ qkv_w
    gemm_bf16<0><<<dim3(6, 512), 256, GEMM_SMEM_BYTES>>>(
        p_xh, p_xl, p_wqh, p_wql, p_qkv, 65536, 768, 256,
        (const float*)0, (const float*)0);

    // fork: attn on side stream, concurrent with fconv+conv
    cudaEventRecord(ev_fork, 0);
    cudaStreamWaitEvent(s_attn, ev_fork, 0);
    attn_kernel<<<dim3(1024, 8), 256, 0, s_attn>>>(rpb);
    cudaEventRecord(ev_join, s_attn);

    // 2) f_conv (main stream)
    fconv_kernel<<<dim3(512, 4), 1024>>>(fc_w, fc_b);
    // 3) grouped conv -> out = beta*(conv + dep_b)
    conv_kernel<<<dim3(2, 8, 128), 512, CONV_SMEM_BYTES>>>(dep_w, dep_b, beta, out);

    // join: gemm1 needs both conv (program order) and attn (event)
    cudaStreamWaitEvent(0, ev_join, 0);
    // 5) proj + window-reverse + out += alpha*(...)
    gemm_bf16<1><<<dim3(2, 512), 256, GEMM_SMEM_BYTES>>>(
        p_ah, p_al, p_pwh, p_pwl, out, 65536, 256, 256, proj_b, alpha);
}

// round 12
// speedup vs baseline: 1.7620x; 1.0141x over previous
#include <cuda_runtime.h>
#include <cuda_bf16.h>
#include <stdint.h>
#include <math.h>

typedef unsigned int u32;

// ---------------------------------------------------------------------------
// x_in [4,16,32,32,256], qkv_w [256,768], proj_w [256,256], proj_b [256]
// rpb_table [343,8], fc_w [27,24], fc_b [27], dep_w [256,27,3,3,3],
// dep_b [256], alpha, beta; out [4,16,32,32,256] float32
// ---------------------------------------------------------------------------
#define LSP 16384

__device__ float g_qkv  [(size_t)65536 * 768];
__device__ float g_fconv[(size_t)4 * 864 * LSP];

__device__ __nv_bfloat16 g_xh[(size_t)65536 * 256];
__device__ __nv_bfloat16 g_xl[(size_t)65536 * 256];
__device__ __nv_bfloat16 g_ah[(size_t)65536 * 256];
__device__ __nv_bfloat16 g_al[(size_t)65536 * 256];
__device__ __nv_bfloat16 g_wqh[256 * 768];
__device__ __nv_bfloat16 g_wql[256 * 768];
__device__ __nv_bfloat16 g_pwh[256 * 256];
__device__ __nv_bfloat16 g_pwl[256 * 256];

__device__ __forceinline__ u32 smem_u32(const void* p) {
    return (u32)__cvta_generic_to_shared(p);
}

__device__ __forceinline__ void ldsm_x4(u32& r0, u32& r1, u32& r2, u32& r3, u32 a) {
    asm volatile("ldmatrix.sync.aligned.m8n8.x4.shared.b16 {%0,%1,%2,%3}, [%4];\n"
                 : "=r"(r0), "=r"(r1), "=r"(r2), "=r"(r3) : "r"(a));
}

__device__ __forceinline__ void ldsm_x4t(u32& r0, u32& r1, u32& r2, u32& r3, u32 a) {
    asm volatile("ldmatrix.sync.aligned.m8n8.x4.trans.shared.b16 {%0,%1,%2,%3}, [%4];\n"
                 : "=r"(r0), "=r"(r1), "=r"(r2), "=r"(r3) : "r"(a));
}

__device__ __forceinline__ void mma_bf16(float* c, const u32* a, const u32* b) {
    asm volatile(
        "mma.sync.aligned.m16n8k16.row.col.f32.bf16.bf16.f32 "
        "{%0,%1,%2,%3}, {%4,%5,%6,%7}, {%8,%9}, {%0,%1,%2,%3};\n"
        : "+f"(c[0]), "+f"(c[1]), "+f"(c[2]), "+f"(c[3])
        : "r"(a[0]), "r"(a[1]), "r"(a[2]), "r"(a[3]), "r"(b[0]), "r"(b[1]));
}

__device__ __forceinline__ float warp16_max(float v) {
    v = fmaxf(v, __shfl_xor_sync(0xffffffffu, v, 1));
    v = fmaxf(v, __shfl_xor_sync(0xffffffffu, v, 2));
    v = fmaxf(v, __shfl_xor_sync(0xffffffffu, v, 4));
    v = fmaxf(v, __shfl_xor_sync(0xffffffffu, v, 8));
    return v;
}

__device__ __forceinline__ float warp16_sum(float v) {
    v += __shfl_xor_sync(0xffffffffu, v, 1);
    v += __shfl_xor_sync(0xffffffffu, v, 2);
    v += __shfl_xor_sync(0xffffffffu, v, 4);
    v += __shfl_xor_sync(0xffffffffu, v, 8);
    return v;
}

// ---------------------------------------------------------------------------
// Merged elementwise fp32 -> (bf16 hi, bf16 lo) split for all 3 tensors.
// ---------------------------------------------------------------------------
#define SPLIT_N1 4194304
#define SPLIT_N2 49152
#define SPLIT_N3 16384

__global__ __launch_bounds__(256) void split3_kernel(
    const float* __restrict__ x, const float* __restrict__ wq,
    const float* __restrict__ pw)
{
    int i = blockIdx.x * blockDim.x + threadIdx.x;
    const float* s;
    __nv_bfloat16* h;
    __nv_bfloat16* l;
    int idx;
    if (i < SPLIT_N1) {
        s = x;
        h = g_xh;
        l = g_xl;
        idx = i;
    } else if (i < SPLIT_N1 + SPLIT_N2) {
        s = wq;
        h = g_wqh;
        l = g_wql;
        idx = i - SPLIT_N1;
    } else if (i < SPLIT_N1 + SPLIT_N2 + SPLIT_N3) {
        s = pw;
        h = g_pwh;
        l = g_pwl;
        idx = i - SPLIT_N1 - SPLIT_N2;
    } else {
        return;
    }
    float4 v = reinterpret_cast<const float4*>(s)[idx];
    __nv_bfloat16 h0 = __float2bfloat16(v.x);
    __nv_bfloat16 h1 = __float2bfloat16(v.y);
    __nv_bfloat16 h2 = __float2bfloat16(v.z);
    __nv_bfloat16 h3 = __float2bfloat16(v.w);
    __nv_bfloat16 l0 = __float2bfloat16(v.x - __bfloat162float(h0));
    __nv_bfloat16 l1 = __float2bfloat16(v.y - __bfloat162float(h1));
    __nv_bfloat16 l2 = __float2bfloat16(v.z - __bfloat162float(h2));
    __nv_bfloat16 l3 = __float2bfloat16(v.w - __bfloat162float(h3));
    __nv_bfloat162* hp = reinterpret_cast<__nv_bfloat162*>(h) + idx * 2;
    __nv_bfloat162* lp = reinterpret_cast<__nv_bfloat162*>(l) + idx * 2;
    hp[0] = __halves2bfloat162(h0, h1);
    hp[1] = __halves2bfloat162(h2, h3);
    lp[0] = __halves2bfloat162(l0, l1);
    lp[1] = __halves2bfloat162(l2, l3);
}

// ---------------------------------------------------------------------------
// Tensor-core GEMM, 128(M) x 64(N) x 32(K) tile, 256 threads, 8 warps (4Mx2N),
// 32x32 per warp, 2 blocks/SM. Double-buffered smem (~58KB dynamic).
// C = Ah@Bh + Ah@Bl + Al@Bh.
// smem (bf16 units): Ah [2][128*40] @0, Al @10240, Bh [2][32*72] @20480,
// Bl @25088. Total 29696 el = 59392 B.
// ---------------------------------------------------------------------------
#define GEMM_SMEM_BYTES (29696 * 2)

template<int MODE>
__global__ __launch_bounds__(256, 2) void gemm_bf16(
    const __nv_bfloat16* __restrict__ Ah, const __nv_bfloat16* __restrict__ Al,
    const __nv_bfloat16* __restrict__ Bh, const __nv_bfloat16* __restrict__ Bl,
    float* __restrict__ C, int M, int N, int K,
    const float* __restrict__ bias, const float* __restrict__ alpha_p)
{
    extern __shared__ __nv_bfloat16 gsm[];
    __nv_bfloat16* pAh = gsm;
    __nv_bfloat16* pAl = gsm + 10240;
    __nv_bfloat16* pBh = gsm + 20480;
    __nv_bfloat16* pBl = gsm + 25088;

    const int tid = threadIdx.x;
    const int lane = tid & 31;
    const int wid = tid >> 5;
    const int wm = (wid & 3) * 32;
    const int wn = (wid >> 2) * 32;
    const int bm = blockIdx.y * 128;
    const int bn = blockIdx.x * 64;

    float acc[2][4][4];
#pragma unroll
    for (int i = 0; i < 2; i++) {
#pragma unroll
        for (int j = 0; j < 4; j++) {
#pragma unroll
            for (int r = 0; r < 4; r++) {
                acc[i][j][r] = 0.0f;
            }
        }
    }

    const int nk = K >> 5;
    uint4 rAh[2];
    uint4 rAl[2];
    uint4 rBh;
    uint4 rBl;

    const int arow0 = tid >> 2;
    const int acol0 = (tid & 3) * 8;
    const int arow1 = (tid + 256) >> 2;
    const int brow = tid >> 3;
    const int bcol = (tid & 7) * 8;

    // prologue: load tile 0
    rAh[0] = *reinterpret_cast<const uint4*>(Ah + (size_t)(bm + arow0) * K + acol0);
    rAl[0] = *reinterpret_cast<const uint4*>(Al + (size_t)(bm + arow0) * K + acol0);
    rAh[1] = *reinterpret_cast<const uint4*>(Ah + (size_t)(bm + arow1) * K + acol0);
    rAl[1] = *reinterpret_cast<const uint4*>(Al + (size_t)(bm + arow1) * K + acol0);
    rBh = *reinterpret_cast<const uint4*>(Bh + (size_t)brow * N + bn + bcol);
    rBl = *reinterpret_cast<const uint4*>(Bl + (size_t)brow * N + bn + bcol);

    *reinterpret_cast<uint4*>(pAh + arow0 * 40 + acol0) = rAh[0];
    *reinterpret_cast<uint4*>(pAl + arow0 * 40 + acol0) = rAl[0];
    *reinterpret_cast<uint4*>(pAh + arow1 * 40 + acol0) = rAh[1];
    *reinterpret_cast<uint4*>(pAl + arow1 * 40 + acol0) = rAl[1];
    *reinterpret_cast<uint4*>(pBh + brow * 72 + bcol) = rBh;
    *reinterpret_cast<uint4*>(pBl + brow * 72 + bcol) = rBl;
    __syncthreads();

    const int a_r = lane & 15;
    const int a_k = (lane >> 4) * 8;

    for (int kt = 0; kt < nk; kt++) {
        const int curA = (kt & 1) * 5120;
        const int curB = (kt & 1) * 2304;

        if (kt + 1 < nk) {
            size_t koff = (size_t)(kt + 1) * 32;
            rAh[0] = *reinterpret_cast<const uint4*>(Ah + (size_t)(bm + arow0) * K + koff + acol0);
            rAl[0] = *reinterpret_cast<const uint4*>(Al + (size_t)(bm + arow0) * K + koff + acol0);
            rAh[1] = *reinterpret_cast<const uint4*>(Ah + (size_t)(bm + arow1) * K + koff + acol0);
            rAl[1] = *reinterpret_cast<const uint4*>(Al + (size_t)(bm + arow1) * K + koff + acol0);
            rBh = *reinterpret_cast<const uint4*>(Bh + (koff + brow) * N + bn + bcol);
            rBl = *reinterpret_cast<const uint4*>(Bl + (koff + brow) * N + bn + bcol);
        }

#pragma unroll
        for (int ks = 0; ks < 2; ks++) {
            u32 aH[2][4];
            u32 aL[2][4];
            u32 bH[4][2];
            u32 bL[4][2];
#pragma unroll
            for (int mi = 0; mi < 2; mi++) {
                u32 adr = smem_u32(pAh + curA + (wm + mi * 16 + a_r) * 40 + ks * 16 + a_k);
                ldsm_x4(aH[mi][0], aH[mi][1], aH[mi][2], aH[mi][3], adr);
                adr = smem_u32(pAl + curA + (wm + mi * 16 + a_r) * 40 + ks * 16 + a_k);
                ldsm_x4(aL[mi][0], aL[mi][1], aL[mi][2], aL[mi][3], adr);
            }
#pragma unroll
            for (int nj = 0; nj < 2; nj++) {
                u32 r0;
                u32 r1;
                u32 r2;
                u32 r3;
                u32 adr = smem_u32(pBh + curB + (ks * 16 + a_r) * 72 + wn + nj * 16 + a_k);
                ldsm_x4t(r0, r1, r2, r3, adr);
                bH[nj * 2][0] = r0;
                bH[nj * 2][1] = r1;
                bH[nj * 2 + 1][0] = r2;
                bH[nj * 2 + 1][1] = r3;
                adr = smem_u32(pBl + curB + (ks * 16 + a_r) * 72 + wn + nj * 16 + a_k);
                ldsm_x4t(r0, r1, r2, r3, adr);
                bL[nj * 2][0] = r0;
                bL[nj * 2][1] = r1;
                bL[nj * 2 + 1][0] = r2;
                bL[nj * 2 + 1][1] = r3;
            }
#pragma unroll
            for (int mi = 0; mi < 2; mi++) {
#pragma unroll
                for (int ni = 0; ni < 4; ni++) {
                    mma_bf16(acc[mi][ni], aH[mi], bH[ni]);
                    mma_bf16(acc[mi][ni], aH[mi], bL[ni]);
                    mma_bf16(acc[mi][ni], aL[mi], bH[ni]);
                }
            }
        }

        if (kt + 1 < nk) {
            const int nxtA = ((kt + 1) & 1) * 5120;
            const int nxtB = ((kt + 1) & 1) * 2304;
            *reinterpret_cast<uint4*>(pAh + nxtA + arow0 * 40 + acol0) = rAh[0];
            *reinterpret_cast<uint4*>(pAl + nxtA + arow0 * 40 + acol0) = rAl[0];
            *reinterpret_cast<uint4*>(pAh + nxtA + arow1 * 40 + acol0) = rAh[1];
            *reinterpret_cast<uint4*>(pAl + nxtA + arow1 * 40 + acol0) = rAl[1];
            *reinterpret_cast<uint4*>(pBh + nxtB + brow * 72 + bcol) = rBh;
            *reinterpret_cast<uint4*>(pBl + nxtB + brow * 72 + bcol) = rBl;
        }
        __syncthreads();
    }

    const int g = lane >> 2;
    const int tg = lane & 3;

    if (MODE == 0) {
#pragma unroll
        for (int mi = 0; mi < 2; mi++) {
            int row0 = bm + wm + mi * 16 + g;
#pragma unroll
            for (int ni = 0; ni < 4; ni++) {
                int col = bn + wn + ni * 8 + tg * 2;
                float2 v0;
                float2 v1;
                v0.x = acc[mi][ni][0];
                v0.y = acc[mi][ni][1];
                v1.x = acc[mi][ni][2];
                v1.y = acc[mi][ni][3];
                *reinterpret_cast<float2*>(&C[(size_t)row0 * N + col]) = v0;
                *reinterpret_cast<float2*>(&C[(size_t)(row0 + 8) * N + col]) = v1;
            }
        }
    } else {
        const float alpha = alpha_p[0];
#pragma unroll
        for (int mi = 0; mi < 2; mi++) {
#pragma unroll
            for (int half = 0; half < 2; half++) {
                int row = bm + wm + mi * 16 + g + half * 8;
                int win = row >> 6;
                int tok = row & 63;
                int b = win >> 8;
                int r2 = win & 255;
                int dblk = r2 >> 6;
                int h2 = r2 & 63;
                int hblk = h2 >> 3;
                int wblk = h2 & 7;
                int z4 = tok >> 4;
                int y4 = (tok >> 2) & 3;
                int x4 = tok & 3;
                size_t spat = (((size_t)b * 16 + dblk * 4 + z4) * 32 + hblk * 4 + y4) * 32
                              + wblk * 4 + x4;
#pragma unroll
                for (int ni = 0; ni < 4; ni++) {
                    int col = bn + wn + ni * 8 + tg * 2;
                    float2 pb = *reinterpret_cast<const float2*>(&bias[col]);
                    float* dst = &C[spat * 256 + col];
                    float2 e = *reinterpret_cast<float2*>(dst);
                    e.x += alpha * (acc[mi][ni][half * 2 + 0] + pb.x);
                    e.y += alpha * (acc[mi][ni][half * 2 + 1] + pb.y);
                    *reinterpret_cast<float2*>(dst) = e;
                }
            }
        }
    }
}

// ---------------------------------------------------------------------------
// fconv
// ---------------------------------------------------------------------------
__global__ __launch_bounds__(1024) void fconv_kernel(
    const float* __restrict__ fcw, const float* __restrict__ fcb)
{
    __shared__ float s_fcw[27 * 24];
    __shared__ float s_fcb[27];
    __shared__ float s_out[32 * 9 * 33];

    const int tid = threadIdx.x;
    const int b = blockIdx.y;
    const int l0 = blockIdx.x * 32;

    if (tid < 648) {
        s_fcw[tid] = fcw[tid];
    }
    if (tid < 27) {
        s_fcb[tid] = fcb[tid];
    }
    __syncthreads();

    const float* qb = g_qkv + (size_t)b * 12582912;
    float acc[27];
#pragma unroll
    for (int o = 0; o < 27; o++) {
        acc[o] = s_fcb[o];
    }

#pragma unroll 4
    for (int g = 0; g < 24; g++) {
        float v = qb[(size_t)g * 524288 + (size_t)l0 * 32 + tid];
#pragma unroll
        for (int o = 0; o < 27; o++) {
            acc[o] = fmaf(s_fcw[o * 24 + g], v, acc[o]);
        }
    }

    const int xx = tid & 31;
    const int ll = tid >> 5;
    float* fco = g_fconv + (size_t)b * 864 * LSP;
#pragma unroll
    for (int r = 0; r < 3; r++) {
#pragma unroll
        for (int oo = 0; oo < 9; oo++) {
            s_out[(xx * 9 + oo) * 33 + ll] = acc[r * 9 + oo];
        }
        __syncthreads();
#pragma unroll
        for (int it = 0; it < 9; it++) {
            int e = it * 1024 + tid;
            int l = e & 31;
            int rest = e >> 5;
            int o = rest % 9;
            int x2 = rest / 9;
            fco[(size_t)(x2 * 27 + r * 9 + o) * LSP + l0 + l] =
                s_out[(x2 * 9 + o) * 33 + l];
        }
        __syncthreads();
    }
}

// ---------------------------------------------------------------------------
// Grouped conv: 2z x 16y x 32x tile, 512 threads, per-thread 2oc x 2y x 4x.
// k streamed in 4 chunks (7,7,7,6); 103.7KB smem -> 2 blocks/SM.
// ---------------------------------------------------------------------------
#define CONV_KCHUNK 7
#define CONV_SW_FLOATS  (CONV_KCHUNK * 4 * 18 * 36)
#define CONV_DEP_FLOATS (8 * 27 * 9 * 4)
#define CONV_SMEM_BYTES ((CONV_SW_FLOATS + CONV_DEP_FLOATS) * 4)

__device__ __forceinline__ void conv_load_chunk(
    float* sw, const float* fin, int tid, int y0, int z0, int kbase, int nk)
{
    const int elems = nk * 4 * 18 * 34;
    for (int e = tid; e < elems; e += 512) {
        int x = e % 34;
        int t1 = e / 34;
        int yy = t1 % 18;
        int t2 = t1 / 18;
        int wz = t2 & 3;
        int kl = t2 >> 2;
        int gx = x - 1;
        int gy = y0 + yy - 1;
        int gz = z0 + wz - 1;
        float v = 0.0f;
        if (gx >= 0 && gx < 32 && gy >= 0 && gy < 32 && gz >= 0 && gz < 16) {
            v = fin[(size_t)(kbase + kl) * LSP + gz * 1024 + gy * 32 + gx];
        }
        sw[((kl * 4 + wz) * 18 + yy) * 36 + x] = v;
    }
}

__global__ __launch_bounds__(512, 2) void conv_kernel(
    const float* __restrict__ dep_w, const float* __restrict__ dep_b,
    const float* __restrict__ beta_p, float* __restrict__ out)
{
    extern __shared__ float sm[];
    float* sw = sm;
    float* sdep = sm + CONV_SW_FLOATS;

    const int tid = threadIdx.x;
    const int y0 = blockIdx.x * 16;
    const int z0 = blockIdx.y * 2;
    const int bg = blockIdx.z;
    const int b = bg >> 5;
    const int g = bg & 31;

    for (int e = tid; e < CONV_DEP_FLOATS; e += 512) {
        int dx = e & 3;
        int rest = e >> 2;
        int dydz = rest % 9;
        int rest2 = rest / 9;
        int k = rest2 % 27;
        int ocl = rest2 / 27;
        float v = 0.0f;
        if (dx < 3) {
            v = dep_w[(size_t)(g * 8 + ocl) * 729 + k * 27 + dydz * 3 + dx];
        }
        sdep[e] = v;
    }

    const float* fin = g_fconv + ((size_t)(b * 864 + g * 27)) * LSP;
    conv_load_chunk(sw, fin, tid, y0, z0, 0, CONV_KCHUNK);
    __syncthreads();

    const int xq = tid & 7;
    const int yq = (tid >> 3) & 7;
    const int zz = (tid >> 6) & 1;
    const int ocp = tid >> 7;
    const int oc0 = ocp * 2;

    float acc0[2][4];
    float acc1[2][4];
#pragma unroll
    for (int oy = 0; oy < 2; oy++) {
#pragma unroll
        for (int c = 0; c < 4; c++) {
            acc0[oy][c] = 0.0f;
            acc1[oy][c] = 0.0f;
        }
    }

    const float* wd0 = sdep + oc0 * 972;
    const float* wd1 = wd0 + 972;

#pragma unroll
    for (int chunk = 0; chunk < 4; chunk++) {
        const int kbase = chunk * CONV_KCHUNK;
        const int nk = (chunk < 3) ? CONV_KCHUNK : (27 - 3 * CONV_KCHUNK);
#pragma unroll 1
        for (int kl = 0; kl < nk; kl++) {
            const int k = kbase + kl;
#pragma unroll
            for (int dz = 0; dz < 3; dz++) {
                const float* rowb = &sw[(((kl * 4) + zz + dz) * 18 + yq * 2) * 36 + xq * 4];
                float P[4][6];
#pragma unroll
                for (int ry = 0; ry < 4; ry++) {
                    float4 pa = *reinterpret_cast<const float4*>(rowb + ry * 36);
                    float2 pb = *reinterpret_cast<const float2*>(rowb + ry * 36 + 4);
                    P[ry][0] = pa.x;
                    P[ry][1] = pa.y;
                    P[ry][2] = pa.z;
                    P[ry][3] = pa.w;
                    P[ry][4] = pb.x;
                    P[ry][5] = pb.y;
                }
#pragma unroll
                for (int dy = 0; dy < 3; dy++) {
                    float4 w0v = *reinterpret_cast<const float4*>(wd0 + (k * 9 + dz * 3 + dy) * 4);
                    float4 w1v = *reinterpret_cast<const float4*>(wd1 + (k * 9 + dz * 3 + dy) * 4);
                    float w0[3];
                    float w1[3];
                    w0[0] = w0v.x;
                    w0[1] = w0v.y;
                    w0[2] = w0v.z;
                    w1[0] = w1v.x;
                    w1[1] = w1v.y;
                    w1[2] = w1v.z;
#pragma unroll
                    for (int oy = 0; oy < 2; oy++) {
#pragma unroll
                        for (int dx = 0; dx < 3; dx++) {
#pragma unroll
                            for (int c = 0; c < 4; c++) {
                                float pv = P[oy + dy][c + dx];
                                acc0[oy][c] = fmaf(pv, w0[dx], acc0[oy][c]);
                                acc1[oy][c] = fmaf(pv, w1[dx], acc1[oy][c]);
                            }
                        }
                    }
                }
            }
        }
        if (chunk < 3) {
            __syncthreads();
            const int nkn = (chunk < 2) ? CONV_KCHUNK : (27 - 3 * CONV_KCHUNK);
            conv_load_chunk(sw, fin, tid, y0, z0, kbase + CONV_KCHUNK, nkn);
            __syncthreads();
        }
    }

    const float beta = beta_p[0];
    const int ocg0 = g * 8 + oc0;
    const float b0 = dep_b[ocg0];
    const float b1 = dep_b[ocg0 + 1];
#pragma unroll
    for (int oy = 0; oy < 2; oy++) {
        const size_t spatbase = (size_t)b * LSP + (z0 + zz) * 1024
                                + (y0 + yq * 2 + oy) * 32 + xq * 4;
#pragma unroll
        for (int c = 0; c < 4; c++) {
            float2 v;
            v.x = beta * (acc0[oy][c] + b0);
            v.y = beta * (acc1[oy][c] + b1);
            *reinterpret_cast<float2*>(out + (spatbase + c) * 256 + ocg0) = v;
        }
    }
}

// ---------------------------------------------------------------------------
// Windowed attention -> bf16 split output (g_ah/g_al).
// ---------------------------------------------------------------------------
__global__ __launch_bounds__(256) void attn_kernel(const float* __restrict__ rpb)
{
    __shared__ __align__(16) float sq[64][36];
    __shared__ __align__(16) float skT[32][68];
    __shared__ __align__(16) float sv[64][36];
    __shared__ __align__(16) float sS[64][68];
    __shared__ float sbias[343];

    const int tid = threadIdx.x;
    const int win = blockIdx.x;
    const int head = blockIdx.y;
    const int b = win >> 8;
    const int rr = win & 255;
    const int dblk = rr >> 6;
    const int h2 = rr & 63;
    const int hblk = h2 >> 3;
    const int wblk = h2 & 7;

    for (int i = tid; i < 343; i += 256) {
        sbias[i] = rpb[i * 8 + head];
    }

    for (int e = tid; e < 64 * 32; e += 256) {
        int tok = e >> 5;
        int dd = e & 31;
        int z = tok >> 4;
        int y = (tok >> 2) & 3;
        int x = tok & 3;
        size_t spat = (((size_t)b * 16 + dblk * 4 + z) * 32 + hblk * 4 + y) * 32
                      + wblk * 4 + x;
        const float* src = g_qkv + spat * 768 + head * 32 + dd;
        sq[tok][dd] = src[0];
        skT[dd][tok] = src[256];
        sv[tok][dd] = src[512];
    }
    __syncthreads();

    const int i4 = tid >> 4;
    const int jq = tid & 15;
    const int i0 = i4 * 4;
    const int j0 = jq * 4;

    float dots[4][4];
#pragma unroll
    for (int r = 0; r < 4; r++) {
#pragma unroll
        for (int c = 0; c < 4; c++) {
            dots[r][c] = 0.0f;
        }
    }

#pragma unroll
    for (int d8 = 0; d8 < 4; d8++) {
        float qreg[4][8];
#pragma unroll
        for (int r = 0; r < 4; r++) {
            float4 q0 = *reinterpret_cast<const float4*>(&sq[i0 + r][d8 * 8]);
            float4 q1 = *reinterpret_cast<const float4*>(&sq[i0 + r][d8 * 8 + 4]);
            qreg[r][0] = q0.x; qreg[r][1] = q0.y; qreg[r][2] = q0.z; qreg[r][3] = q0.w;
            qreg[r][4] = q1.x; qreg[r][5] = q1.y; qreg[r][6] = q1.z; qreg[r][7] = q1.w;
        }
#pragma unroll
        for (int dd = 0; dd < 8; dd++) {
            float4 kv = *reinterpret_cast<const float4*>(&skT[d8 * 8 + dd][j0]);
#pragma unroll
            for (int r = 0; r < 4; r++) {
                dots[r][0] = fmaf(qreg[r][dd], kv.x, dots[r][0]);
                dots[r][1] = fmaf(qreg[r][dd], kv.y, dots[r][1]);
                dots[r][2] = fmaf(qreg[r][dd], kv.z, dots[r][2]);
                dots[r][3] = fmaf(qreg[r][dd], kv.w, dots[r][3]);
            }
        }
    }

    const float scale = 0.17677669529663687f;
#pragma unroll
    for (int r = 0; r < 4; r++) {
        int ti = i0 + r;
        int zi = ti >> 4;
        int yi = (ti >> 2) & 3;
        int xi = ti & 3;
        float sv4[4];
#pragma unroll
        for (int c = 0; c < 4; c++) {
            int tj = j0 + c;
            int zj = tj >> 4;
            int yj = (tj >> 2) & 3;
            int xj = tj & 3;
            int rel = (zi - zj + 3) * 49 + (yi - yj + 3) * 7 + (xi - xj + 3);
            sv4[c] = dots[r][c] * scale + sbias[rel];
        }
        float rmax = fmaxf(fmaxf(sv4[0], sv4[1]), fmaxf(sv4[2], sv4[3]));
        rmax = warp16_max(rmax);
        float rsum = 0.0f;
#pragma unroll
        for (int c = 0; c < 4; c++) {
            sv4[c] = __expf(sv4[c] - rmax);
            rsum += sv4[c];
        }
        rsum = warp16_sum(rsum);
        float inv = 1.0f / rsum;
        float4 pv;
        pv.x = sv4[0] * inv;
        pv.y = sv4[1] * inv;
        pv.z = sv4[2] * inv;
        pv.w = sv4[3] * inv;
        *reinterpret_cast<float4*>(&sS[i0 + r][j0]) = pv;
    }
    __syncthreads();

    const int p2 = tid >> 3;
    const int dg = tid & 7;
    const int r0 = p2 * 2;
    const int r1 = r0 + 1;
    float o0[4] = {0.0f, 0.0f, 0.0f, 0.0f};
    float o1[4] = {0.0f, 0.0f, 0.0f, 0.0f};
#pragma unroll 4
    for (int j = 0; j < 64; j++) {
        float4 v = *reinterpret_cast<const float4*>(&sv[j][dg * 4]);
        float pa = sS[r0][j];
        float pbv = sS[r1][j];
        o0[0] = fmaf(pa, v.x, o0[0]);
        o0[1] = fmaf(pa, v.y, o0[1]);
        o0[2] = fmaf(pa, v.z, o0[2]);
        o0[3] = fmaf(pa, v.w, o0[3]);
        o1[0] = fmaf(pbv, v.x, o1[0]);
        o1[1] = fmaf(pbv, v.y, o1[1]);
        o1[2] = fmaf(pbv, v.z, o1[2]);
        o1[3] = fmaf(pbv, v.w, o1[3]);
    }
    size_t off0 = ((size_t)win * 64 + r0) * 256 + head * 32 + dg * 4;
    size_t off1 = ((size_t)win * 64 + r1) * 256 + head * 32 + dg * 4;
#pragma unroll
    for (int pass = 0; pass < 2; pass++) {
        const float* ov = (pass == 0) ? o0 : o1;
        size_t off = (pass == 0) ? off0 : off1;
        __nv_bfloat16 hh[4];
        __nv_bfloat16 ll[4];
#pragma unroll
        for (int c = 0; c < 4; c++) {
            hh[c] = __float2bfloat16(ov[c]);
            ll[c] = __float2bfloat16(ov[c] - __bfloat162float(hh[c]));
        }
        __nv_bfloat162* hp = reinterpret_cast<__nv_bfloat162*>(g_ah + off);
        __nv_bfloat162* lp = reinterpret_cast<__nv_bfloat162*>(g_al + off);
        hp[0] = __halves2bfloat162(hh[0], hh[1]);
        hp[1] = __halves2bfloat162(hh[2], hh[3]);
        lp[0] = __halves2bfloat162(ll[0], ll[1]);
        lp[1] = __halves2bfloat162(ll[2], ll[3]);
    }
}

// ---------------------------------------------------------------------------
// Launch. DAG: split3 -> gemm0 -> { (fconv -> conv), attn } -> gemm1
// ---------------------------------------------------------------------------
extern "C" void kernel_launch(void* const* d_in, const int* in_sizes, int n_in,
                              void* d_out, int out_size)
{
    (void)in_sizes;
    (void)n_in;
    (void)out_size;
    const float* x_in   = (const float*)d_in[0];
    const float* qkv_w  = (const float*)d_in[1];
    const float* proj_w = (const float*)d_in[2];
    const float* proj_b = (const float*)d_in[3];
    const float* rpb    = (const float*)d_in[4];
    const float* fc_w   = (const float*)d_in[5];
    const float* fc_b   = (const float*)d_in[6];
    const float* dep_w  = (const float*)d_in[7];
    const float* dep_b  = (const float*)d_in[8];
    const float* alpha  = (const float*)d_in[9];
    const float* beta   = (const float*)d_in[10];
    float* out = (float*)d_out;

    float* p_qkv;
    __nv_bfloat16* p_xh;
    __nv_bfloat16* p_xl;
    __nv_bfloat16* p_ah;
    __nv_bfloat16* p_al;
    __nv_bfloat16* p_wqh;
    __nv_bfloat16* p_wql;
    __nv_bfloat16* p_pwh;
    __nv_bfloat16* p_pwl;
    cudaGetSymbolAddress((void**)&p_qkv, g_qkv);
    cudaGetSymbolAddress((void**)&p_xh, g_xh);
    cudaGetSymbolAddress((void**)&p_xl, g_xl);
    cudaGetSymbolAddress((void**)&p_ah, g_ah);
    cudaGetSymbolAddress((void**)&p_al, g_al);
    cudaGetSymbolAddress((void**)&p_wqh, g_wqh);
    cudaGetSymbolAddress((void**)&p_wql, g_wql);
    cudaGetSymbolAddress((void**)&p_pwh, g_pwh);
    cudaGetSymbolAddress((void**)&p_pwl, g_pwl);

    cudaFuncSetAttribute(gemm_bf16<0>, cudaFuncAttributeMaxDynamicSharedMemorySize,
                         GEMM_SMEM_BYTES);
    cudaFuncSetAttribute(gemm_bf16<1>, cudaFuncAttributeMaxDynamicSharedMemorySize,
                         GEMM_SMEM_BYTES);
    cudaFuncSetAttribute(conv_kernel, cudaFuncAttributeMaxDynamicSharedMemorySize,
                         CONV_SMEM_BYTES);

    static cudaStream_t s_attn = 0;
    static cudaEvent_t ev_fork = 0;
    static cudaEvent_t ev_join = 0;
    if (s_attn == 0) {
        cudaStreamCreateWithFlags(&s_attn, cudaStreamNonBlocking);
        cudaEventCreateWithFlags(&ev_fork, cudaEventDisableTiming);
        cudaEventCreateWithFlags(&ev_join, cudaEventDisableTiming);
    }

    // 0) merged bf16 splits
    split3_kernel<<<16640, 256>>>(x_in, qkv_w, proj_w);
    // 1) qkv = x_in @ qkv_w   (128x64 tiles)
    gemm_bf16<0><<<dim3(12, 512), 256, GEMM_SMEM_BYTES>>>(
        p_xh, p_xl, p_wqh, p_wql, p_qkv, 65536, 768, 256,
        (const float*)0, (const float*)0);

    // fork: attn on side stream
    cudaEventRecord(ev_fork, 0);
    cudaStreamWaitEvent(s_attn, ev_fork, 0);
    attn_kernel<<<dim3(1024, 8), 256, 0, s_attn>>>(rpb);
    cudaEventRecord(ev_join, s_attn);

    // 2) f_conv (main stream)
    fconv_kernel<<<dim3(512, 4), 1024>>>(fc_w, fc_b);
    // 3) grouped conv -> out = beta*(conv + dep_b)
    conv_kernel<<<dim3(2, 8, 128), 512, CONV_SMEM_BYTES>>>(dep_w, dep_b, beta, out);

    // join, then 5) proj + window-reverse + out += alpha*(...)  (128x64 tiles)
    cudaStreamWaitEvent(0, ev_join, 0);
    gemm_bf16<1><<<dim3(4, 512), 256, GEMM_SMEM_BYTES>>>(
        p_ah, p_al, p_pwh, p_pwl, out, 65536, 256, 256, proj_b, alpha);
}

// round 13
// speedup vs baseline: 1.9562x; 1.1102x over previous
#include <cuda_runtime.h>
#include <cuda_bf16.h>
#include <stdint.h>
#include <math.h>

typedef unsigned int u32;

// ---------------------------------------------------------------------------
// x_in [4,16,32,32,256], qkv_w [256,768], proj_w [256,256], proj_b [256]
// rpb_table [343,8], fc_w [27,24], fc_b [27], dep_w [256,27,3,3,3],
// dep_b [256], alpha, beta; out [4,16,32,32,256] float32
// ---------------------------------------------------------------------------
#define LSP 16384

__device__ float g_qkv[(size_t)65536 * 768];
__device__ float g_qt [(size_t)4 * 32 * 24 * LSP];   // transposed qkv for conv
__device__ float g_w2 [256 * 25 * 27];               // folded conv weights

__device__ __nv_bfloat16 g_xh[(size_t)65536 * 256];
__device__ __nv_bfloat16 g_xl[(size_t)65536 * 256];
__device__ __nv_bfloat16 g_ah[(size_t)65536 * 256];
__device__ __nv_bfloat16 g_al[(size_t)65536 * 256];
__device__ __nv_bfloat16 g_wqh[256 * 768];
__device__ __nv_bfloat16 g_wql[256 * 768];
__device__ __nv_bfloat16 g_pwh[256 * 256];
__device__ __nv_bfloat16 g_pwl[256 * 256];

__device__ __forceinline__ u32 smem_u32(const void* p) {
    return (u32)__cvta_generic_to_shared(p);
}

__device__ __forceinline__ void ldsm_x4(u32& r0, u32& r1, u32& r2, u32& r3, u32 a) {
    asm volatile("ldmatrix.sync.aligned.m8n8.x4.shared.b16 {%0,%1,%2,%3}, [%4];\n"
                 : "=r"(r0), "=r"(r1), "=r"(r2), "=r"(r3) : "r"(a));
}

__device__ __forceinline__ void ldsm_x4t(u32& r0, u32& r1, u32& r2, u32& r3, u32 a) {
    asm volatile("ldmatrix.sync.aligned.m8n8.x4.trans.shared.b16 {%0,%1,%2,%3}, [%4];\n"
                 : "=r"(r0), "=r"(r1), "=r"(r2), "=r"(r3) : "r"(a));
}

__device__ __forceinline__ void mma_bf16(float* c, const u32* a, const u32* b) {
    asm volatile(
        "mma.sync.aligned.m16n8k16.row.col.f32.bf16.bf16.f32 "
        "{%0,%1,%2,%3}, {%4,%5,%6,%7}, {%8,%9}, {%0,%1,%2,%3};\n"
        : "+f"(c[0]), "+f"(c[1]), "+f"(c[2]), "+f"(c[3])
        : "r"(a[0]), "r"(a[1]), "r"(a[2]), "r"(a[3]), "r"(b[0]), "r"(b[1]));
}

__device__ __forceinline__ float warp16_max(float v) {
    v = fmaxf(v, __shfl_xor_sync(0xffffffffu, v, 1));
    v = fmaxf(v, __shfl_xor_sync(0xffffffffu, v, 2));
    v = fmaxf(v, __shfl_xor_sync(0xffffffffu, v, 4));
    v = fmaxf(v, __shfl_xor_sync(0xffffffffu, v, 8));
    return v;
}

__device__ __forceinline__ float warp16_sum(float v) {
    v += __shfl_xor_sync(0xffffffffu, v, 1);
    v += __shfl_xor_sync(0xffffffffu, v, 2);
    v += __shfl_xor_sync(0xffffffffu, v, 4);
    v += __shfl_xor_sync(0xffffffffu, v, 8);
    return v;
}

// ---------------------------------------------------------------------------
// Merged elementwise fp32 -> (bf16 hi, bf16 lo) split for all 3 tensors.
// ---------------------------------------------------------------------------
#define SPLIT_N1 4194304
#define SPLIT_N2 49152
#define SPLIT_N3 16384

__global__ __launch_bounds__(256) void split3_kernel(
    const float* __restrict__ x, const float* __restrict__ wq,
    const float* __restrict__ pw)
{
    int i = blockIdx.x * blockDim.x + threadIdx.x;
    const float* s;
    __nv_bfloat16* h;
    __nv_bfloat16* l;
    int idx;
    if (i < SPLIT_N1) {
        s = x;
        h = g_xh;
        l = g_xl;
        idx = i;
    } else if (i < SPLIT_N1 + SPLIT_N2) {
        s = wq;
        h = g_wqh;
        l = g_wql;
        idx = i - SPLIT_N1;
    } else if (i < SPLIT_N1 + SPLIT_N2 + SPLIT_N3) {
        s = pw;
        h = g_pwh;
        l = g_pwl;
        idx = i - SPLIT_N1 - SPLIT_N2;
    } else {
        return;
    }
    float4 v = reinterpret_cast<const float4*>(s)[idx];
    __nv_bfloat16 h0 = __float2bfloat16(v.x);
    __nv_bfloat16 h1 = __float2bfloat16(v.y);
    __nv_bfloat16 h2 = __float2bfloat16(v.z);
    __nv_bfloat16 h3 = __float2bfloat16(v.w);
    __nv_bfloat16 l0 = __float2bfloat16(v.x - __bfloat162float(h0));
    __nv_bfloat16 l1 = __float2bfloat16(v.y - __bfloat162float(h1));
    __nv_bfloat16 l2 = __float2bfloat16(v.z - __bfloat162float(h2));
    __nv_bfloat16 l3 = __float2bfloat16(v.w - __bfloat162float(h3));
    __nv_bfloat162* hp = reinterpret_cast<__nv_bfloat162*>(h) + idx * 2;
    __nv_bfloat162* lp = reinterpret_cast<__nv_bfloat162*>(l) + idx * 2;
    hp[0] = __halves2bfloat162(h0, h1);
    hp[1] = __halves2bfloat162(h2, h3);
    lp[0] = __halves2bfloat162(l0, l1);
    lp[1] = __halves2bfloat162(l2, l3);
}

// ---------------------------------------------------------------------------
// Tensor-core GEMM, 128(M) x 64(N) x 32(K) tile, 256 threads, 2 blocks/SM.
// ---------------------------------------------------------------------------
#define GEMM_SMEM_BYTES (29696 * 2)

template<int MODE>
__global__ __launch_bounds__(256, 2) void gemm_bf16(
    const __nv_bfloat16* __restrict__ Ah, const __nv_bfloat16* __restrict__ Al,
    const __nv_bfloat16* __restrict__ Bh, const __nv_bfloat16* __restrict__ Bl,
    float* __restrict__ C, int M, int N, int K,
    const float* __restrict__ bias, const float* __restrict__ alpha_p)
{
    extern __shared__ __nv_bfloat16 gsm[];
    __nv_bfloat16* pAh = gsm;
    __nv_bfloat16* pAl = gsm + 10240;
    __nv_bfloat16* pBh = gsm + 20480;
    __nv_bfloat16* pBl = gsm + 25088;

    const int tid = threadIdx.x;
    const int lane = tid & 31;
    const int wid = tid >> 5;
    const int wm = (wid & 3) * 32;
    const int wn = (wid >> 2) * 32;
    const int bm = blockIdx.y * 128;
    const int bn = blockIdx.x * 64;

    float acc[2][4][4];
#pragma unroll
    for (int i = 0; i < 2; i++) {
#pragma unroll
        for (int j = 0; j < 4; j++) {
#pragma unroll
            for (int r = 0; r < 4; r++) {
                acc[i][j][r] = 0.0f;
            }
        }
    }

    const int nk = K >> 5;
    uint4 rAh[2];
    uint4 rAl[2];
    uint4 rBh;
    uint4 rBl;

    const int arow0 = tid >> 2;
    const int acol0 = (tid & 3) * 8;
    const int arow1 = (tid + 256) >> 2;
    const int brow = tid >> 3;
    const int bcol = (tid & 7) * 8;

    rAh[0] = *reinterpret_cast<const uint4*>(Ah + (size_t)(bm + arow0) * K + acol0);
    rAl[0] = *reinterpret_cast<const uint4*>(Al + (size_t)(bm + arow0) * K + acol0);
    rAh[1] = *reinterpret_cast<const uint4*>(Ah + (size_t)(bm + arow1) * K + acol0);
    rAl[1] = *reinterpret_cast<const uint4*>(Al + (size_t)(bm + arow1) * K + acol0);
    rBh = *reinterpret_cast<const uint4*>(Bh + (size_t)brow * N + bn + bcol);
    rBl = *reinterpret_cast<const uint4*>(Bl + (size_t)brow * N + bn + bcol);

    *reinterpret_cast<uint4*>(pAh + arow0 * 40 + acol0) = rAh[0];
    *reinterpret_cast<uint4*>(pAl + arow0 * 40 + acol0) = rAl[0];
    *reinterpret_cast<uint4*>(pAh + arow1 * 40 + acol0) = rAh[1];
    *reinterpret_cast<uint4*>(pAl + arow1 * 40 + acol0) = rAl[1];
    *reinterpret_cast<uint4*>(pBh + brow * 72 + bcol) = rBh;
    *reinterpret_cast<uint4*>(pBl + brow * 72 + bcol) = rBl;
    __syncthreads();

    const int a_r = lane & 15;
    const int a_k = (lane >> 4) * 8;

    for (int kt = 0; kt < nk; kt++) {
        const int curA = (kt & 1) * 5120;
        const int curB = (kt & 1) * 2304;

        if (kt + 1 < nk) {
            size_t koff = (size_t)(kt + 1) * 32;
            rAh[0] = *reinterpret_cast<const uint4*>(Ah + (size_t)(bm + arow0) * K + koff + acol0);
            rAl[0] = *reinterpret_cast<const uint4*>(Al + (size_t)(bm + arow0) * K + koff + acol0);
            rAh[1] = *reinterpret_cast<const uint4*>(Ah + (size_t)(bm + arow1) * K + koff + acol0);
            rAl[1] = *reinterpret_cast<const uint4*>(Al + (size_t)(bm + arow1) * K + koff + acol0);
            rBh = *reinterpret_cast<const uint4*>(Bh + (koff + brow) * N + bn + bcol);
            rBl = *reinterpret_cast<const uint4*>(Bl + (koff + brow) * N + bn + bcol);
        }

#pragma unroll
        for (int ks = 0; ks < 2; ks++) {
            u32 aH[2][4];
            u32 aL[2][4];
            u32 bH[4][2];
            u32 bL[4][2];
#pragma unroll
            for (int mi = 0; mi < 2; mi++) {
                u32 adr = smem_u32(pAh + curA + (wm + mi * 16 + a_r) * 40 + ks * 16 + a_k);
                ldsm_x4(aH[mi][0], aH[mi][1], aH[mi][2], aH[mi][3], adr);
                adr = smem_u32(pAl + curA + (wm + mi * 16 + a_r) * 40 + ks * 16 + a_k);
                ldsm_x4(aL[mi][0], aL[mi][1], aL[mi][2], aL[mi][3], adr);
            }
#pragma unroll
            for (int nj = 0; nj < 2; nj++) {
                u32 r0;
                u32 r1;
                u32 r2;
                u32 r3;
                u32 adr = smem_u32(pBh + curB + (ks * 16 + a_r) * 72 + wn + nj * 16 + a_k);
                ldsm_x4t(r0, r1, r2, r3, adr);
                bH[nj * 2][0] = r0;
                bH[nj * 2][1] = r1;
                bH[nj * 2 + 1][0] = r2;
                bH[nj * 2 + 1][1] = r3;
                adr = smem_u32(pBl + curB + (ks * 16 + a_r) * 72 + wn + nj * 16 + a_k);
                ldsm_x4t(r0, r1, r2, r3, adr);
                bL[nj * 2][0] = r0;
                bL[nj * 2][1] = r1;
                bL[nj * 2 + 1][0] = r2;
                bL[nj * 2 + 1][1] = r3;
            }
#pragma unroll
            for (int mi = 0; mi < 2; mi++) {
#pragma unroll
                for (int ni = 0; ni < 4; ni++) {
                    mma_bf16(acc[mi][ni], aH[mi], bH[ni]);
                    mma_bf16(acc[mi][ni], aH[mi], bL[ni]);
                    mma_bf16(acc[mi][ni], aL[mi], bH[ni]);
                }
            }
        }

        if (kt + 1 < nk) {
            const int nxtA = ((kt + 1) & 1) * 5120;
            const int nxtB = ((kt + 1) & 1) * 2304;
            *reinterpret_cast<uint4*>(pAh + nxtA + arow0 * 40 + acol0) = rAh[0];
            *reinterpret_cast<uint4*>(pAl + nxtA + arow0 * 40 + acol0) = rAl[0];
            *reinterpret_cast<uint4*>(pAh + nxtA + arow1 * 40 + acol0) = rAh[1];
            *reinterpret_cast<uint4*>(pAl + nxtA + arow1 * 40 + acol0) = rAl[1];
            *reinterpret_cast<uint4*>(pBh + nxtB + brow * 72 + bcol) = rBh;
            *reinterpret_cast<uint4*>(pBl + nxtB + brow * 72 + bcol) = rBl;
        }
        __syncthreads();
    }

    const int g = lane >> 2;
    const int tg = lane & 3;

    if (MODE == 0) {
#pragma unroll
        for (int mi = 0; mi < 2; mi++) {
            int row0 = bm + wm + mi * 16 + g;
#pragma unroll
            for (int ni = 0; ni < 4; ni++) {
                int col = bn + wn + ni * 8 + tg * 2;
                float2 v0;
                float2 v1;
                v0.x = acc[mi][ni][0];
                v0.y = acc[mi][ni][1];
                v1.x = acc[mi][ni][2];
                v1.y = acc[mi][ni][3];
                *reinterpret_cast<float2*>(&C[(size_t)row0 * N + col]) = v0;
                *reinterpret_cast<float2*>(&C[(size_t)(row0 + 8) * N + col]) = v1;
            }
        }
    } else {
        const float alpha = alpha_p[0];
#pragma unroll
        for (int mi = 0; mi < 2; mi++) {
#pragma unroll
            for (int half = 0; half < 2; half++) {
                int row = bm + wm + mi * 16 + g + half * 8;
                int win = row >> 6;
                int tok = row & 63;
                int b = win >> 8;
                int r2 = win & 255;
                int dblk = r2 >> 6;
                int h2 = r2 & 63;
                int hblk = h2 >> 3;
                int wblk = h2 & 7;
                int z4 = tok >> 4;
                int y4 = (tok >> 2) & 3;
                int x4 = tok & 3;
                size_t spat = (((size_t)b * 16 + dblk * 4 + z4) * 32 + hblk * 4 + y4) * 32
                              + wblk * 4 + x4;
#pragma unroll
                for (int ni = 0; ni < 4; ni++) {
                    int col = bn + wn + ni * 8 + tg * 2;
                    float2 pb = *reinterpret_cast<const float2*>(&bias[col]);
                    float* dst = &C[spat * 256 + col];
                    float2 e = *reinterpret_cast<float2*>(dst);
                    e.x += alpha * (acc[mi][ni][half * 2 + 0] + pb.x);
                    e.y += alpha * (acc[mi][ni][half * 2 + 1] + pb.y);
                    *reinterpret_cast<float2*>(dst) = e;
                }
            }
        }
    }
}

// ---------------------------------------------------------------------------
// Weight fold: W2[ocg][ch<24][tap] = sum_o dep_w[ocg][o][tap]*fc_w[o][ch];
//              W2[ocg][24][tap]   = sum_o dep_w[ocg][o][tap]*fc_b[o].
// g_w2 layout [ocg][25][27].
// ---------------------------------------------------------------------------
__global__ __launch_bounds__(256) void wfold_kernel(
    const float* __restrict__ dep_w, const float* __restrict__ fcw,
    const float* __restrict__ fcb)
{
    __shared__ float s_fcw[648];
    __shared__ float s_fcb[27];
    const int tap = blockIdx.x;
    const int ocg = threadIdx.x;
    for (int e = threadIdx.x; e < 648; e += 256) {
        s_fcw[e] = fcw[e];
    }
    if (threadIdx.x < 27) {
        s_fcb[threadIdx.x] = fcb[threadIdx.x];
    }
    __syncthreads();

    float dw[27];
#pragma unroll
    for (int o = 0; o < 27; o++) {
        dw[o] = dep_w[(size_t)ocg * 729 + o * 27 + tap];
    }
#pragma unroll 1
    for (int ch = 0; ch < 24; ch++) {
        float s = 0.0f;
#pragma unroll
        for (int o = 0; o < 27; o++) {
            s = fmaf(dw[o], s_fcw[o * 24 + ch], s);
        }
        g_w2[ocg * 675 + ch * 27 + tap] = s;
    }
    float sb = 0.0f;
#pragma unroll
    for (int o = 0; o < 27; o++) {
        sb = fmaf(dw[o], s_fcb[o], sb);
    }
    g_w2[ocg * 675 + 24 * 27 + tap] = sb;
}

// ---------------------------------------------------------------------------
// Transpose: g_qt[b][g][gg][l] = qkv_flat[b][gg*524288 + l*32 + g].
// Block = (ltile 128, gg, b); 256 threads; smem 32x132 transpose tile.
// ---------------------------------------------------------------------------
__global__ __launch_bounds__(256) void transpose_kernel()
{
    __shared__ float sm[32 * 132];
    const int lt = blockIdx.x;
    const int gg = blockIdx.y;
    const int b = blockIdx.z;
    const int tid = threadIdx.x;
    const float* src = g_qkv + (size_t)b * 12582912 + (size_t)gg * 524288
                       + (size_t)lt * 128 * 32;
#pragma unroll
    for (int it = 0; it < 4; it++) {
        int idx4 = tid + it * 256;
        float4 v = reinterpret_cast<const float4*>(src)[idx4];
        int flat = idx4 * 4;
        int l = flat >> 5;
        int x = flat & 31;
        sm[(x + 0) * 132 + l] = v.x;
        sm[(x + 1) * 132 + l] = v.y;
        sm[(x + 2) * 132 + l] = v.z;
        sm[(x + 3) * 132 + l] = v.w;
    }
    __syncthreads();
    const int l4 = (tid & 31) * 4;
#pragma unroll
    for (int go = 0; go < 4; go++) {
        int gch = go * 8 + (tid >> 5);
        float4 v = *reinterpret_cast<const float4*>(&sm[gch * 132 + l4]);
        float* dst = g_qt + (((size_t)(b * 32 + gch) * 24 + gg) * LSP)
                     + lt * 128 + l4;
        *reinterpret_cast<float4*>(dst) = v;
    }
}

// ---------------------------------------------------------------------------
// Fused grouped conv: 25 channels (24 qkv-derived + ones channel for fc_b),
// folded weights g_w2. 2z x 16y x 32x tile, 512 threads, 2oc x 2y x 4x /thr.
// k streamed in 4 chunks (7,7,7,4); ~101KB smem -> 2 blocks/SM.
// ---------------------------------------------------------------------------
#define CONV_NCH 25
#define CONV_KCHUNK 7
#define CONV_SW_FLOATS  (CONV_KCHUNK * 4 * 18 * 36)
#define CONV_DEP_FLOATS (8 * CONV_NCH * 9 * 4)
#define CONV_SMEM_BYTES ((CONV_SW_FLOATS + CONV_DEP_FLOATS) * 4)

__device__ __forceinline__ void conv_load_chunk(
    float* sw, const float* fin, int tid, int y0, int z0, int kbase, int nk)
{
    const int elems = nk * 4 * 18 * 34;
    for (int e = tid; e < elems; e += 512) {
        int x = e % 34;
        int t1 = e / 34;
        int yy = t1 % 18;
        int t2 = t1 / 18;
        int wz = t2 & 3;
        int kl = t2 >> 2;
        int ch = kbase + kl;
        int gx = x - 1;
        int gy = y0 + yy - 1;
        int gz = z0 + wz - 1;
        float v = 0.0f;
        if (gx >= 0 && gx < 32 && gy >= 0 && gy < 32 && gz >= 0 && gz < 16) {
            if (ch < 24) {
                v = fin[(size_t)ch * LSP + gz * 1024 + gy * 32 + gx];
            } else {
                v = 1.0f;
            }
        }
        sw[((kl * 4 + wz) * 18 + yy) * 36 + x] = v;
    }
}

__global__ __launch_bounds__(512, 2) void conv_kernel(
    const float* __restrict__ dep_b, const float* __restrict__ beta_p,
    float* __restrict__ out)
{
    extern __shared__ float sm[];
    float* sw = sm;
    float* sdep = sm + CONV_SW_FLOATS;

    const int tid = threadIdx.x;
    const int y0 = blockIdx.x * 16;
    const int z0 = blockIdx.y * 2;
    const int bg = blockIdx.z;
    const int b = bg >> 5;
    const int g = bg & 31;

    // folded weights: g_w2[(g*8+ocl)*675 + ch*27 + dydz*3+dx]
    //   -> sdep[((ocl*25 + ch)*9 + dydz)*4 + dx], dx==3 zero-padded
    for (int e = tid; e < CONV_DEP_FLOATS; e += 512) {
        int dx = e & 3;
        int rest = e >> 2;
        int dydz = rest % 9;
        int rest2 = rest / 9;
        int ch = rest2 % CONV_NCH;
        int ocl = rest2 / CONV_NCH;
        float v = 0.0f;
        if (dx < 3) {
            v = g_w2[(g * 8 + ocl) * 675 + ch * 27 + dydz * 3 + dx];
        }
        sdep[e] = v;
    }

    const float* fin = g_qt + (size_t)(b * 32 + g) * 24 * LSP;
    conv_load_chunk(sw, fin, tid, y0, z0, 0, CONV_KCHUNK);
    __syncthreads();

    const int xq = tid & 7;
    const int yq = (tid >> 3) & 7;
    const int zz = (tid >> 6) & 1;
    const int ocp = tid >> 7;
    const int oc0 = ocp * 2;

    float acc0[2][4];
    float acc1[2][4];
#pragma unroll
    for (int oy = 0; oy < 2; oy++) {
#pragma unroll
        for (int c = 0; c < 4; c++) {
            acc0[oy][c] = 0.0f;
            acc1[oy][c] = 0.0f;
        }
    }

    const float* wd0 = sdep + oc0 * (CONV_NCH * 36);
    const float* wd1 = wd0 + CONV_NCH * 36;

#pragma unroll
    for (int chunk = 0; chunk < 4; chunk++) {
        const int kbase = chunk * CONV_KCHUNK;
        const int nk = (chunk < 3) ? CONV_KCHUNK : (CONV_NCH - 3 * CONV_KCHUNK);
#pragma unroll 1
        for (int kl = 0; kl < nk; kl++) {
            const int k = kbase + kl;
#pragma unroll
            for (int dz = 0; dz < 3; dz++) {
                const float* rowb = &sw[(((kl * 4) + zz + dz) * 18 + yq * 2) * 36 + xq * 4];
                float P[4][6];
#pragma unroll
                for (int ry = 0; ry < 4; ry++) {
                    float4 pa = *reinterpret_cast<const float4*>(rowb + ry * 36);
                    float2 pb = *reinterpret_cast<const float2*>(rowb + ry * 36 + 4);
                    P[ry][0] = pa.x;
                    P[ry][1] = pa.y;
                    P[ry][2] = pa.z;
                    P[ry][3] = pa.w;
                    P[ry][4] = pb.x;
                    P[ry][5] = pb.y;
                }
#pragma unroll
                for (int dy = 0; dy < 3; dy++) {
                    float4 w0v = *reinterpret_cast<const float4*>(wd0 + (k * 9 + dz * 3 + dy) * 4);
                    float4 w1v = *reinterpret_cast<const float4*>(wd1 + (k * 9 + dz * 3 + dy) * 4);
                    float w0[3];
                    float w1[3];
                    w0[0] = w0v.x;
                    w0[1] = w0v.y;
                    w0[2] = w0v.z;
                    w1[0] = w1v.x;
                    w1[1] = w1v.y;
                    w1[2] = w1v.z;
#pragma unroll
                    for (int oy = 0; oy < 2; oy++) {
#pragma unroll
                        for (int dx = 0; dx < 3; dx++) {
#pragma unroll
                            for (int c = 0; c < 4; c++) {
                                float pv = P[oy + dy][c + dx];
                                acc0[oy][c] = fmaf(pv, w0[dx], acc0[oy][c]);
                                acc1[oy][c] = fmaf(pv, w1[dx], acc1[oy][c]);
                            }
                        }
                    }
                }
            }
        }
        if (chunk < 3) {
            __syncthreads();
            const int nkn = (chunk < 2) ? CONV_KCHUNK : (CONV_NCH - 3 * CONV_KCHUNK);
            conv_load_chunk(sw, fin, tid, y0, z0, kbase + CONV_KCHUNK, nkn);
            __syncthreads();
        }
    }

    const float beta = beta_p[0];
    const int ocg0 = g * 8 + oc0;
    const float b0 = dep_b[ocg0];
    const float b1 = dep_b[ocg0 + 1];
#pragma unroll
    for (int oy = 0; oy < 2; oy++) {
        const size_t spatbase = (size_t)b * LSP + (z0 + zz) * 1024
                                + (y0 + yq * 2 + oy) * 32 + xq * 4;
#pragma unroll
        for (int c = 0; c < 4; c++) {
            float2 v;
            v.x = beta * (acc0[oy][c] + b0);
            v.y = beta * (acc1[oy][c] + b1);
            *reinterpret_cast<float2*>(out + (spatbase + c) * 256 + ocg0) = v;
        }
    }
}

// ---------------------------------------------------------------------------
// Windowed attention -> bf16 split output (g_ah/g_al).
// ---------------------------------------------------------------------------
__global__ __launch_bounds__(256) void attn_kernel(const float* __restrict__ rpb)
{
    __shared__ __align__(16) float sq[64][36];
    __shared__ __align__(16) float skT[32][68];
    __shared__ __align__(16) float sv[64][36];
    __shared__ __align__(16) float sS[64][68];
    __shared__ float sbias[343];

    const int tid = threadIdx.x;
    const int win = blockIdx.x;
    const int head = blockIdx.y;
    const int b = win >> 8;
    const int rr = win & 255;
    const int dblk = rr >> 6;
    const int h2 = rr & 63;
    const int hblk = h2 >> 3;
    const int wblk = h2 & 7;

    for (int i = tid; i < 343; i += 256) {
        sbias[i] = rpb[i * 8 + head];
    }

    for (int e = tid; e < 64 * 32; e += 256) {
        int tok = e >> 5;
        int dd = e & 31;
        int z = tok >> 4;
        int y = (tok >> 2) & 3;
        int x = tok & 3;
        size_t spat = (((size_t)b * 16 + dblk * 4 + z) * 32 + hblk * 4 + y) * 32
                      + wblk * 4 + x;
        const float* src = g_qkv + spat * 768 + head * 32 + dd;
        sq[tok][dd] = src[0];
        skT[dd][tok] = src[256];
        sv[tok][dd] = src[512];
    }
    __syncthreads();

    const int i4 = tid >> 4;
    const int jq = tid & 15;
    const int i0 = i4 * 4;
    const int j0 = jq * 4;

    float dots[4][4];
#pragma unroll
    for (int r = 0; r < 4; r++) {
#pragma unroll
        for (int c = 0; c < 4; c++) {
            dots[r][c] = 0.0f;
        }
    }

#pragma unroll
    for (int d8 = 0; d8 < 4; d8++) {
        float qreg[4][8];
#pragma unroll
        for (int r = 0; r < 4; r++) {
            float4 q0 = *reinterpret_cast<const float4*>(&sq[i0 + r][d8 * 8]);
            float4 q1 = *reinterpret_cast<const float4*>(&sq[i0 + r][d8 * 8 + 4]);
            qreg[r][0] = q0.x; qreg[r][1] = q0.y; qreg[r][2] = q0.z; qreg[r][3] = q0.w;
            qreg[r][4] = q1.x; qreg[r][5] = q1.y; qreg[r][6] = q1.z; qreg[r][7] = q1.w;
        }
#pragma unroll
        for (int dd = 0; dd < 8; dd++) {
            float4 kv = *reinterpret_cast<const float4*>(&skT[d8 * 8 + dd][j0]);
#pragma unroll
            for (int r = 0; r < 4; r++) {
                dots[r][0] = fmaf(qreg[r][dd], kv.x, dots[r][0]);
                dots[r][1] = fmaf(qreg[r][dd], kv.y, dots[r][1]);
                dots[r][2] = fmaf(qreg[r][dd], kv.z, dots[r][2]);
                dots[r][3] = fmaf(qreg[r][dd], kv.w, dots[r][3]);
            }
        }
    }

    const float scale = 0.17677669529663687f;
#pragma unroll
    for (int r = 0; r < 4; r++) {
        int ti = i0 + r;
        int zi = ti >> 4;
        int yi = (ti >> 2) & 3;
        int xi = ti & 3;
        float sv4[4];
#pragma unroll
        for (int c = 0; c < 4; c++) {
            int tj = j0 + c;
            int zj = tj >> 4;
            int yj = (tj >> 2) & 3;
            int xj = tj & 3;
            int rel = (zi - zj + 3) * 49 + (yi - yj + 3) * 7 + (xi - xj + 3);
            sv4[c] = dots[r][c] * scale + sbias[rel];
        }
        float rmax = fmaxf(fmaxf(sv4[0], sv4[1]), fmaxf(sv4[2], sv4[3]));
        rmax = warp16_max(rmax);
        float rsum = 0.0f;
#pragma unroll
        for (int c = 0; c < 4; c++) {
            sv4[c] = __expf(sv4[c] - rmax);
            rsum += sv4[c];
        }
        rsum = warp16_sum(rsum);
        float inv = 1.0f / rsum;
        float4 pv;
        pv.x = sv4[0] * inv;
        pv.y = sv4[1] * inv;
        pv.z = sv4[2] * inv;
        pv.w = sv4[3] * inv;
        *reinterpret_cast<float4*>(&sS[i0 + r][j0]) = pv;
    }
    __syncthreads();

    const int p2 = tid >> 3;
    const int dg = tid & 7;
    const int r0 = p2 * 2;
    const int r1 = r0 + 1;
    float o0[4] = {0.0f, 0.0f, 0.0f, 0.0f};
    float o1[4] = {0.0f, 0.0f, 0.0f, 0.0f};
#pragma unroll 4
    for (int j = 0; j < 64; j++) {
        float4 v = *reinterpret_cast<const float4*>(&sv[j][dg * 4]);
        float pa = sS[r0][j];
        float pbv = sS[r1][j];
        o0[0] = fmaf(pa, v.x, o0[0]);
        o0[1] = fmaf(pa, v.y, o0[1]);
        o0[2] = fmaf(pa, v.z, o0[2]);
        o0[3] = fmaf(pa, v.w, o0[3]);
        o1[0] = fmaf(pbv, v.x, o1[0]);
        o1[1] = fmaf(pbv, v.y, o1[1]);
        o1[2] = fmaf(pbv, v.z, o1[2]);
        o1[3] = fmaf(pbv, v.w, o1[3]);
    }
    size_t off0 = ((size_t)win * 64 + r0) * 256 + head * 32 + dg * 4;
    size_t off1 = ((size_t)win * 64 + r1) * 256 + head * 32 + dg * 4;
#pragma unroll
    for (int pass = 0; pass < 2; pass++) {
        const float* ov = (pass == 0) ? o0 : o1;
        size_t off = (pass == 0) ? off0 : off1;
        __nv_bfloat16 hh[4];
        __nv_bfloat16 ll[4];
#pragma unroll
        for (int c = 0; c < 4; c++) {
            hh[c] = __float2bfloat16(ov[c]);
            ll[c] = __float2bfloat16(ov[c] - __bfloat162float(hh[c]));
        }
        __nv_bfloat162* hp = reinterpret_cast<__nv_bfloat162*>(g_ah + off);
        __nv_bfloat162* lp = reinterpret_cast<__nv_bfloat162*>(g_al + off);
        hp[0] = __halves2bfloat162(hh[0], hh[1]);
        hp[1] = __halves2bfloat162(hh[2], hh[3]);
        lp[0] = __halves2bfloat162(ll[0], ll[1]);
        lp[1] = __halves2bfloat162(ll[2], ll[3]);
    }
}

// ---------------------------------------------------------------------------
// Launch. DAG: wfold, split3 -> gemm0 -> { (transpose -> conv), attn } -> gemm1
// ---------------------------------------------------------------------------
extern "C" void kernel_launch(void* const* d_in, const int* in_sizes, int n_in,
                              void* d_out, int out_size)
{
    (void)in_sizes;
    (void)n_in;
    (void)out_size;
    const float* x_in   = (const float*)d_in[0];
    const float* qkv_w  = (const float*)d_in[1];
    const float* proj_w = (const float*)d_in[2];
    const float* proj_b = (const float*)d_in[3];
    const float* rpb    = (const float*)d_in[4];
    const float* fc_w   = (const float*)d_in[5];
    const float* fc_b   = (const float*)d_in[6];
    const float* dep_w  = (const float*)d_in[7];
    const float* dep_b  = (const float*)d_in[8];
    const float* alpha  = (const float*)d_in[9];
    const float* beta   = (const float*)d_in[10];
    float* out = (float*)d_out;

    float* p_qkv;
    __nv_bfloat16* p_xh;
    __nv_bfloat16* p_xl;
    __nv_bfloat16* p_ah;
    __nv_bfloat16* p_al;
    __nv_bfloat16* p_wqh;
    __nv_bfloat16* p_wql;
    __nv_bfloat16* p_pwh;
    __nv_bfloat16* p_pwl;
    cudaGetSymbolAddress((void**)&p_qkv, g_qkv);
    cudaGetSymbolAddress((void**)&p_xh, g_xh);
    cudaGetSymbolAddress((void**)&p_xl, g_xl);
    cudaGetSymbolAddress((void**)&p_ah, g_ah);
    cudaGetSymbolAddress((void**)&p_al, g_al);
    cudaGetSymbolAddress((void**)&p_wqh, g_wqh);
    cudaGetSymbolAddress((void**)&p_wql, g_wql);
    cudaGetSymbolAddress((void**)&p_pwh, g_pwh);
    cudaGetSymbolAddress((void**)&p_pwl, g_pwl);

    cudaFuncSetAttribute(gemm_bf16<0>, cudaFuncAttributeMaxDynamicSharedMemorySize,
                         GEMM_SMEM_BYTES);
    cudaFuncSetAttribute(gemm_bf16<1>, cudaFuncAttributeMaxDynamicSharedMemorySize,
                         GEMM_SMEM_BYTES);
    cudaFuncSetAttribute(conv_kernel, cudaFuncAttributeMaxDynamicSharedMemorySize,
                         CONV_SMEM_BYTES);

    static cudaStream_t s_attn = 0;
    static cudaEvent_t ev_fork = 0;
    static cudaEvent_t ev_join = 0;
    if (s_attn == 0) {
        cudaStreamCreateWithFlags(&s_attn, cudaStreamNonBlocking);
        cudaEventCreateWithFlags(&ev_fork, cudaEventDisableTiming);
        cudaEventCreateWithFlags(&ev_join, cudaEventDisableTiming);
    }

    // weight fold (independent of qkv)
    wfold_kernel<<<27, 256>>>(dep_w, fc_w, fc_b);
    // merged bf16 splits
    split3_kernel<<<16640, 256>>>(x_in, qkv_w, proj_w);
    // qkv = x_in @ qkv_w
    gemm_bf16<0><<<dim3(12, 512), 256, GEMM_SMEM_BYTES>>>(
        p_xh, p_xl, p_wqh, p_wql, p_qkv, 65536, 768, 256,
        (const float*)0, (const float*)0);

    // fork: attn on side stream
    cudaEventRecord(ev_fork, 0);
    cudaStreamWaitEvent(s_attn, ev_fork, 0);
    attn_kernel<<<dim3(1024, 8), 256, 0, s_attn>>>(rpb);
    cudaEventRecord(ev_join, s_attn);

    // transpose qkv for conv
    transpose_kernel<<<dim3(128, 24, 4), 256>>>();
    // fused grouped conv -> out = beta*(conv + dep_b)
    conv_kernel<<<dim3(2, 8, 128), 512, CONV_SMEM_BYTES>>>(dep_b, beta, out);

    // join, then proj + window-reverse + out += alpha*(...)
    cudaStreamWaitEvent(0, ev_join, 0);
    gemm_bf16<1><<<dim3(4, 512), 256, GEMM_SMEM_BYTES>>>(
        p_ah, p_al, p_pwh, p_pwl, out, 65536, 256, 256, proj_b, alpha);
}

// round 14
// speedup vs baseline: 2.0129x; 1.0290x over previous
#include <cuda_runtime.h>
#include <cuda_bf16.h>
#include <stdint.h>
#include <math.h>

typedef unsigned int u32;

// ---------------------------------------------------------------------------
// x_in [4,16,32,32,256], qkv_w [256,768], proj_w [256,256], proj_b [256]
// rpb_table [343,8], fc_w [27,24], fc_b [27], dep_w [256,27,3,3,3],
// dep_b [256], alpha, beta; out [4,16,32,32,256] float32
// ---------------------------------------------------------------------------
#define LSP 16384

__device__ float g_qkv[(size_t)65536 * 768];
__device__ float g_qt [(size_t)4 * 32 * 24 * LSP];
__device__ float g_w2 [256 * 25 * 27];

__device__ __nv_bfloat16 g_xh[(size_t)65536 * 256];
__device__ __nv_bfloat16 g_xl[(size_t)65536 * 256];
__device__ __nv_bfloat16 g_ah[(size_t)65536 * 256];
__device__ __nv_bfloat16 g_al[(size_t)65536 * 256];
__device__ __nv_bfloat16 g_wqh[256 * 768];
__device__ __nv_bfloat16 g_wql[256 * 768];
__device__ __nv_bfloat16 g_pwh[256 * 256];
__device__ __nv_bfloat16 g_pwl[256 * 256];

__device__ __forceinline__ u32 smem_u32(const void* p) {
    return (u32)__cvta_generic_to_shared(p);
}

__device__ __forceinline__ void ldsm_x4(u32& r0, u32& r1, u32& r2, u32& r3, u32 a) {
    asm volatile("ldmatrix.sync.aligned.m8n8.x4.shared.b16 {%0,%1,%2,%3}, [%4];\n"
                 : "=r"(r0), "=r"(r1), "=r"(r2), "=r"(r3) : "r"(a));
}

__device__ __forceinline__ void ldsm_x4t(u32& r0, u32& r1, u32& r2, u32& r3, u32 a) {
    asm volatile("ldmatrix.sync.aligned.m8n8.x4.trans.shared.b16 {%0,%1,%2,%3}, [%4];\n"
                 : "=r"(r0), "=r"(r1), "=r"(r2), "=r"(r3) : "r"(a));
}

__device__ __forceinline__ void mma_bf16(float* c, const u32* a, const u32* b) {
    asm volatile(
        "mma.sync.aligned.m16n8k16.row.col.f32.bf16.bf16.f32 "
        "{%0,%1,%2,%3}, {%4,%5,%6,%7}, {%8,%9}, {%0,%1,%2,%3};\n"
        : "+f"(c[0]), "+f"(c[1]), "+f"(c[2]), "+f"(c[3])
        : "r"(a[0]), "r"(a[1]), "r"(a[2]), "r"(a[3]), "r"(b[0]), "r"(b[1]));
}

__device__ __forceinline__ float warp16_max(float v) {
    v = fmaxf(v, __shfl_xor_sync(0xffffffffu, v, 1));
    v = fmaxf(v, __shfl_xor_sync(0xffffffffu, v, 2));
    v = fmaxf(v, __shfl_xor_sync(0xffffffffu, v, 4));
    v = fmaxf(v, __shfl_xor_sync(0xffffffffu, v, 8));
    return v;
}

__device__ __forceinline__ float warp16_sum(float v) {
    v += __shfl_xor_sync(0xffffffffu, v, 1);
    v += __shfl_xor_sync(0xffffffffu, v, 2);
    v += __shfl_xor_sync(0xffffffffu, v, 4);
    v += __shfl_xor_sync(0xffffffffu, v, 8);
    return v;
}

// ---------------------------------------------------------------------------
// Merged elementwise fp32 -> (bf16 hi, bf16 lo) split for all 3 tensors.
// ---------------------------------------------------------------------------
#define SPLIT_N1 4194304
#define SPLIT_N2 49152
#define SPLIT_N3 16384

__global__ __launch_bounds__(256) void split3_kernel(
    const float* __restrict__ x, const float* __restrict__ wq,
    const float* __restrict__ pw)
{
    int i = blockIdx.x * blockDim.x + threadIdx.x;
    const float* s;
    __nv_bfloat16* h;
    __nv_bfloat16* l;
    int idx;
    if (i < SPLIT_N1) {
        s = x;
        h = g_xh;
        l = g_xl;
        idx = i;
    } else if (i < SPLIT_N1 + SPLIT_N2) {
        s = wq;
        h = g_wqh;
        l = g_wql;
        idx = i - SPLIT_N1;
    } else if (i < SPLIT_N1 + SPLIT_N2 + SPLIT_N3) {
        s = pw;
        h = g_pwh;
        l = g_pwl;
        idx = i - SPLIT_N1 - SPLIT_N2;
    } else {
        return;
    }
    float4 v = reinterpret_cast<const float4*>(s)[idx];
    __nv_bfloat16 h0 = __float2bfloat16(v.x);
    __nv_bfloat16 h1 = __float2bfloat16(v.y);
    __nv_bfloat16 h2 = __float2bfloat16(v.z);
    __nv_bfloat16 h3 = __float2bfloat16(v.w);
    __nv_bfloat16 l0 = __float2bfloat16(v.x - __bfloat162float(h0));
    __nv_bfloat16 l1 = __float2bfloat16(v.y - __bfloat162float(h1));
    __nv_bfloat16 l2 = __float2bfloat16(v.z - __bfloat162float(h2));
    __nv_bfloat16 l3 = __float2bfloat16(v.w - __bfloat162float(h3));
    __nv_bfloat162* hp = reinterpret_cast<__nv_bfloat162*>(h) + idx * 2;
    __nv_bfloat162* lp = reinterpret_cast<__nv_bfloat162*>(l) + idx * 2;
    hp[0] = __halves2bfloat162(h0, h1);
    hp[1] = __halves2bfloat162(h2, h3);
    lp[0] = __halves2bfloat162(l0, l1);
    lp[1] = __halves2bfloat162(l2, l3);
}

// ---------------------------------------------------------------------------
// Tensor-core GEMM, 128(M) x 64(N) x 32(K) tile, 256 threads, 2 blocks/SM.
// ---------------------------------------------------------------------------
#define GEMM_SMEM_BYTES (29696 * 2)

template<int MODE>
__global__ __launch_bounds__(256, 2) void gemm_bf16(
    const __nv_bfloat16* __restrict__ Ah, const __nv_bfloat16* __restrict__ Al,
    const __nv_bfloat16* __restrict__ Bh, const __nv_bfloat16* __restrict__ Bl,
    float* __restrict__ C, int M, int N, int K,
    const float* __restrict__ bias, const float* __restrict__ alpha_p)
{
    extern __shared__ __nv_bfloat16 gsm[];
    __nv_bfloat16* pAh = gsm;
    __nv_bfloat16* pAl = gsm + 10240;
    __nv_bfloat16* pBh = gsm + 20480;
    __nv_bfloat16* pBl = gsm + 25088;

    const int tid = threadIdx.x;
    const int lane = tid & 31;
    const int wid = tid >> 5;
    const int wm = (wid & 3) * 32;
    const int wn = (wid >> 2) * 32;
    const int bm = blockIdx.y * 128;
    const int bn = blockIdx.x * 64;

    float acc[2][4][4];
#pragma unroll
    for (int i = 0; i < 2; i++) {
#pragma unroll
        for (int j = 0; j < 4; j++) {
#pragma unroll
            for (int r = 0; r < 4; r++) {
                acc[i][j][r] = 0.0f;
            }
        }
    }

    const int nk = K >> 5;
    uint4 rAh[2];
    uint4 rAl[2];
    uint4 rBh;
    uint4 rBl;

    const int arow0 = tid >> 2;
    const int acol0 = (tid & 3) * 8;
    const int arow1 = (tid + 256) >> 2;
    const int brow = tid >> 3;
    const int bcol = (tid & 7) * 8;

    rAh[0] = *reinterpret_cast<const uint4*>(Ah + (size_t)(bm + arow0) * K + acol0);
    rAl[0] = *reinterpret_cast<const uint4*>(Al + (size_t)(bm + arow0) * K + acol0);
    rAh[1] = *reinterpret_cast<const uint4*>(Ah + (size_t)(bm + arow1) * K + acol0);
    rAl[1] = *reinterpret_cast<const uint4*>(Al + (size_t)(bm + arow1) * K + acol0);
    rBh = *reinterpret_cast<const uint4*>(Bh + (size_t)brow * N + bn + bcol);
    rBl = *reinterpret_cast<const uint4*>(Bl + (size_t)brow * N + bn + bcol);

    *reinterpret_cast<uint4*>(pAh + arow0 * 40 + acol0) = rAh[0];
    *reinterpret_cast<uint4*>(pAl + arow0 * 40 + acol0) = rAl[0];
    *reinterpret_cast<uint4*>(pAh + arow1 * 40 + acol0) = rAh[1];
    *reinterpret_cast<uint4*>(pAl + arow1 * 40 + acol0) = rAl[1];
    *reinterpret_cast<uint4*>(pBh + brow * 72 + bcol) = rBh;
    *reinterpret_cast<uint4*>(pBl + brow * 72 + bcol) = rBl;
    __syncthreads();

    const int a_r = lane & 15;
    const int a_k = (lane >> 4) * 8;

    for (int kt = 0; kt < nk; kt++) {
        const int curA = (kt & 1) * 5120;
        const int curB = (kt & 1) * 2304;

        if (kt + 1 < nk) {
            size_t koff = (size_t)(kt + 1) * 32;
            rAh[0] = *reinterpret_cast<const uint4*>(Ah + (size_t)(bm + arow0) * K + koff + acol0);
            rAl[0] = *reinterpret_cast<const uint4*>(Al + (size_t)(bm + arow0) * K + koff + acol0);
            rAh[1] = *reinterpret_cast<const uint4*>(Ah + (size_t)(bm + arow1) * K + koff + acol0);
            rAl[1] = *reinterpret_cast<const uint4*>(Al + (size_t)(bm + arow1) * K + koff + acol0);
            rBh = *reinterpret_cast<const uint4*>(Bh + (koff + brow) * N + bn + bcol);
            rBl = *reinterpret_cast<const uint4*>(Bl + (koff + brow) * N + bn + bcol);
        }

#pragma unroll
        for (int ks = 0; ks < 2; ks++) {
            u32 aH[2][4];
            u32 aL[2][4];
            u32 bH[4][2];
            u32 bL[4][2];
#pragma unroll
            for (int mi = 0; mi < 2; mi++) {
                u32 adr = smem_u32(pAh + curA + (wm + mi * 16 + a_r) * 40 + ks * 16 + a_k);
                ldsm_x4(aH[mi][0], aH[mi][1], aH[mi][2], aH[mi][3], adr);
                adr = smem_u32(pAl + curA + (wm + mi * 16 + a_r) * 40 + ks * 16 + a_k);
                ldsm_x4(aL[mi][0], aL[mi][1], aL[mi][2], aL[mi][3], adr);
            }
#pragma unroll
            for (int nj = 0; nj < 2; nj++) {
                u32 r0;
                u32 r1;
                u32 r2;
                u32 r3;
                u32 adr = smem_u32(pBh + curB + (ks * 16 + a_r) * 72 + wn + nj * 16 + a_k);
                ldsm_x4t(r0, r1, r2, r3, adr);
                bH[nj * 2][0] = r0;
                bH[nj * 2][1] = r1;
                bH[nj * 2 + 1][0] = r2;
                bH[nj * 2 + 1][1] = r3;
                adr = smem_u32(pBl + curB + (ks * 16 + a_r) * 72 + wn + nj * 16 + a_k);
                ldsm_x4t(r0, r1, r2, r3, adr);
                bL[nj * 2][0] = r0;
                bL[nj * 2][1] = r1;
                bL[nj * 2 + 1][0] = r2;
                bL[nj * 2 + 1][1] = r3;
            }
#pragma unroll
            for (int mi = 0; mi < 2; mi++) {
#pragma unroll
                for (int ni = 0; ni < 4; ni++) {
                    mma_bf16(acc[mi][ni], aH[mi], bH[ni]);
                    mma_bf16(acc[mi][ni], aH[mi], bL[ni]);
                    mma_bf16(acc[mi][ni], aL[mi], bH[ni]);
                }
            }
        }

        if (kt + 1 < nk) {
            const int nxtA = ((kt + 1) & 1) * 5120;
            const int nxtB = ((kt + 1) & 1) * 2304;
            *reinterpret_cast<uint4*>(pAh + nxtA + arow0 * 40 + acol0) = rAh[0];
            *reinterpret_cast<uint4*>(pAl + nxtA + arow0 * 40 + acol0) = rAl[0];
            *reinterpret_cast<uint4*>(pAh + nxtA + arow1 * 40 + acol0) = rAh[1];
            *reinterpret_cast<uint4*>(pAl + nxtA + arow1 * 40 + acol0) = rAl[1];
            *reinterpret_cast<uint4*>(pBh + nxtB + brow * 72 + bcol) = rBh;
            *reinterpret_cast<uint4*>(pBl + nxtB + brow * 72 + bcol) = rBl;
        }
        __syncthreads();
    }

    const int g = lane >> 2;
    const int tg = lane & 3;

    if (MODE == 0) {
#pragma unroll
        for (int mi = 0; mi < 2; mi++) {
            int row0 = bm + wm + mi * 16 + g;
#pragma unroll
            for (int ni = 0; ni < 4; ni++) {
                int col = bn + wn + ni * 8 + tg * 2;
                float2 v0;
                float2 v1;
                v0.x = acc[mi][ni][0];
                v0.y = acc[mi][ni][1];
                v1.x = acc[mi][ni][2];
                v1.y = acc[mi][ni][3];
                *reinterpret_cast<float2*>(&C[(size_t)row0 * N + col]) = v0;
                *reinterpret_cast<float2*>(&C[(size_t)(row0 + 8) * N + col]) = v1;
            }
        }
    } else {
        const float alpha = alpha_p[0];
#pragma unroll
        for (int mi = 0; mi < 2; mi++) {
#pragma unroll
            for (int half = 0; half < 2; half++) {
                int row = bm + wm + mi * 16 + g + half * 8;
                int win = row >> 6;
                int tok = row & 63;
                int b = win >> 8;
                int r2 = win & 255;
                int dblk = r2 >> 6;
                int h2 = r2 & 63;
                int hblk = h2 >> 3;
                int wblk = h2 & 7;
                int z4 = tok >> 4;
                int y4 = (tok >> 2) & 3;
                int x4 = tok & 3;
                size_t spat = (((size_t)b * 16 + dblk * 4 + z4) * 32 + hblk * 4 + y4) * 32
                              + wblk * 4 + x4;
#pragma unroll
                for (int ni = 0; ni < 4; ni++) {
                    int col = bn + wn + ni * 8 + tg * 2;
                    float2 pb = *reinterpret_cast<const float2*>(&bias[col]);
                    float* dst = &C[spat * 256 + col];
                    float2 e = *reinterpret_cast<float2*>(dst);
                    e.x += alpha * (acc[mi][ni][half * 2 + 0] + pb.x);
                    e.y += alpha * (acc[mi][ni][half * 2 + 1] + pb.y);
                    *reinterpret_cast<float2*>(dst) = e;
                }
            }
        }
    }
}

// ---------------------------------------------------------------------------
// Weight fold: W2[ocg][ch<24][tap] = sum_o dep_w[ocg][o][tap]*fc_w[o][ch];
//              W2[ocg][24][tap]   = sum_o dep_w[ocg][o][tap]*fc_b[o].
// ---------------------------------------------------------------------------
__global__ __launch_bounds__(256) void wfold_kernel(
    const float* __restrict__ dep_w, const float* __restrict__ fcw,
    const float* __restrict__ fcb)
{
    __shared__ float s_fcw[648];
    __shared__ float s_fcb[27];
    const int tap = blockIdx.x;
    const int ocg = threadIdx.x;
    for (int e = threadIdx.x; e < 648; e += 256) {
        s_fcw[e] = fcw[e];
    }
    if (threadIdx.x < 27) {
        s_fcb[threadIdx.x] = fcb[threadIdx.x];
    }
    __syncthreads();

    float dw[27];
#pragma unroll
    for (int o = 0; o < 27; o++) {
        dw[o] = dep_w[(size_t)ocg * 729 + o * 27 + tap];
    }
#pragma unroll 1
    for (int ch = 0; ch < 24; ch++) {
        float s = 0.0f;
#pragma unroll
        for (int o = 0; o < 27; o++) {
            s = fmaf(dw[o], s_fcw[o * 24 + ch], s);
        }
        g_w2[ocg * 675 + ch * 27 + tap] = s;
    }
    float sb = 0.0f;
#pragma unroll
    for (int o = 0; o < 27; o++) {
        sb = fmaf(dw[o], s_fcb[o], sb);
    }
    g_w2[ocg * 675 + 24 * 27 + tap] = sb;
}

// ---------------------------------------------------------------------------
// Transpose: g_qt[b][g][gg][l] = qkv_flat[b][gg*524288 + l*32 + g].
// ---------------------------------------------------------------------------
__global__ __launch_bounds__(256) void transpose_kernel()
{
    __shared__ float sm[32 * 132];
    const int lt = blockIdx.x;
    const int gg = blockIdx.y;
    const int b = blockIdx.z;
    const int tid = threadIdx.x;
    const float* src = g_qkv + (size_t)b * 12582912 + (size_t)gg * 524288
                       + (size_t)lt * 128 * 32;
#pragma unroll
    for (int it = 0; it < 4; it++) {
        int idx4 = tid + it * 256;
        float4 v = reinterpret_cast<const float4*>(src)[idx4];
        int flat = idx4 * 4;
        int l = flat >> 5;
        int x = flat & 31;
        sm[(x + 0) * 132 + l] = v.x;
        sm[(x + 1) * 132 + l] = v.y;
        sm[(x + 2) * 132 + l] = v.z;
        sm[(x + 3) * 132 + l] = v.w;
    }
    __syncthreads();
    const int l4 = (tid & 31) * 4;
#pragma unroll
    for (int go = 0; go < 4; go++) {
        int gch = go * 8 + (tid >> 5);
        float4 v = *reinterpret_cast<const float4*>(&sm[gch * 132 + l4]);
        float* dst = g_qt + (((size_t)(b * 32 + gch) * 24 + gg) * LSP)
                     + lt * 128 + l4;
        *reinterpret_cast<float4*>(dst) = v;
    }
}

// ---------------------------------------------------------------------------
// Fused grouped conv: 25 channels (24 qkv-derived + ones for fc_b), folded
// weights. Block tile 2z x 8y x 32x, 512 threads, per-thread 2oc x 4x.
// k streamed in chunks of 7 (7,7,7,4); window 40.3KB + weights 28.8KB
// = 69.1KB -> 3 blocks/SM (launch_bounds(512,3), ~40 regs).
// ---------------------------------------------------------------------------
#define CONV_NCH 25
#define CONV_KCHUNK 7
#define CONV_SW_FLOATS  (CONV_KCHUNK * 4 * 10 * 36)
#define CONV_DEP_FLOATS (8 * CONV_NCH * 9 * 4)
#define CONV_SMEM_BYTES ((CONV_SW_FLOATS + CONV_DEP_FLOATS) * 4)

__device__ __forceinline__ void conv_load_chunk(
    float* sw, const float* fin, int tid, int y0, int z0, int kbase, int nk)
{
    const int elems = nk * 4 * 10 * 34;
    for (int e = tid; e < elems; e += 512) {
        int x = e % 34;
        int t1 = e / 34;
        int yy = t1 % 10;
        int t2 = t1 / 10;
        int wz = t2 & 3;
        int kl = t2 >> 2;
        int ch = kbase + kl;
        int gx = x - 1;
        int gy = y0 + yy - 1;
        int gz = z0 + wz - 1;
        float v = 0.0f;
        if (gx >= 0 && gx < 32 && gy >= 0 && gy < 32 && gz >= 0 && gz < 16) {
            if (ch < 24) {
                v = fin[(size_t)ch * LSP + gz * 1024 + gy * 32 + gx];
            } else {
                v = 1.0f;
            }
        }
        sw[((kl * 4 + wz) * 10 + yy) * 36 + x] = v;
    }
}

__global__ __launch_bounds__(512, 3) void conv_kernel(
    const float* __restrict__ dep_b, const float* __restrict__ beta_p,
    float* __restrict__ out)
{
    extern __shared__ float sm[];
    float* sw = sm;
    float* sdep = sm + CONV_SW_FLOATS;

    const int tid = threadIdx.x;
    const int y0 = blockIdx.x * 8;
    const int z0 = blockIdx.y * 2;
    const int bg = blockIdx.z;
    const int b = bg >> 5;
    const int g = bg & 31;

    for (int e = tid; e < CONV_DEP_FLOATS; e += 512) {
        int dx = e & 3;
        int rest = e >> 2;
        int dydz = rest % 9;
        int rest2 = rest / 9;
        int ch = rest2 % CONV_NCH;
        int ocl = rest2 / CONV_NCH;
        float v = 0.0f;
        if (dx < 3) {
            v = g_w2[(g * 8 + ocl) * 675 + ch * 27 + dydz * 3 + dx];
        }
        sdep[e] = v;
    }

    const float* fin = g_qt + (size_t)(b * 32 + g) * 24 * LSP;
    conv_load_chunk(sw, fin, tid, y0, z0, 0, CONV_KCHUNK);
    __syncthreads();

    const int xq = tid & 7;
    const int ocp = (tid >> 3) & 3;
    const int yy = (tid >> 5) & 7;
    const int zz = tid >> 8;
    const int oc0 = ocp * 2;

    float acc0[4] = {0.0f, 0.0f, 0.0f, 0.0f};
    float acc1[4] = {0.0f, 0.0f, 0.0f, 0.0f};

    const float* wd0 = sdep + oc0 * (CONV_NCH * 36);
    const float* wd1 = wd0 + CONV_NCH * 36;

#pragma unroll
    for (int chunk = 0; chunk < 4; chunk++) {
        const int kbase = chunk * CONV_KCHUNK;
        const int nk = (chunk < 3) ? CONV_KCHUNK : (CONV_NCH - 3 * CONV_KCHUNK);
#pragma unroll 1
        for (int kl = 0; kl < nk; kl++) {
            const int k = kbase + kl;
#pragma unroll
            for (int dz = 0; dz < 3; dz++) {
#pragma unroll
                for (int dy = 0; dy < 3; dy++) {
                    const float* wrow = &sw[((kl * 4 + zz + dz) * 10 + yy + dy) * 36 + xq * 4];
                    float4 wa = *reinterpret_cast<const float4*>(wrow);
                    float2 wb = *reinterpret_cast<const float2*>(wrow + 4);
                    float win[6];
                    win[0] = wa.x;
                    win[1] = wa.y;
                    win[2] = wa.z;
                    win[3] = wa.w;
                    win[4] = wb.x;
                    win[5] = wb.y;
                    float4 w0v = *reinterpret_cast<const float4*>(wd0 + (k * 9 + dz * 3 + dy) * 4);
                    float4 w1v = *reinterpret_cast<const float4*>(wd1 + (k * 9 + dz * 3 + dy) * 4);
                    float w0[3];
                    float w1[3];
                    w0[0] = w0v.x;
                    w0[1] = w0v.y;
                    w0[2] = w0v.z;
                    w1[0] = w1v.x;
                    w1[1] = w1v.y;
                    w1[2] = w1v.z;
#pragma unroll
                    for (int dx = 0; dx < 3; dx++) {
#pragma unroll
                        for (int c = 0; c < 4; c++) {
                            acc0[c] = fmaf(win[c + dx], w0[dx], acc0[c]);
                            acc1[c] = fmaf(win[c + dx], w1[dx], acc1[c]);
                        }
                    }
                }
            }
        }
        if (chunk < 3) {
            __syncthreads();
            const int nkn = (chunk < 2) ? CONV_KCHUNK : (CONV_NCH - 3 * CONV_KCHUNK);
            conv_load_chunk(sw, fin, tid, y0, z0, kbase + CONV_KCHUNK, nkn);
            __syncthreads();
        }
    }

    const float beta = beta_p[0];
    const int ocg0 = g * 8 + oc0;
    const float b0 = dep_b[ocg0];
    const float b1 = dep_b[ocg0 + 1];
    const size_t spatbase = (size_t)b * LSP + (z0 + zz) * 1024 + (y0 + yy) * 32 + xq * 4;
#pragma unroll
    for (int c = 0; c < 4; c++) {
        float2 v;
        v.x = beta * (acc0[c] + b0);
        v.y = beta * (acc1[c] + b1);
        *reinterpret_cast<float2*>(out + (spatbase + c) * 256 + ocg0) = v;
    }
}

// ---------------------------------------------------------------------------
// Windowed attention -> bf16 split output (g_ah/g_al).
// ---------------------------------------------------------------------------
__global__ __launch_bounds__(256) void attn_kernel(const float* __restrict__ rpb)
{
    __shared__ __align__(16) float sq[64][36];
    __shared__ __align__(16) float skT[32][68];
    __shared__ __align__(16) float sv[64][36];
    __shared__ __align__(16) float sS[64][68];
    __shared__ float sbias[343];

    const int tid = threadIdx.x;
    const int win = blockIdx.x;
    const int head = blockIdx.y;
    const int b = win >> 8;
    const int rr = win & 255;
    const int dblk = rr >> 6;
    const int h2 = rr & 63;
    const int hblk = h2 >> 3;
    const int wblk = h2 & 7;

    for (int i = tid; i < 343; i += 256) {
        sbias[i] = rpb[i * 8 + head];
    }

    for (int e = tid; e < 64 * 32; e += 256) {
        int tok = e >> 5;
        int dd = e & 31;
        int z = tok >> 4;
        int y = (tok >> 2) & 3;
        int x = tok & 3;
        size_t spat = (((size_t)b * 16 + dblk * 4 + z) * 32 + hblk * 4 + y) * 32
                      + wblk * 4 + x;
        const float* src = g_qkv + spat * 768 + head * 32 + dd;
        sq[tok][dd] = src[0];
        skT[dd][tok] = src[256];
        sv[tok][dd] = src[512];
    }
    __syncthreads();

    const int i4 = tid >> 4;
    const int jq = tid & 15;
    const int i0 = i4 * 4;
    const int j0 = jq * 4;

    float dots[4][4];
#pragma unroll
    for (int r = 0; r < 4; r++) {
#pragma unroll
        for (int c = 0; c < 4; c++) {
            dots[r][c] = 0.0f;
        }
    }

#pragma unroll
    for (int d8 = 0; d8 < 4; d8++) {
        float qreg[4][8];
#pragma unroll
        for (int r = 0; r < 4; r++) {
            float4 q0 = *reinterpret_cast<const float4*>(&sq[i0 + r][d8 * 8]);
            float4 q1 = *reinterpret_cast<const float4*>(&sq[i0 + r][d8 * 8 + 4]);
            qreg[r][0] = q0.x; qreg[r][1] = q0.y; qreg[r][2] = q0.z; qreg[r][3] = q0.w;
            qreg[r][4] = q1.x; qreg[r][5] = q1.y; qreg[r][6] = q1.z; qreg[r][7] = q1.w;
        }
#pragma unroll
        for (int dd = 0; dd < 8; dd++) {
            float4 kv = *reinterpret_cast<const float4*>(&skT[d8 * 8 + dd][j0]);
#pragma unroll
            for (int r = 0; r < 4; r++) {
                dots[r][0] = fmaf(qreg[r][dd], kv.x, dots[r][0]);
                dots[r][1] = fmaf(qreg[r][dd], kv.y, dots[r][1]);
                dots[r][2] = fmaf(qreg[r][dd], kv.z, dots[r][2]);
                dots[r][3] = fmaf(qreg[r][dd], kv.w, dots[r][3]);
            }
        }
    }

    const float scale = 0.17677669529663687f;
#pragma unroll
    for (int r = 0; r < 4; r++) {
        int ti = i0 + r;
        int zi = ti >> 4;
        int yi = (ti >> 2) & 3;
        int xi = ti & 3;
        float sv4[4];
#pragma unroll
        for (int c = 0; c < 4; c++) {
            int tj = j0 + c;
            int zj = tj >> 4;
            int yj = (tj >> 2) & 3;
            int xj = tj & 3;
            int rel = (zi - zj + 3) * 49 + (yi - yj + 3) * 7 + (xi - xj + 3);
            sv4[c] = dots[r][c] * scale + sbias[rel];
        }
        float rmax = fmaxf(fmaxf(sv4[0], sv4[1]), fmaxf(sv4[2], sv4[3]));
        rmax = warp16_max(rmax);
        float rsum = 0.0f;
#pragma unroll
        for (int c = 0; c < 4; c++) {
            sv4[c] = __expf(sv4[c] - rmax);
            rsum += sv4[c];
        }
        rsum = warp16_sum(rsum);
        float inv = 1.0f / rsum;
        float4 pv;
        pv.x = sv4[0] * inv;
        pv.y = sv4[1] * inv;
        pv.z = sv4[2] * inv;
        pv.w = sv4[3] * inv;
        *reinterpret_cast<float4*>(&sS[i0 + r][j0]) = pv;
    }
    __syncthreads();

    const int p2 = tid >> 3;
    const int dg = tid & 7;
    const int r0 = p2 * 2;
    const int r1 = r0 + 1;
    float o0[4] = {0.0f, 0.0f, 0.0f, 0.0f};
    float o1[4] = {0.0f, 0.0f, 0.0f, 0.0f};
#pragma unroll 4
    for (int j = 0; j < 64; j++) {
        float4 v = *reinterpret_cast<const float4*>(&sv[j][dg * 4]);
        float pa = sS[r0][j];
        float pbv = sS[r1][j];
        o0[0] = fmaf(pa, v.x, o0[0]);
        o0[1] = fmaf(pa, v.y, o0[1]);
        o0[2] = fmaf(pa, v.z, o0[2]);
        o0[3] = fmaf(pa, v.w, o0[3]);
        o1[0] = fmaf(pbv, v.x, o1[0]);
        o1[1] = fmaf(pbv, v.y, o1[1]);
        o1[2] = fmaf(pbv, v.z, o1[2]);
        o1[3] = fmaf(pbv, v.w, o1[3]);
    }
    size_t off0 = ((size_t)win * 64 + r0) * 256 + head * 32 + dg * 4;
    size_t off1 = ((size_t)win * 64 + r1) * 256 + head * 32 + dg * 4;
#pragma unroll
    for (int pass = 0; pass < 2; pass++) {
        const float* ov = (pass == 0) ? o0 : o1;
        size_t off = (pass == 0) ? off0 : off1;
        __nv_bfloat16 hh[4];
        __nv_bfloat16 ll[4];
#pragma unroll
        for (int c = 0; c < 4; c++) {
            hh[c] = __float2bfloat16(ov[c]);
            ll[c] = __float2bfloat16(ov[c] - __bfloat162float(hh[c]));
        }
        __nv_bfloat162* hp = reinterpret_cast<__nv_bfloat162*>(g_ah + off);
        __nv_bfloat162* lp = reinterpret_cast<__nv_bfloat162*>(g_al + off);
        hp[0] = __halves2bfloat162(hh[0], hh[1]);
        hp[1] = __halves2bfloat162(hh[2], hh[3]);
        lp[0] = __halves2bfloat162(ll[0], ll[1]);
        lp[1] = __halves2bfloat162(ll[2], ll[3]);
    }
}

// ---------------------------------------------------------------------------
// Launch. DAG: wfold, split3 -> gemm0 -> { (transpose -> conv), attn } -> gemm1
// ---------------------------------------------------------------------------
extern "C" void kernel_launch(void* const* d_in, const int* in_sizes, int n_in,
                              void* d_out, int out_size)
{
    (void)in_sizes;
    (void)n_in;
    (void)out_size;
    const float* x_in   = (const float*)d_in[0];
    const float* qkv_w  = (const float*)d_in[1];
    const float* proj_w = (const float*)d_in[2];
    const float* proj_b = (const float*)d_in[3];
    const float* rpb    = (const float*)d_in[4];
    const float* fc_w   = (const float*)d_in[5];
    const float* fc_b   = (const float*)d_in[6];
    const float* dep_w  = (const float*)d_in[7];
    const float* dep_b  = (const float*)d_in[8];
    const float* alpha  = (const float*)d_in[9];
    const float* beta   = (const float*)d_in[10];
    float* out = (float*)d_out;

    float* p_qkv;
    __nv_bfloat16* p_xh;
    __nv_bfloat16* p_xl;
    __nv_bfloat16* p_ah;
    __nv_bfloat16* p_al;
    __nv_bfloat16* p_wqh;
    __nv_bfloat16* p_wql;
    __nv_bfloat16* p_pwh;
    __nv_bfloat16* p_pwl;
    cudaGetSymbolAddress((void**)&p_qkv, g_qkv);
    cudaGetSymbolAddress((void**)&p_xh, g_xh);
    cudaGetSymbolAddress((void**)&p_xl, g_xl);
    cudaGetSymbolAddress((void**)&p_ah, g_ah);
    cudaGetSymbolAddress((void**)&p_al, g_al);
    cudaGetSymbolAddress((void**)&p_wqh, g_wqh);
    cudaGetSymbolAddress((void**)&p_wql, g_wql);
    cudaGetSymbolAddress((void**)&p_pwh, g_pwh);
    cudaGetSymbolAddress((void**)&p_pwl, g_pwl);

    cudaFuncSetAttribute(gemm_bf16<0>, cudaFuncAttributeMaxDynamicSharedMemorySize,
                         GEMM_SMEM_BYTES);
    cudaFuncSetAttribute(gemm_bf16<1>, cudaFuncAttributeMaxDynamicSharedMemorySize,
                         GEMM_SMEM_BYTES);
    cudaFuncSetAttribute(conv_kernel, cudaFuncAttributeMaxDynamicSharedMemorySize,
                         CONV_SMEM_BYTES);

    static cudaStream_t s_attn = 0;
    static cudaEvent_t ev_fork = 0;
    static cudaEvent_t ev_join = 0;
    if (s_attn == 0) {
        cudaStreamCreateWithFlags(&s_attn, cudaStreamNonBlocking);
        cudaEventCreateWithFlags(&ev_fork, cudaEventDisableTiming);
        cudaEventCreateWithFlags(&ev_join, cudaEventDisableTiming);
    }

    // weight fold (independent of qkv)
    wfold_kernel<<<27, 256>>>(dep_w, fc_w, fc_b);
    // merged bf16 splits
    split3_kernel<<<16640, 256>>>(x_in, qkv_w, proj_w);
    // qkv = x_in @ qkv_w
    gemm_bf16<0><<<dim3(12, 512), 256, GEMM_SMEM_BYTES>>>(
        p_xh, p_xl, p_wqh, p_wql, p_qkv, 65536, 768, 256,
        (const float*)0, (const float*)0);

    // fork: attn on side stream
    cudaEventRecord(ev_fork, 0);
    cudaStreamWaitEvent(s_attn, ev_fork, 0);
    attn_kernel<<<dim3(1024, 8), 256, 0, s_attn>>>(rpb);
    cudaEventRecord(ev_join, s_attn);

    // transpose qkv for conv
    transpose_kernel<<<dim3(128, 24, 4), 256>>>();
    // fused grouped conv (3 blocks/SM) -> out = beta*(conv + dep_b)
    conv_kernel<<<dim3(4, 8, 128), 512, CONV_SMEM_BYTES>>>(dep_b, beta, out);

    // join, then proj + window-reverse + out += alpha*(...)
    cudaStreamWaitEvent(0, ev_join, 0);
    gemm_bf16<1><<<dim3(4, 512), 256, GEMM_SMEM_BYTES>>>(
        p_ah, p_al, p_pwh, p_pwl, out, 65536, 256, 256, proj_b, alpha);
}

// round 15
// speedup vs baseline: 2.0136x; 1.0003x over previous
#include <cuda_runtime.h>
#include <cuda_bf16.h>
#include <stdint.h>
#include <math.h>

typedef unsigned int u32;

// ---------------------------------------------------------------------------
// x_in [4,16,32,32,256], qkv_w [256,768], proj_w [256,256], proj_b [256]
// rpb_table [343,8], fc_w [27,24], fc_b [27], dep_w [256,27,3,3,3],
// dep_b [256], alpha, beta; out [4,16,32,32,256] float32
// ---------------------------------------------------------------------------
#define LSP 16384

__device__ float g_qkv[(size_t)65536 * 768];
__device__ float g_qt [(size_t)4 * 32 * 24 * LSP];
__device__ float g_w2 [256 * 25 * 27];

__device__ __nv_bfloat16 g_xh[(size_t)65536 * 256];
__device__ __nv_bfloat16 g_xl[(size_t)65536 * 256];
__device__ __nv_bfloat16 g_ah[(size_t)65536 * 256];
__device__ __nv_bfloat16 g_al[(size_t)65536 * 256];
__device__ __nv_bfloat16 g_wqh[256 * 768];
__device__ __nv_bfloat16 g_wql[256 * 768];
__device__ __nv_bfloat16 g_pwh[256 * 256];
__device__ __nv_bfloat16 g_pwl[256 * 256];

__device__ __forceinline__ u32 smem_u32(const void* p) {
    return (u32)__cvta_generic_to_shared(p);
}

__device__ __forceinline__ void ldsm_x4(u32& r0, u32& r1, u32& r2, u32& r3, u32 a) {
    asm volatile("ldmatrix.sync.aligned.m8n8.x4.shared.b16 {%0,%1,%2,%3}, [%4];\n"
                 : "=r"(r0), "=r"(r1), "=r"(r2), "=r"(r3) : "r"(a));
}

__device__ __forceinline__ void ldsm_x4t(u32& r0, u32& r1, u32& r2, u32& r3, u32 a) {
    asm volatile("ldmatrix.sync.aligned.m8n8.x4.trans.shared.b16 {%0,%1,%2,%3}, [%4];\n"
                 : "=r"(r0), "=r"(r1), "=r"(r2), "=r"(r3) : "r"(a));
}

__device__ __forceinline__ void mma_bf16(float* c, const u32* a, const u32* b) {
    asm volatile(
        "mma.sync.aligned.m16n8k16.row.col.f32.bf16.bf16.f32 "
        "{%0,%1,%2,%3}, {%4,%5,%6,%7}, {%8,%9}, {%0,%1,%2,%3};\n"
        : "+f"(c[0]), "+f"(c[1]), "+f"(c[2]), "+f"(c[3])
        : "r"(a[0]), "r"(a[1]), "r"(a[2]), "r"(a[3]), "r"(b[0]), "r"(b[1]));
}

__device__ __forceinline__ float warp16_max(float v) {
    v = fmaxf(v, __shfl_xor_sync(0xffffffffu, v, 1));
    v = fmaxf(v, __shfl_xor_sync(0xffffffffu, v, 2));
    v = fmaxf(v, __shfl_xor_sync(0xffffffffu, v, 4));
    v = fmaxf(v, __shfl_xor_sync(0xffffffffu, v, 8));
    return v;
}

__device__ __forceinline__ float warp16_sum(float v) {
    v += __shfl_xor_sync(0xffffffffu, v, 1);
    v += __shfl_xor_sync(0xffffffffu, v, 2);
    v += __shfl_xor_sync(0xffffffffu, v, 4);
    v += __shfl_xor_sync(0xffffffffu, v, 8);
    return v;
}

// ---------------------------------------------------------------------------
// Merged elementwise fp32 -> (bf16 hi, bf16 lo) split for all 3 tensors.
// ---------------------------------------------------------------------------
#define SPLIT_N1 4194304
#define SPLIT_N2 49152
#define SPLIT_N3 16384

__global__ __launch_bounds__(256) void split3_kernel(
    const float* __restrict__ x, const float* __restrict__ wq,
    const float* __restrict__ pw)
{
    int i = blockIdx.x * blockDim.x + threadIdx.x;
    const float* s;
    __nv_bfloat16* h;
    __nv_bfloat16* l;
    int idx;
    if (i < SPLIT_N1) {
        s = x;
        h = g_xh;
        l = g_xl;
        idx = i;
    } else if (i < SPLIT_N1 + SPLIT_N2) {
        s = wq;
        h = g_wqh;
        l = g_wql;
        idx = i - SPLIT_N1;
    } else if (i < SPLIT_N1 + SPLIT_N2 + SPLIT_N3) {
        s = pw;
        h = g_pwh;
        l = g_pwl;
        idx = i - SPLIT_N1 - SPLIT_N2;
    } else {
        return;
    }
    float4 v = reinterpret_cast<const float4*>(s)[idx];
    __nv_bfloat16 h0 = __float2bfloat16(v.x);
    __nv_bfloat16 h1 = __float2bfloat16(v.y);
    __nv_bfloat16 h2 = __float2bfloat16(v.z);
    __nv_bfloat16 h3 = __float2bfloat16(v.w);
    __nv_bfloat16 l0 = __float2bfloat16(v.x - __bfloat162float(h0));
    __nv_bfloat16 l1 = __float2bfloat16(v.y - __bfloat162float(h1));
    __nv_bfloat16 l2 = __float2bfloat16(v.z - __bfloat162float(h2));
    __nv_bfloat16 l3 = __float2bfloat16(v.w - __bfloat162float(h3));
    __nv_bfloat162* hp = reinterpret_cast<__nv_bfloat162*>(h) + idx * 2;
    __nv_bfloat162* lp = reinterpret_cast<__nv_bfloat162*>(l) + idx * 2;
    hp[0] = __halves2bfloat162(h0, h1);
    hp[1] = __halves2bfloat162(h2, h3);
    lp[0] = __halves2bfloat162(l0, l1);
    lp[1] = __halves2bfloat162(l2, l3);
}

// ---------------------------------------------------------------------------
// Tensor-core GEMM, 128(M) x 64(N) x 32(K) tile, 256 threads, 2 blocks/SM.
// ---------------------------------------------------------------------------
#define GEMM_SMEM_BYTES (29696 * 2)

template<int MODE>
__global__ __launch_bounds__(256, 2) void gemm_bf16(
    const __nv_bfloat16* __restrict__ Ah, const __nv_bfloat16* __restrict__ Al,
    const __nv_bfloat16* __restrict__ Bh, const __nv_bfloat16* __restrict__ Bl,
    float* __restrict__ C, int M, int N, int K,
    const float* __restrict__ bias, const float* __restrict__ alpha_p)
{
    extern __shared__ __nv_bfloat16 gsm[];
    __nv_bfloat16* pAh = gsm;
    __nv_bfloat16* pAl = gsm + 10240;
    __nv_bfloat16* pBh = gsm + 20480;
    __nv_bfloat16* pBl = gsm + 25088;

    const int tid = threadIdx.x;
    const int lane = tid & 31;
    const int wid = tid >> 5;
    const int wm = (wid & 3) * 32;
    const int wn = (wid >> 2) * 32;
    const int bm = blockIdx.y * 128;
    const int bn = blockIdx.x * 64;

    float acc[2][4][4];
#pragma unroll
    for (int i = 0; i < 2; i++) {
#pragma unroll
        for (int j = 0; j < 4; j++) {
#pragma unroll
            for (int r = 0; r < 4; r++) {
                acc[i][j][r] = 0.0f;
            }
        }
    }

    const int nk = K >> 5;
    uint4 rAh[2];
    uint4 rAl[2];
    uint4 rBh;
    uint4 rBl;

    const int arow0 = tid >> 2;
    const int acol0 = (tid & 3) * 8;
    const int arow1 = (tid + 256) >> 2;
    const int brow = tid >> 3;
    const int bcol = (tid & 7) * 8;

    rAh[0] = *reinterpret_cast<const uint4*>(Ah + (size_t)(bm + arow0) * K + acol0);
    rAl[0] = *reinterpret_cast<const uint4*>(Al + (size_t)(bm + arow0) * K + acol0);
    rAh[1] = *reinterpret_cast<const uint4*>(Ah + (size_t)(bm + arow1) * K + acol0);
    rAl[1] = *reinterpret_cast<const uint4*>(Al + (size_t)(bm + arow1) * K + acol0);
    rBh = *reinterpret_cast<const uint4*>(Bh + (size_t)brow * N + bn + bcol);
    rBl = *reinterpret_cast<const uint4*>(Bl + (size_t)brow * N + bn + bcol);

    *reinterpret_cast<uint4*>(pAh + arow0 * 40 + acol0) = rAh[0];
    *reinterpret_cast<uint4*>(pAl + arow0 * 40 + acol0) = rAl[0];
    *reinterpret_cast<uint4*>(pAh + arow1 * 40 + acol0) = rAh[1];
    *reinterpret_cast<uint4*>(pAl + arow1 * 40 + acol0) = rAl[1];
    *reinterpret_cast<uint4*>(pBh + brow * 72 + bcol) = rBh;
    *reinterpret_cast<uint4*>(pBl + brow * 72 + bcol) = rBl;
    __syncthreads();

    const int a_r = lane & 15;
    const int a_k = (lane >> 4) * 8;

    for (int kt = 0; kt < nk; kt++) {
        const int curA = (kt & 1) * 5120;
        const int curB = (kt & 1) * 2304;

        if (kt + 1 < nk) {
            size_t koff = (size_t)(kt + 1) * 32;
            rAh[0] = *reinterpret_cast<const uint4*>(Ah + (size_t)(bm + arow0) * K + koff + acol0);
            rAl[0] = *reinterpret_cast<const uint4*>(Al + (size_t)(bm + arow0) * K + koff + acol0);
            rAh[1] = *reinterpret_cast<const uint4*>(Ah + (size_t)(bm + arow1) * K + koff + acol0);
            rAl[1] = *reinterpret_cast<const uint4*>(Al + (size_t)(bm + arow1) * K + koff + acol0);
            rBh = *reinterpret_cast<const uint4*>(Bh + (koff + brow) * N + bn + bcol);
            rBl = *reinterpret_cast<const uint4*>(Bl + (koff + brow) * N + bn + bcol);
        }

#pragma unroll
        for (int ks = 0; ks < 2; ks++) {
            u32 aH[2][4];
            u32 aL[2][4];
            u32 bH[4][2];
            u32 bL[4][2];
#pragma unroll
            for (int mi = 0; mi < 2; mi++) {
                u32 adr = smem_u32(pAh + curA + (wm + mi * 16 + a_r) * 40 + ks * 16 + a_k);
                ldsm_x4(aH[mi][0], aH[mi][1], aH[mi][2], aH[mi][3], adr);
                adr = smem_u32(pAl + curA + (wm + mi * 16 + a_r) * 40 + ks * 16 + a_k);
                ldsm_x4(aL[mi][0], aL[mi][1], aL[mi][2], aL[mi][3], adr);
            }
#pragma unroll
            for (int nj = 0; nj < 2; nj++) {
                u32 r0;
                u32 r1;
                u32 r2;
                u32 r3;
                u32 adr = smem_u32(pBh + curB + (ks * 16 + a_r) * 72 + wn + nj * 16 + a_k);
                ldsm_x4t(r0, r1, r2, r3, adr);
                bH[nj * 2][0] = r0;
                bH[nj * 2][1] = r1;
                bH[nj * 2 + 1][0] = r2;
                bH[nj * 2 + 1][1] = r3;
                adr = smem_u32(pBl + curB + (ks * 16 + a_r) * 72 + wn + nj * 16 + a_k);
                ldsm_x4t(r0, r1, r2, r3, adr);
                bL[nj * 2][0] = r0;
                bL[nj * 2][1] = r1;
                bL[nj * 2 + 1][0] = r2;
                bL[nj * 2 + 1][1] = r3;
            }
#pragma unroll
            for (int mi = 0; mi < 2; mi++) {
#pragma unroll
                for (int ni = 0; ni < 4; ni++) {
                    mma_bf16(acc[mi][ni], aH[mi], bH[ni]);
                    mma_bf16(acc[mi][ni], aH[mi], bL[ni]);
                    mma_bf16(acc[mi][ni], aL[mi], bH[ni]);
                }
            }
        }

        if (kt + 1 < nk) {
            const int nxtA = ((kt + 1) & 1) * 5120;
            const int nxtB = ((kt + 1) & 1) * 2304;
            *reinterpret_cast<uint4*>(pAh + nxtA + arow0 * 40 + acol0) = rAh[0];
            *reinterpret_cast<uint4*>(pAl + nxtA + arow0 * 40 + acol0) = rAl[0];
            *reinterpret_cast<uint4*>(pAh + nxtA + arow1 * 40 + acol0) = rAh[1];
            *reinterpret_cast<uint4*>(pAl + nxtA + arow1 * 40 + acol0) = rAl[1];
            *reinterpret_cast<uint4*>(pBh + nxtB + brow * 72 + bcol) = rBh;
            *reinterpret_cast<uint4*>(pBl + nxtB + brow * 72 + bcol) = rBl;
        }
        __syncthreads();
    }

    const int g = lane >> 2;
    const int tg = lane & 3;

    if (MODE == 0) {
#pragma unroll
        for (int mi = 0; mi < 2; mi++) {
            int row0 = bm + wm + mi * 16 + g;
#pragma unroll
            for (int ni = 0; ni < 4; ni++) {
                int col = bn + wn + ni * 8 + tg * 2;
                float2 v0;
                float2 v1;
                v0.x = acc[mi][ni][0];
                v0.y = acc[mi][ni][1];
                v1.x = acc[mi][ni][2];
                v1.y = acc[mi][ni][3];
                *reinterpret_cast<float2*>(&C[(size_t)row0 * N + col]) = v0;
                *reinterpret_cast<float2*>(&C[(size_t)(row0 + 8) * N + col]) = v1;
            }
        }
    } else {
        const float alpha = alpha_p[0];
#pragma unroll
        for (int mi = 0; mi < 2; mi++) {
#pragma unroll
            for (int half = 0; half < 2; half++) {
                int row = bm + wm + mi * 16 + g + half * 8;
                int win = row >> 6;
                int tok = row & 63;
                int b = win >> 8;
                int r2 = win & 255;
                int dblk = r2 >> 6;
                int h2 = r2 & 63;
                int hblk = h2 >> 3;
                int wblk = h2 & 7;
                int z4 = tok >> 4;
                int y4 = (tok >> 2) & 3;
                int x4 = tok & 3;
                size_t spat = (((size_t)b * 16 + dblk * 4 + z4) * 32 + hblk * 4 + y4) * 32
                              + wblk * 4 + x4;
#pragma unroll
                for (int ni = 0; ni < 4; ni++) {
                    int col = bn + wn + ni * 8 + tg * 2;
                    float2 pb = *reinterpret_cast<const float2*>(&bias[col]);
                    float* dst = &C[spat * 256 + col];
                    float2 e = *reinterpret_cast<float2*>(dst);
                    e.x += alpha * (acc[mi][ni][half * 2 + 0] + pb.x);
                    e.y += alpha * (acc[mi][ni][half * 2 + 1] + pb.y);
                    *reinterpret_cast<float2*>(dst) = e;
                }
            }
        }
    }
}

// ---------------------------------------------------------------------------
// Weight fold: W2[ocg][ch<24][tap] = sum_o dep_w[ocg][o][tap]*fc_w[o][ch];
//              W2[ocg][24][tap]   = sum_o dep_w[ocg][o][tap]*fc_b[o].
// ---------------------------------------------------------------------------
__global__ __launch_bounds__(256) void wfold_kernel(
    const float* __restrict__ dep_w, const float* __restrict__ fcw,
    const float* __restrict__ fcb)
{
    __shared__ float s_fcw[648];
    __shared__ float s_fcb[27];
    const int tap = blockIdx.x;
    const int ocg = threadIdx.x;
    for (int e = threadIdx.x; e < 648; e += 256) {
        s_fcw[e] = fcw[e];
    }
    if (threadIdx.x < 27) {
        s_fcb[threadIdx.x] = fcb[threadIdx.x];
    }
    __syncthreads();

    float dw[27];
#pragma unroll
    for (int o = 0; o < 27; o++) {
        dw[o] = dep_w[(size_t)ocg * 729 + o * 27 + tap];
    }
#pragma unroll 1
    for (int ch = 0; ch < 24; ch++) {
        float s = 0.0f;
#pragma unroll
        for (int o = 0; o < 27; o++) {
            s = fmaf(dw[o], s_fcw[o * 24 + ch], s);
        }
        g_w2[ocg * 675 + ch * 27 + tap] = s;
    }
    float sb = 0.0f;
#pragma unroll
    for (int o = 0; o < 27; o++) {
        sb = fmaf(dw[o], s_fcb[o], sb);
    }
    g_w2[ocg * 675 + 24 * 27 + tap] = sb;
}

// ---------------------------------------------------------------------------
// Transpose: g_qt[b][g][gg][l] = qkv_flat[b][gg*524288 + l*32 + g].
// ---------------------------------------------------------------------------
__global__ __launch_bounds__(256) void transpose_kernel()
{
    __shared__ float sm[32 * 132];
    const int lt = blockIdx.x;
    const int gg = blockIdx.y;
    const int b = blockIdx.z;
    const int tid = threadIdx.x;
    const float* src = g_qkv + (size_t)b * 12582912 + (size_t)gg * 524288
                       + (size_t)lt * 128 * 32;
#pragma unroll
    for (int it = 0; it < 4; it++) {
        int idx4 = tid + it * 256;
        float4 v = reinterpret_cast<const float4*>(src)[idx4];
        int flat = idx4 * 4;
        int l = flat >> 5;
        int x = flat & 31;
        sm[(x + 0) * 132 + l] = v.x;
        sm[(x + 1) * 132 + l] = v.y;
        sm[(x + 2) * 132 + l] = v.z;
        sm[(x + 3) * 132 + l] = v.w;
    }
    __syncthreads();
    const int l4 = (tid & 31) * 4;
#pragma unroll
    for (int go = 0; go < 4; go++) {
        int gch = go * 8 + (tid >> 5);
        float4 v = *reinterpret_cast<const float4*>(&sm[gch * 132 + l4]);
        float* dst = g_qt + (((size_t)(b * 32 + gch) * 24 + gg) * LSP)
                     + lt * 128 + l4;
        *reinterpret_cast<float4*>(dst) = v;
    }
}

// ---------------------------------------------------------------------------
// Fused grouped conv: 25 channels, folded weights, 2z x 8y x 32x tile,
// 512 threads, per-thread 2oc x 4x, 3 blocks/SM.
// ---------------------------------------------------------------------------
#define CONV_NCH 25
#define CONV_KCHUNK 7
#define CONV_SW_FLOATS  (CONV_KCHUNK * 4 * 10 * 36)
#define CONV_DEP_FLOATS (8 * CONV_NCH * 9 * 4)
#define CONV_SMEM_BYTES ((CONV_SW_FLOATS + CONV_DEP_FLOATS) * 4)

__device__ __forceinline__ void conv_load_chunk(
    float* sw, const float* fin, int tid, int y0, int z0, int kbase, int nk)
{
    const int elems = nk * 4 * 10 * 34;
    for (int e = tid; e < elems; e += 512) {
        int x = e % 34;
        int t1 = e / 34;
        int yy = t1 % 10;
        int t2 = t1 / 10;
        int wz = t2 & 3;
        int kl = t2 >> 2;
        int ch = kbase + kl;
        int gx = x - 1;
        int gy = y0 + yy - 1;
        int gz = z0 + wz - 1;
        float v = 0.0f;
        if (gx >= 0 && gx < 32 && gy >= 0 && gy < 32 && gz >= 0 && gz < 16) {
            if (ch < 24) {
                v = fin[(size_t)ch * LSP + gz * 1024 + gy * 32 + gx];
            } else {
                v = 1.0f;
            }
        }
        sw[((kl * 4 + wz) * 10 + yy) * 36 + x] = v;
    }
}

__global__ __launch_bounds__(512, 3) void conv_kernel(
    const float* __restrict__ dep_b, const float* __restrict__ beta_p,
    float* __restrict__ out)
{
    extern __shared__ float sm[];
    float* sw = sm;
    float* sdep = sm + CONV_SW_FLOATS;

    const int tid = threadIdx.x;
    const int y0 = blockIdx.x * 8;
    const int z0 = blockIdx.y * 2;
    const int bg = blockIdx.z;
    const int b = bg >> 5;
    const int g = bg & 31;

    for (int e = tid; e < CONV_DEP_FLOATS; e += 512) {
        int dx = e & 3;
        int rest = e >> 2;
        int dydz = rest % 9;
        int rest2 = rest / 9;
        int ch = rest2 % CONV_NCH;
        int ocl = rest2 / CONV_NCH;
        float v = 0.0f;
        if (dx < 3) {
            v = g_w2[(g * 8 + ocl) * 675 + ch * 27 + dydz * 3 + dx];
        }
        sdep[e] = v;
    }

    const float* fin = g_qt + (size_t)(b * 32 + g) * 24 * LSP;
    conv_load_chunk(sw, fin, tid, y0, z0, 0, CONV_KCHUNK);
    __syncthreads();

    const int xq = tid & 7;
    const int ocp = (tid >> 3) & 3;
    const int yy = (tid >> 5) & 7;
    const int zz = tid >> 8;
    const int oc0 = ocp * 2;

    float acc0[4] = {0.0f, 0.0f, 0.0f, 0.0f};
    float acc1[4] = {0.0f, 0.0f, 0.0f, 0.0f};

    const float* wd0 = sdep + oc0 * (CONV_NCH * 36);
    const float* wd1 = wd0 + CONV_NCH * 36;

#pragma unroll
    for (int chunk = 0; chunk < 4; chunk++) {
        const int kbase = chunk * CONV_KCHUNK;
        const int nk = (chunk < 3) ? CONV_KCHUNK : (CONV_NCH - 3 * CONV_KCHUNK);
#pragma unroll 1
        for (int kl = 0; kl < nk; kl++) {
            const int k = kbase + kl;
#pragma unroll
            for (int dz = 0; dz < 3; dz++) {
#pragma unroll
                for (int dy = 0; dy < 3; dy++) {
                    const float* wrow = &sw[((kl * 4 + zz + dz) * 10 + yy + dy) * 36 + xq * 4];
                    float4 wa = *reinterpret_cast<const float4*>(wrow);
                    float2 wb = *reinterpret_cast<const float2*>(wrow + 4);
                    float win[6];
                    win[0] = wa.x;
                    win[1] = wa.y;
                    win[2] = wa.z;
                    win[3] = wa.w;
                    win[4] = wb.x;
                    win[5] = wb.y;
                    float4 w0v = *reinterpret_cast<const float4*>(wd0 + (k * 9 + dz * 3 + dy) * 4);
                    float4 w1v = *reinterpret_cast<const float4*>(wd1 + (k * 9 + dz * 3 + dy) * 4);
                    float w0[3];
                    float w1[3];
                    w0[0] = w0v.x;
                    w0[1] = w0v.y;
                    w0[2] = w0v.z;
                    w1[0] = w1v.x;
                    w1[1] = w1v.y;
                    w1[2] = w1v.z;
#pragma unroll
                    for (int dx = 0; dx < 3; dx++) {
#pragma unroll
                        for (int c = 0; c < 4; c++) {
                            acc0[c] = fmaf(win[c + dx], w0[dx], acc0[c]);
                            acc1[c] = fmaf(win[c + dx], w1[dx], acc1[c]);
                        }
                    }
                }
            }
        }
        if (chunk < 3) {
            __syncthreads();
            const int nkn = (chunk < 2) ? CONV_KCHUNK : (CONV_NCH - 3 * CONV_KCHUNK);
            conv_load_chunk(sw, fin, tid, y0, z0, kbase + CONV_KCHUNK, nkn);
            __syncthreads();
        }
    }

    const float beta = beta_p[0];
    const int ocg0 = g * 8 + oc0;
    const float b0 = dep_b[ocg0];
    const float b1 = dep_b[ocg0 + 1];
    const size_t spatbase = (size_t)b * LSP + (z0 + zz) * 1024 + (y0 + yy) * 32 + xq * 4;
#pragma unroll
    for (int c = 0; c < 4; c++) {
        float2 v;
        v.x = beta * (acc0[c] + b0);
        v.y = beta * (acc1[c] + b1);
        *reinterpret_cast<float2*>(out + (spatbase + c) * 256 + ocg0) = v;
    }
}

// ---------------------------------------------------------------------------
// Windowed attention -> bf16 split output (g_ah/g_al).
// PV stage reads probabilities as float4 (4-j groups) to cut smem traffic.
// ---------------------------------------------------------------------------
__global__ __launch_bounds__(256) void attn_kernel(const float* __restrict__ rpb)
{
    __shared__ __align__(16) float sq[64][36];
    __shared__ __align__(16) float skT[32][68];
    __shared__ __align__(16) float sv[64][36];
    __shared__ __align__(16) float sS[64][68];
    __shared__ float sbias[343];

    const int tid = threadIdx.x;
    const int win = blockIdx.x;
    const int head = blockIdx.y;
    const int b = win >> 8;
    const int rr = win & 255;
    const int dblk = rr >> 6;
    const int h2 = rr & 63;
    const int hblk = h2 >> 3;
    const int wblk = h2 & 7;

    for (int i = tid; i < 343; i += 256) {
        sbias[i] = rpb[i * 8 + head];
    }

    for (int e = tid; e < 64 * 32; e += 256) {
        int tok = e >> 5;
        int dd = e & 31;
        int z = tok >> 4;
        int y = (tok >> 2) & 3;
        int x = tok & 3;
        size_t spat = (((size_t)b * 16 + dblk * 4 + z) * 32 + hblk * 4 + y) * 32
                      + wblk * 4 + x;
        const float* src = g_qkv + spat * 768 + head * 32 + dd;
        sq[tok][dd] = src[0];
        skT[dd][tok] = src[256];
        sv[tok][dd] = src[512];
    }
    __syncthreads();

    const int i4 = tid >> 4;
    const int jq = tid & 15;
    const int i0 = i4 * 4;
    const int j0 = jq * 4;

    float dots[4][4];
#pragma unroll
    for (int r = 0; r < 4; r++) {
#pragma unroll
        for (int c = 0; c < 4; c++) {
            dots[r][c] = 0.0f;
        }
    }

#pragma unroll
    for (int d8 = 0; d8 < 4; d8++) {
        float qreg[4][8];
#pragma unroll
        for (int r = 0; r < 4; r++) {
            float4 q0 = *reinterpret_cast<const float4*>(&sq[i0 + r][d8 * 8]);
            float4 q1 = *reinterpret_cast<const float4*>(&sq[i0 + r][d8 * 8 + 4]);
            qreg[r][0] = q0.x; qreg[r][1] = q0.y; qreg[r][2] = q0.z; qreg[r][3] = q0.w;
            qreg[r][4] = q1.x; qreg[r][5] = q1.y; qreg[r][6] = q1.z; qreg[r][7] = q1.w;
        }
#pragma unroll
        for (int dd = 0; dd < 8; dd++) {
            float4 kv = *reinterpret_cast<const float4*>(&skT[d8 * 8 + dd][j0]);
#pragma unroll
            for (int r = 0; r < 4; r++) {
                dots[r][0] = fmaf(qreg[r][dd], kv.x, dots[r][0]);
                dots[r][1] = fmaf(qreg[r][dd], kv.y, dots[r][1]);
                dots[r][2] = fmaf(qreg[r][dd], kv.z, dots[r][2]);
                dots[r][3] = fmaf(qreg[r][dd], kv.w, dots[r][3]);
            }
        }
    }

    const float scale = 0.17677669529663687f;
#pragma unroll
    for (int r = 0; r < 4; r++) {
        int ti = i0 + r;
        int zi = ti >> 4;
        int yi = (ti >> 2) & 3;
        int xi = ti & 3;
        float sv4[4];
#pragma unroll
        for (int c = 0; c < 4; c++) {
            int tj = j0 + c;
            int zj = tj >> 4;
            int yj = (tj >> 2) & 3;
            int xj = tj & 3;
            int rel = (zi - zj + 3) * 49 + (yi - yj + 3) * 7 + (xi - xj + 3);
            sv4[c] = dots[r][c] * scale + sbias[rel];
        }
        float rmax = fmaxf(fmaxf(sv4[0], sv4[1]), fmaxf(sv4[2], sv4[3]));
        rmax = warp16_max(rmax);
        float rsum = 0.0f;
#pragma unroll
        for (int c = 0; c < 4; c++) {
            sv4[c] = __expf(sv4[c] - rmax);
            rsum += sv4[c];
        }
        rsum = warp16_sum(rsum);
        float inv = 1.0f / rsum;
        float4 pv;
        pv.x = sv4[0] * inv;
        pv.y = sv4[1] * inv;
        pv.z = sv4[2] * inv;
        pv.w = sv4[3] * inv;
        *reinterpret_cast<float4*>(&sS[i0 + r][j0]) = pv;
    }
    __syncthreads();

    const int p2 = tid >> 3;
    const int dg = tid & 7;
    const int r0 = p2 * 2;
    const int r1 = r0 + 1;
    float o0[4] = {0.0f, 0.0f, 0.0f, 0.0f};
    float o1[4] = {0.0f, 0.0f, 0.0f, 0.0f};
#pragma unroll 2
    for (int j4 = 0; j4 < 16; j4++) {
        float4 pa4 = *reinterpret_cast<const float4*>(&sS[r0][j4 * 4]);
        float4 pb4 = *reinterpret_cast<const float4*>(&sS[r1][j4 * 4]);
        float pav[4];
        float pbv[4];
        pav[0] = pa4.x; pav[1] = pa4.y; pav[2] = pa4.z; pav[3] = pa4.w;
        pbv[0] = pb4.x; pbv[1] = pb4.y; pbv[2] = pb4.z; pbv[3] = pb4.w;
#pragma unroll
        for (int jj = 0; jj < 4; jj++) {
            float4 v = *reinterpret_cast<const float4*>(&sv[j4 * 4 + jj][dg * 4]);
            o0[0] = fmaf(pav[jj], v.x, o0[0]);
            o0[1] = fmaf(pav[jj], v.y, o0[1]);
            o0[2] = fmaf(pav[jj], v.z, o0[2]);
            o0[3] = fmaf(pav[jj], v.w, o0[3]);
            o1[0] = fmaf(pbv[jj], v.x, o1[0]);
            o1[1] = fmaf(pbv[jj], v.y, o1[1]);
            o1[2] = fmaf(pbv[jj], v.z, o1[2]);
            o1[3] = fmaf(pbv[jj], v.w, o1[3]);
        }
    }
    size_t off0 = ((size_t)win * 64 + r0) * 256 + head * 32 + dg * 4;
    size_t off1 = ((size_t)win * 64 + r1) * 256 + head * 32 + dg * 4;
#pragma unroll
    for (int pass = 0; pass < 2; pass++) {
        const float* ov = (pass == 0) ? o0 : o1;
        size_t off = (pass == 0) ? off0 : off1;
        __nv_bfloat16 hh[4];
        __nv_bfloat16 ll[4];
#pragma unroll
        for (int c = 0; c < 4; c++) {
            hh[c] = __float2bfloat16(ov[c]);
            ll[c] = __float2bfloat16(ov[c] - __bfloat162float(hh[c]));
        }
        __nv_bfloat162* hp = reinterpret_cast<__nv_bfloat162*>(g_ah + off);
        __nv_bfloat162* lp = reinterpret_cast<__nv_bfloat162*>(g_al + off);
        hp[0] = __halves2bfloat162(hh[0], hh[1]);
        hp[1] = __halves2bfloat162(hh[2], hh[3]);
        lp[0] = __halves2bfloat162(ll[0], ll[1]);
        lp[1] = __halves2bfloat162(ll[2], ll[3]);
    }
}

// ---------------------------------------------------------------------------
// Launch. DAG: wfold, split3 -> gemm0 -> { (transpose -> conv), attn } -> gemm1
// ---------------------------------------------------------------------------
extern "C" void kernel_launch(void* const* d_in, const int* in_sizes, int n_in,
                              void* d_out, int out_size)
{
    (void)in_sizes;
    (void)n_in;
    (void)out_size;
    const float* x_in   = (const float*)d_in[0];
    const float* qkv_w  = (const float*)d_in[1];
    const float* proj_w = (const float*)d_in[2];
    const float* proj_b = (const float*)d_in[3];
    const float* rpb    = (const float*)d_in[4];
    const float* fc_w   = (const float*)d_in[5];
    const float* fc_b   = (const float*)d_in[6];
    const float* dep_w  = (const float*)d_in[7];
    const float* dep_b  = (const float*)d_in[8];
    const float* alpha  = (const float*)d_in[9];
    const float* beta   = (const float*)d_in[10];
    float* out = (float*)d_out;

    float* p_qkv;
    __nv_bfloat16* p_xh;
    __nv_bfloat16* p_xl;
    __nv_bfloat16* p_ah;
    __nv_bfloat16* p_al;
    __nv_bfloat16* p_wqh;
    __nv_bfloat16* p_wql;
    __nv_bfloat16* p_pwh;
    __nv_bfloat16* p_pwl;
    cudaGetSymbolAddress((void**)&p_qkv, g_qkv);
    cudaGetSymbolAddress((void**)&p_xh, g_xh);
    cudaGetSymbolAddress((void**)&p_xl, g_xl);
    cudaGetSymbolAddress((void**)&p_ah, g_ah);
    cudaGetSymbolAddress((void**)&p_al, g_al);
    cudaGetSymbolAddress((void**)&p_wqh, g_wqh);
    cudaGetSymbolAddress((void**)&p_wql, g_wql);
    cudaGetSymbolAddress((void**)&p_pwh, g_pwh);
    cudaGetSymbolAddress((void**)&p_pwl, g_pwl);

    cudaFuncSetAttribute(gemm_bf16<0>, cudaFuncAttributeMaxDynamicSharedMemorySize,
                         GEMM_SMEM_BYTES);
    cudaFuncSetAttribute(gemm_bf16<1>, cudaFuncAttributeMaxDynamicSharedMemorySize,
                         GEMM_SMEM_BYTES);
    cudaFuncSetAttribute(conv_kernel, cudaFuncAttributeMaxDynamicSharedMemorySize,
                         CONV_SMEM_BYTES);

    static cudaStream_t s_attn = 0;
    static cudaEvent_t ev_fork = 0;
    static cudaEvent_t ev_join = 0;
    if (s_attn == 0) {
        cudaStreamCreateWithFlags(&s_attn, cudaStreamNonBlocking);
        cudaEventCreateWithFlags(&ev_fork, cudaEventDisableTiming);
        cudaEventCreateWithFlags(&ev_join, cudaEventDisableTiming);
    }

    // weight fold (independent of qkv)
    wfold_kernel<<<27, 256>>>(dep_w, fc_w, fc_b);
    // merged bf16 splits
    split3_kernel<<<16640, 256>>>(x_in, qkv_w, proj_w);
    // qkv = x_in @ qkv_w
    gemm_bf16<0><<<dim3(12, 512), 256, GEMM_SMEM_BYTES>>>(
        p_xh, p_xl, p_wqh, p_wql, p_qkv, 65536, 768, 256,
        (const float*)0, (const float*)0);

    // fork: attn on side stream
    cudaEventRecord(ev_fork, 0);
    cudaStreamWaitEvent(s_attn, ev_fork, 0);
    attn_kernel<<<dim3(1024, 8), 256, 0, s_attn>>>(rpb);
    cudaEventRecord(ev_join, s_attn);

    // transpose qkv for conv
    transpose_kernel<<<dim3(128, 24, 4), 256>>>();
    // fused grouped conv (3 blocks/SM) -> out = beta*(conv + dep_b)
    conv_kernel<<<dim3(4, 8, 128), 512, CONV_SMEM_BYTES>>>(dep_b, beta, out);

    // join, then proj + window-reverse + out += alpha*(...)
    cudaStreamWaitEvent(0, ev_join, 0);
    gemm_bf16<1><<<dim3(4, 512), 256, GEMM_SMEM_BYTES>>>(
        p_ah, p_al, p_pwh, p_pwl, out, 65536, 256, 256, proj_b, alpha);
}